// round 2
// baseline (speedup 1.0000x reference)
#include <cuda_runtime.h>

// ---------------------------------------------------------------------------
// BinomialLoss fused kernel.
//   sim = X @ X^T  (X L2-normalized [n,d] fp32), per-row masked softplus sums,
//   final 4 scalars: (loss, prec, last_pos_sim_mean, last_neg_sim_mean)
//
// Diagonal handling: reference pos filter is (same_class & sim < 1.0).
// Self-sim ~ 1.0 +/- few ulps, so the <1.0 decision is rounding-determined.
// We replicate it with a sequential ascending-k scalar FMA chain (the
// accumulation order of Eigen/oneDNN/cublas fp32 microkernels per C element).
// ---------------------------------------------------------------------------

#define NMAX   4096
#define CLSMAX 512
#define TILES_MAX 32

#define BM 128
#define BN 128
#define BK 16
#define TM 8
#define TN 8
#define PAD 4

// Scratch (allocation-free rules: __device__ globals)
__device__ int   g_tgt[NMAX];
__device__ int   g_hist[CLSMAX];
__device__ float g_diag_val[NMAX];
__device__ int   g_diag_in[NMAX];     // 1 if self-sim < 1.0f (include in pos)
__device__ float g_pos_part[TILES_MAX * NMAX];
__device__ float g_neg_part[TILES_MAX * NMAX];
__device__ float g_last_part[TILES_MAX][2];

// ---------------------------------------------------------------------------
// prep: convert targets (int64 or int32, auto-detected) -> int32, histogram.
// ---------------------------------------------------------------------------
__global__ void prep_kernel(const void* __restrict__ tgt_raw, int n) {
    __shared__ int sh[CLSMAX];
    __shared__ int is64;
    const int t = threadIdx.x;

    if (t == 0) is64 = 1;
    for (int i = t; i < CLSMAX; i += blockDim.x) sh[i] = 0;
    __syncthreads();

    const long long* p64 = (const long long*)tgt_raw;
    const int*       p32 = (const int*)tgt_raw;
    for (int i = t; i < 64 && i < n; i += blockDim.x) {
        long long v = p64[i];
        if (v < 0 || v >= (long long)CLSMAX) atomicAnd(&is64, 0);
    }
    __syncthreads();
    const bool use64 = (is64 != 0);

    for (int i = t; i < n; i += blockDim.x) {
        int v = use64 ? (int)p64[i] : p32[i];
        if (v < 0) v = 0;
        if (v >= CLSMAX) v = CLSMAX - 1;
        g_tgt[i] = v;
        atomicAdd(&sh[v], 1);
    }
    __syncthreads();
    for (int i = t; i < CLSMAX; i += blockDim.x) g_hist[i] = sh[i];
}

// ---------------------------------------------------------------------------
// diag: self-sim per row, EXACT sequential ascending-k fp32 FMA chain.
// One thread per row; the dependent chain (512*4cyc) is hidden by row count.
// ---------------------------------------------------------------------------
__global__ void diag_kernel(const float* __restrict__ X, int n, int d) {
    const int i = blockIdx.x * blockDim.x + threadIdx.x;
    if (i >= n) return;
    const float* row = X + (size_t)i * d;
    float acc = 0.f;
    for (int k = 0; k < d; k++)
        acc = fmaf(row[k], row[k], acc);   // sequential order, do not reassociate
    g_diag_val[i] = acc;
    g_diag_in[i]  = (acc < 1.0f) ? 1 : 0;
}

// ---------------------------------------------------------------------------
// main: fused tiled X@X^T + masked softplus + per-row partial sums.
// ---------------------------------------------------------------------------
__global__ __launch_bounds__(256, 2)
void binloss_main(const float* __restrict__ X, int n, int d) {
    __shared__ float As[BK][BM + PAD];
    __shared__ float Bs[BK][BN + PAD];
    __shared__ int tR[BM];
    __shared__ int tC[BN];

    const int tid = threadIdx.x;
    const int tx  = tid & 15;
    const int ty  = tid >> 4;
    const int rowBlk = blockIdx.y * BM;
    const int colBlk = blockIdx.x * BN;

    if (tid < BM) {
        tR[tid] = g_tgt[rowBlk + tid];
        tC[tid] = g_tgt[colBlk + tid];
    }

    float acc[TM][TN];
#pragma unroll
    for (int i = 0; i < TM; i++)
#pragma unroll
        for (int j = 0; j < TN; j++) acc[i][j] = 0.f;

    const int lr = tid >> 2;
    const int lc = (tid & 3) << 2;

    for (int k0 = 0; k0 < d; k0 += BK) {
#pragma unroll
        for (int p = 0; p < 2; p++) {
            const int r = lr + p * 64;
            const float4 va = *(const float4*)(X + (size_t)(rowBlk + r) * d + k0 + lc);
            As[lc + 0][r] = va.x; As[lc + 1][r] = va.y;
            As[lc + 2][r] = va.z; As[lc + 3][r] = va.w;
            const float4 vb = *(const float4*)(X + (size_t)(colBlk + r) * d + k0 + lc);
            Bs[lc + 0][r] = vb.x; Bs[lc + 1][r] = vb.y;
            Bs[lc + 2][r] = vb.z; Bs[lc + 3][r] = vb.w;
        }
        __syncthreads();
#pragma unroll
        for (int kk = 0; kk < BK; kk++) {
            float ra[TM], rb[TN];
#pragma unroll
            for (int i = 0; i < TM; i += 4) {
                const float4 v = *(const float4*)&As[kk][ty * TM + i];
                ra[i] = v.x; ra[i + 1] = v.y; ra[i + 2] = v.z; ra[i + 3] = v.w;
            }
#pragma unroll
            for (int j = 0; j < TN; j += 4) {
                const float4 v = *(const float4*)&Bs[kk][tx * TN + j];
                rb[j] = v.x; rb[j + 1] = v.y; rb[j + 2] = v.z; rb[j + 3] = v.w;
            }
#pragma unroll
            for (int i = 0; i < TM; i++)
#pragma unroll
                for (int j = 0; j < TN; j++)
                    acc[i][j] = fmaf(ra[i], rb[j], acc[i][j]);
        }
        __syncthreads();
    }

    // ---- fused epilogue ----
    const float ALPHA = 40.f, MARGIN = 0.5f;
#pragma unroll
    for (int i = 0; i < TM; i++) {
        const int gr = rowBlk + ty * TM + i;
        const int tr = tR[ty * TM + i];
        const bool lastRow = (gr == n - 1);
        float pos = 0.f, neg = 0.f, sp = 0.f, sn = 0.f;
#pragma unroll
        for (int j = 0; j < TN; j++) {
            const int gc = colBlk + tx * TN + j;
            const int tc = tC[tx * TN + j];
            const float s = acc[i][j];
            const bool same = (tr == tc);
            if (gc == gr) {
                // diagonal: reference-replicated value & <1.0 decision
                if (g_diag_in[gr]) {
                    const float sv = g_diag_val[gr];
                    const float z = -2.f * (sv - MARGIN);
                    pos += fmaxf(z, 0.f) + __logf(1.f + __expf(-fabsf(z)));
                    if (lastRow) sp += sv;
                }
            } else if (same) {
                const float z = -2.f * (s - MARGIN);
                pos += fmaxf(z, 0.f) + __logf(1.f + __expf(-fabsf(z)));
                if (lastRow) sp += s;
            } else {
                const float z = ALPHA * (s - MARGIN);
                neg += fmaxf(z, 0.f) + __logf(1.f + __expf(-fabsf(z)));
                if (lastRow) sn += s;
            }
        }
#pragma unroll
        for (int off = 8; off > 0; off >>= 1) {
            pos += __shfl_down_sync(0xffffffffu, pos, off, 16);
            neg += __shfl_down_sync(0xffffffffu, neg, off, 16);
        }
        if (tx == 0) {
            g_pos_part[blockIdx.x * n + gr] = pos;
            g_neg_part[blockIdx.x * n + gr] = neg;
        }
        if (lastRow) {
#pragma unroll
            for (int off = 8; off > 0; off >>= 1) {
                sp += __shfl_down_sync(0xffffffffu, sp, off, 16);
                sn += __shfl_down_sync(0xffffffffu, sn, off, 16);
            }
            if (tx == 0) {
                g_last_part[blockIdx.x][0] = sp;
                g_last_part[blockIdx.x][1] = sn;
            }
        }
    }
}

// ---------------------------------------------------------------------------
// finalize: per-row partial sums -> 4 output scalars. Single block.
// ---------------------------------------------------------------------------
__global__ void finalize_kernel(float* __restrict__ out, int n, int nTiles) {
    __shared__ float sLoss[256];
    __shared__ float sInv[256];
    const int t = threadIdx.x;
    float loss = 0.f, inv = 0.f;
    for (int i = t; i < n; i += 256) {
        float ps = 0.f, ns = 0.f;
        for (int b = 0; b < nTiles; b++) {
            ps += g_pos_part[b * n + i];
            ns += g_neg_part[b * n + i];
        }
        const int c = g_hist[g_tgt[i]];
        const float pc = (float)(c - 1 + g_diag_in[i]);   // pos_cnt incl. diag decision
        const float nc = (float)(n - c);
        const float pl = ps / fmaxf(pc, 1.f);
        const float nl = ns / fmaxf(nc, 1.f);
        if (nc > 0.f) loss += pl + nl; else inv += 1.f;
    }
    sLoss[t] = loss; sInv[t] = inv;
    __syncthreads();
    for (int s = 128; s > 0; s >>= 1) {
        if (t < s) { sLoss[t] += sLoss[t + s]; sInv[t] += sInv[t + s]; }
        __syncthreads();
    }
    if (t == 0) {
        float sp = 0.f, sn = 0.f;
        for (int b = 0; b < nTiles; b++) { sp += g_last_part[b][0]; sn += g_last_part[b][1]; }
        const int c = g_hist[g_tgt[n - 1]];
        const float pc = (float)(c - 1 + g_diag_in[n - 1]);
        out[0] = sLoss[0] / (float)n;
        out[1] = sInv[0] / (float)n;
        out[2] = sp / fmaxf(pc, 1.f);
        out[3] = sn / fmaxf((float)(n - c), 1.f);
    }
}

// ---------------------------------------------------------------------------
extern "C" void kernel_launch(void* const* d_in, const int* in_sizes, int n_in,
                              void* d_out, int out_size) {
    int ix = 0, it = 1;
    if (n_in >= 2 && in_sizes[0] < in_sizes[1]) { ix = 1; it = 0; }
    const float* X = (const float*)d_in[ix];
    const void*  T = d_in[it];
    const int n = in_sizes[it];
    const int d = in_sizes[ix] / n;
    const int nTiles = n / BN;

    prep_kernel<<<1, 256>>>(T, n);
    diag_kernel<<<(n + 255) / 256, 256>>>(X, n, d);
    dim3 grid(nTiles, n / BM);
    binloss_main<<<grid, 256>>>(X, n, d);
    finalize_kernel<<<1, 256>>>((float*)d_out, n, nTiles);
}

// round 3
// speedup vs baseline: 1.6758x; 1.6758x over previous
#include <cuda_runtime.h>

// ---------------------------------------------------------------------------
// BinomialLoss fused kernel, round 3: symmetric-half GEMM + parallel finalize.
//   sim = X @ X^T  (X L2-normalized [n,d] fp32), per-row masked softplus sums,
//   final 4 scalars: (loss, prec, last_pos_sim_mean, last_neg_sim_mean)
//
// Only upper-triangle 128x128 tiles are computed; each off-diagonal tile
// contributes its softplus values to BOTH its row-block rows (shuffle reduce)
// and its col-block rows (smem tree reduce). Partial slots are disjoint:
//   row-pass writes slot bj (>= tile(row)), col-pass writes slot bi (< tile(row)).
//
// Diagonal: reference pos filter is (same_class & sim < 1.0); self-sim decision
// replicated with a sequential ascending-k scalar FMA chain (diag_kernel).
// ---------------------------------------------------------------------------

#define NMAX   4096
#define CLSMAX 512
#define TILES_MAX 32

#define BM 128
#define BN 128
#define BK 16
#define TM 8
#define TN 8
#define PAD 4

// Scratch (allocation-free rules: __device__ globals)
__device__ int   g_tgt[NMAX];
__device__ int   g_hist[CLSMAX];
__device__ float g_diag_val[NMAX];
__device__ int   g_diag_in[NMAX];
__device__ float g_pos_part[TILES_MAX * NMAX];
__device__ float g_neg_part[TILES_MAX * NMAX];
__device__ float g_last_part[TILES_MAX][2];
__device__ float g_loss_part[64];
__device__ float g_inv_part[64];

__device__ __forceinline__ float softplus_fast(float z) {
    return fmaxf(z, 0.f) + __logf(1.f + __expf(-fabsf(z)));
}

// ---------------------------------------------------------------------------
__global__ void prep_kernel(const void* __restrict__ tgt_raw, int n) {
    __shared__ int sh[CLSMAX];
    __shared__ int is64;
    const int t = threadIdx.x;

    if (t == 0) is64 = 1;
    for (int i = t; i < CLSMAX; i += blockDim.x) sh[i] = 0;
    __syncthreads();

    const long long* p64 = (const long long*)tgt_raw;
    const int*       p32 = (const int*)tgt_raw;
    for (int i = t; i < 64 && i < n; i += blockDim.x) {
        long long v = p64[i];
        if (v < 0 || v >= (long long)CLSMAX) atomicAnd(&is64, 0);
    }
    __syncthreads();
    const bool use64 = (is64 != 0);

    for (int i = t; i < n; i += blockDim.x) {
        int v = use64 ? (int)p64[i] : p32[i];
        if (v < 0) v = 0;
        if (v >= CLSMAX) v = CLSMAX - 1;
        g_tgt[i] = v;
        atomicAdd(&sh[v], 1);
    }
    __syncthreads();
    for (int i = t; i < CLSMAX; i += blockDim.x) g_hist[i] = sh[i];
}

// ---------------------------------------------------------------------------
// diag: self-sim, EXACT sequential ascending-k fp32 FMA chain.
// ---------------------------------------------------------------------------
__global__ void diag_kernel(const float* __restrict__ X, int n, int d) {
    const int i = blockIdx.x * blockDim.x + threadIdx.x;
    if (i >= n) return;
    const float* row = X + (size_t)i * d;
    float acc = 0.f;
    for (int k = 0; k < d; k++)
        acc = fmaf(row[k], row[k], acc);   // do not reassociate
    g_diag_val[i] = acc;
    g_diag_in[i]  = (acc < 1.0f) ? 1 : 0;
}

// ---------------------------------------------------------------------------
// main: upper-triangle fused GEMM + dual epilogue.
// grid = nT*(nT+1)/2 blocks of 256 threads.
// ---------------------------------------------------------------------------
__global__ __launch_bounds__(256, 2)
void binloss_main(const float* __restrict__ X, int n, int d) {
    __shared__ float As[BK][BM + PAD];
    __shared__ float Bs[BK][BN + PAD];
    __shared__ int tR[BM];
    __shared__ int tC[BN];
    __shared__ float sPC[16][BN + 8];   // col-pass pos partials, [ty][col]
    __shared__ float sNC[16][BN + 8];   // col-pass neg partials
    __shared__ float sLast[16][2];      // col-pass last-row sp/sn partials

    // linear block index -> (bi, bj) with bj >= bi
    const int nT = n / BM;
    int idx = blockIdx.x;
    int bi = 0;
    while (idx >= nT - bi) { idx -= nT - bi; bi++; }
    const int bj = bi + idx;
    const bool offd = (bi != bj);

    const int tid = threadIdx.x;
    const int tx  = tid & 15;
    const int ty  = tid >> 4;
    const int rowBlk = bi * BM;
    const int colBlk = bj * BN;

    if (tid < BM) {
        tR[tid] = g_tgt[rowBlk + tid];
        tC[tid] = g_tgt[colBlk + tid];
    }

    float acc[TM][TN];
#pragma unroll
    for (int i = 0; i < TM; i++)
#pragma unroll
        for (int j = 0; j < TN; j++) acc[i][j] = 0.f;

    const int lr = tid >> 2;
    const int lc = (tid & 3) << 2;

    for (int k0 = 0; k0 < d; k0 += BK) {
#pragma unroll
        for (int p = 0; p < 2; p++) {
            const int r = lr + p * 64;
            const float4 va = *(const float4*)(X + (size_t)(rowBlk + r) * d + k0 + lc);
            As[lc + 0][r] = va.x; As[lc + 1][r] = va.y;
            As[lc + 2][r] = va.z; As[lc + 3][r] = va.w;
            const float4 vb = *(const float4*)(X + (size_t)(colBlk + r) * d + k0 + lc);
            Bs[lc + 0][r] = vb.x; Bs[lc + 1][r] = vb.y;
            Bs[lc + 2][r] = vb.z; Bs[lc + 3][r] = vb.w;
        }
        __syncthreads();
#pragma unroll
        for (int kk = 0; kk < BK; kk++) {
            float ra[TM], rb[TN];
#pragma unroll
            for (int i = 0; i < TM; i += 4) {
                const float4 v = *(const float4*)&As[kk][ty * TM + i];
                ra[i] = v.x; ra[i + 1] = v.y; ra[i + 2] = v.z; ra[i + 3] = v.w;
            }
#pragma unroll
            for (int j = 0; j < TN; j += 4) {
                const float4 v = *(const float4*)&Bs[kk][tx * TN + j];
                rb[j] = v.x; rb[j + 1] = v.y; rb[j + 2] = v.z; rb[j + 3] = v.w;
            }
#pragma unroll
            for (int i = 0; i < TM; i++)
#pragma unroll
                for (int j = 0; j < TN; j++)
                    acc[i][j] = fmaf(ra[i], rb[j], acc[i][j]);
        }
        __syncthreads();
    }

    // ---- dual epilogue ----
    const float ALPHA = 40.f, MARGIN = 0.5f;
    float pos_c[TN], neg_c[TN];          // col-pass accumulators (rows = columns gc)
#pragma unroll
    for (int j = 0; j < TN; j++) { pos_c[j] = 0.f; neg_c[j] = 0.f; }
    float spc = 0.f, snc = 0.f;          // col-pass last-row (gc == n-1) sums
    const bool lastColTile = (colBlk + BN == n);

#pragma unroll
    for (int i = 0; i < TM; i++) {
        const int gr = rowBlk + ty * TM + i;
        const int tr = tR[ty * TM + i];
        const bool lastRow = (gr == n - 1);
        float pos = 0.f, neg = 0.f, sp = 0.f, sn = 0.f;
#pragma unroll
        for (int j = 0; j < TN; j++) {
            const int gc = colBlk + tx * TN + j;
            const int tc = tC[tx * TN + j];
            const float s = acc[i][j];
            const bool same = (tr == tc);
            if (gc == gr) {
                if (g_diag_in[gr]) {     // reference-replicated <1.0 decision
                    const float sv = g_diag_val[gr];
                    pos += softplus_fast(-2.f * (sv - MARGIN));
                    if (lastRow) sp += sv;
                }
            } else {
                const float z = same ? (-2.f * (s - MARGIN)) : (ALPHA * (s - MARGIN));
                const float l = softplus_fast(z);
                if (same) { pos += l; if (lastRow) sp += s; }
                else      { neg += l; if (lastRow) sn += s; }
                if (offd) {
                    if (same) pos_c[j] += l; else neg_c[j] += l;
                    if (lastColTile && gc == n - 1) { if (same) spc += s; else snc += s; }
                }
            }
        }
        // row-pass reduce (16 column-threads)
#pragma unroll
        for (int off = 8; off > 0; off >>= 1) {
            pos += __shfl_down_sync(0xffffffffu, pos, off, 16);
            neg += __shfl_down_sync(0xffffffffu, neg, off, 16);
        }
        if (tx == 0) {
            g_pos_part[bj * n + gr] = pos;
            g_neg_part[bj * n + gr] = neg;
        }
        if (lastRow) {
#pragma unroll
            for (int off = 8; off > 0; off >>= 1) {
                sp += __shfl_down_sync(0xffffffffu, sp, off, 16);
                sn += __shfl_down_sync(0xffffffffu, sn, off, 16);
            }
            if (tx == 0) {
                g_last_part[bj][0] = sp;
                g_last_part[bj][1] = sn;
            }
        }
    }

    // col-pass reduce (tree over ty, deterministic)
    if (offd) {
#pragma unroll
        for (int j = 0; j < TN; j++) {
            sPC[ty][tx * TN + j] = pos_c[j];
            sNC[ty][tx * TN + j] = neg_c[j];
        }
        if (lastColTile && tx == 15) { sLast[ty][0] = spc; sLast[ty][1] = snc; }
        __syncthreads();
#pragma unroll
        for (int s = 8; s > 0; s >>= 1) {
            if (ty < s) {
#pragma unroll
                for (int j = 0; j < TN; j++) {
                    sPC[ty][tx * TN + j] += sPC[ty + s][tx * TN + j];
                    sNC[ty][tx * TN + j] += sNC[ty + s][tx * TN + j];
                }
                if (lastColTile && tx == 15) {
                    sLast[ty][0] += sLast[ty + s][0];
                    sLast[ty][1] += sLast[ty + s][1];
                }
            }
            __syncthreads();
        }
        if (ty == 0) {
#pragma unroll
            for (int j = 0; j < TN; j++) {
                const int gc = colBlk + tx * TN + j;
                g_pos_part[bi * n + gc] = sPC[0][tx * TN + j];
                g_neg_part[bi * n + gc] = sNC[0][tx * TN + j];
            }
            if (lastColTile && tx == 15) {
                g_last_part[bi][0] = sLast[0][0];
                g_last_part[bi][1] = sLast[0][1];
            }
        }
    }
}

// ---------------------------------------------------------------------------
// finalize pass 1: 32 blocks x 128 threads, thread <-> row (coalesced).
// ---------------------------------------------------------------------------
__global__ void finalize1_kernel(int n, int nTiles) {
    __shared__ float sLoss[128];
    __shared__ float sInv[128];
    const int t = threadIdx.x;
    const int i = blockIdx.x * 128 + t;
    float loss = 0.f, inv = 0.f;
    if (i < n) {
        float ps = 0.f, ns = 0.f;
        for (int b = 0; b < nTiles; b++) {
            ps += g_pos_part[b * n + i];
            ns += g_neg_part[b * n + i];
        }
        const int c = g_hist[g_tgt[i]];
        const float pc = (float)(c - 1 + g_diag_in[i]);
        const float nc = (float)(n - c);
        const float pl = ps / fmaxf(pc, 1.f);
        const float nl = ns / fmaxf(nc, 1.f);
        if (nc > 0.f) loss = pl + nl; else inv = 1.f;
    }
    sLoss[t] = loss; sInv[t] = inv;
    __syncthreads();
    for (int s = 64; s > 0; s >>= 1) {
        if (t < s) { sLoss[t] += sLoss[t + s]; sInv[t] += sInv[t + s]; }
        __syncthreads();
    }
    if (t == 0) { g_loss_part[blockIdx.x] = sLoss[0]; g_inv_part[blockIdx.x] = sInv[0]; }
}

// ---------------------------------------------------------------------------
// finalize pass 2: one warp combines everything.
// ---------------------------------------------------------------------------
__global__ void finalize2_kernel(float* __restrict__ out, int n, int nTiles, int nB) {
    const int t = threadIdx.x;
    float loss = (t < nB) ? g_loss_part[t] : 0.f;
    float inv  = (t < nB) ? g_inv_part[t]  : 0.f;
    float sp   = (t < nTiles) ? g_last_part[t][0] : 0.f;
    float sn   = (t < nTiles) ? g_last_part[t][1] : 0.f;
#pragma unroll
    for (int off = 16; off > 0; off >>= 1) {
        loss += __shfl_down_sync(0xffffffffu, loss, off);
        inv  += __shfl_down_sync(0xffffffffu, inv,  off);
        sp   += __shfl_down_sync(0xffffffffu, sp,   off);
        sn   += __shfl_down_sync(0xffffffffu, sn,   off);
    }
    if (t == 0) {
        const int c = g_hist[g_tgt[n - 1]];
        const float pc = (float)(c - 1 + g_diag_in[n - 1]);
        out[0] = loss / (float)n;
        out[1] = inv / (float)n;
        out[2] = sp / fmaxf(pc, 1.f);
        out[3] = sn / fmaxf((float)(n - c), 1.f);
    }
}

// ---------------------------------------------------------------------------
extern "C" void kernel_launch(void* const* d_in, const int* in_sizes, int n_in,
                              void* d_out, int out_size) {
    int ix = 0, it = 1;
    if (n_in >= 2 && in_sizes[0] < in_sizes[1]) { ix = 1; it = 0; }
    const float* X = (const float*)d_in[ix];
    const void*  T = d_in[it];
    const int n = in_sizes[it];
    const int d = in_sizes[ix] / n;
    const int nT = n / BM;
    const int nBlocks = nT * (nT + 1) / 2;
    const int nFin = (n + 127) / 128;

    prep_kernel<<<1, 256>>>(T, n);
    diag_kernel<<<(n + 255) / 256, 256>>>(X, n, d);
    binloss_main<<<nBlocks, 256>>>(X, n, d);
    finalize1_kernel<<<nFin, 128>>>(n, nT);
    finalize2_kernel<<<1, 32>>>((float*)d_out, n, nT, nFin);
}

// round 5
// speedup vs baseline: 2.2450x; 1.3396x over previous
#include <cuda_runtime.h>
#include <cuda_bf16.h>
#include <stdint.h>

// ---------------------------------------------------------------------------
// BinomialLoss, round 5: mma.sync (HMMA) bf16x2-split tensor-core GEMM.
// sim = X @ X^T via A0*B0^T + A0*B1^T + A1*B0^T (x = b0 + b1 bf16 split).
// Triangle tiles only; fused masked-softplus dual epilogue (row + col pass).
// Diagonal <1.0 decision replicated with exact sequential fp32 FMA chain.
// (tcgen05 unavailable: harness compiles at sm_100, not sm_100a.)
// ---------------------------------------------------------------------------

#define NMAX   4096
#define DMAX   512
#define CLSMAX 512
#define TILES_MAX 32
#define BT   128          // tile M = N
#define KC   32           // k-chunk
#define SPE  40           // smem row stride in bf16 elems (80 B)

// -------- scratch ----------------------------------------------------------
__device__ int   g_tgt[NMAX];
__device__ int   g_hist[CLSMAX];
__device__ float g_diag_val[NMAX];
__device__ int   g_diag_in[NMAX];
__device__ float g_pos_part[TILES_MAX * NMAX];
__device__ float g_neg_part[TILES_MAX * NMAX];
__device__ float g_last_part[TILES_MAX][2];
__device__ float g_loss_part[64];
__device__ float g_inv_part[64];
__device__ __nv_bfloat16 g_b0[NMAX * DMAX];
__device__ __nv_bfloat16 g_b1[NMAX * DMAX];

__device__ __forceinline__ uint32_t smem_u32(const void* p) {
    uint32_t a;
    asm("{ .reg .u64 t; cvta.to.shared.u64 t, %1; cvt.u32.u64 %0, t; }" : "=r"(a) : "l"(p));
    return a;
}
__device__ __forceinline__ float softplus_fast(float z) {
    return fmaxf(z, 0.f) + __logf(1.f + __expf(-fabsf(z)));
}

#define LDMX4(R, ADDR)                                                          \
    asm volatile("ldmatrix.sync.aligned.m8n8.x4.shared.b16 {%0,%1,%2,%3}, [%4];"\
        : "=r"((R)[0]), "=r"((R)[1]), "=r"((R)[2]), "=r"((R)[3]) : "r"(ADDR))

#define MMA16816(D, A, B0r, B1r)                                                \
    asm volatile(                                                               \
        "mma.sync.aligned.m16n8k16.row.col.f32.bf16.bf16.f32 "                  \
        "{%0,%1,%2,%3}, {%4,%5,%6,%7}, {%8,%9}, {%0,%1,%2,%3};"                 \
        : "+f"((D)[0]), "+f"((D)[1]), "+f"((D)[2]), "+f"((D)[3])                \
        : "r"((A)[0]), "r"((A)[1]), "r"((A)[2]), "r"((A)[3]),                   \
          "r"(B0r), "r"(B1r))

// ---------------------------------------------------------------------------
__global__ void prep_kernel(const void* __restrict__ tgt_raw, int n) {
    __shared__ int sh[CLSMAX];
    __shared__ int is64;
    const int t = threadIdx.x;
    if (t == 0) is64 = 1;
    for (int i = t; i < CLSMAX; i += blockDim.x) sh[i] = 0;
    __syncthreads();
    const long long* p64 = (const long long*)tgt_raw;
    const int*       p32 = (const int*)tgt_raw;
    for (int i = t; i < 64 && i < n; i += blockDim.x) {
        long long v = p64[i];
        if (v < 0 || v >= (long long)CLSMAX) atomicAnd(&is64, 0);
    }
    __syncthreads();
    const bool use64 = (is64 != 0);
    for (int i = t; i < n; i += blockDim.x) {
        int v = use64 ? (int)p64[i] : p32[i];
        if (v < 0) v = 0;
        if (v >= CLSMAX) v = CLSMAX - 1;
        g_tgt[i] = v;
        atomicAdd(&sh[v], 1);
    }
    __syncthreads();
    for (int i = t; i < CLSMAX; i += blockDim.x) g_hist[i] = sh[i];
}

// diag: self-sim, EXACT sequential ascending-k fp32 FMA chain (do not touch).
__global__ void diag_kernel(const float* __restrict__ X, int n, int d) {
    const int i = blockIdx.x * blockDim.x + threadIdx.x;
    if (i >= n) return;
    const float* row = X + (size_t)i * d;
    float acc = 0.f;
    for (int k = 0; k < d; k++) acc = fmaf(row[k], row[k], acc);
    g_diag_val[i] = acc;
    g_diag_in[i]  = (acc < 1.0f) ? 1 : 0;
}

// split x -> b0 (bf16) + b1 (bf16 of residual)
__global__ void split_kernel(const float* __restrict__ X, int total) {
    const int i = (blockIdx.x * blockDim.x + threadIdx.x) * 4;
    if (i + 3 >= total) {
        if (i >= total) return;
    }
    const float4 v = *(const float4*)(X + i);
    __nv_bfloat16 a0 = __float2bfloat16(v.x), a1 = __float2bfloat16(v.y);
    __nv_bfloat16 a2 = __float2bfloat16(v.z), a3 = __float2bfloat16(v.w);
    g_b0[i + 0] = a0; g_b0[i + 1] = a1; g_b0[i + 2] = a2; g_b0[i + 3] = a3;
    g_b1[i + 0] = __float2bfloat16(v.x - __bfloat162float(a0));
    g_b1[i + 1] = __float2bfloat16(v.y - __bfloat162float(a1));
    g_b1[i + 2] = __float2bfloat16(v.z - __bfloat162float(a2));
    g_b1[i + 3] = __float2bfloat16(v.w - __bfloat162float(a3));
}

// ---------------------------------------------------------------------------
// main: triangle tiles, HMMA bf16x2-split, fused dual epilogue.
// grid = nT*(nT+1)/2, block = 256 (8 warps, 2x4 warp grid, 64x32 warp tiles).
// ---------------------------------------------------------------------------
__global__ __launch_bounds__(256, 1)
void binloss_mma(int n, int d) {
    __shared__ __align__(16) __nv_bfloat16 sT[4][BT][SPE];  // A0,A1,B0,B1
    __shared__ float sRP[4][BT], sRN[4][BT];
    __shared__ float sCP[2][BT], sCN[2][BT];
    __shared__ int tR[BT], tC[BT];
    __shared__ float sSpec[8][4];

    const int nT = n / BT;
    int idx = blockIdx.x, bi = 0;
    while (idx >= nT - bi) { idx -= nT - bi; bi++; }
    const int bj = bi + idx;
    const bool offd = (bi != bj);
    const int rowBlk = bi * BT, colBlk = bj * BT;

    const int tid = threadIdx.x;
    const int w = tid >> 5, l = tid & 31;
    const int wm = w & 1, wn = w >> 1;          // 2 x 4 warp grid
    const int lr15 = l & 15, lh8 = (l >> 4) * 8;

    if (tid < BT) { tR[tid] = g_tgt[rowBlk + tid]; tC[tid] = g_tgt[colBlk + tid]; }

    float acc[4][4][4];
#pragma unroll
    for (int a = 0; a < 4; a++)
#pragma unroll
        for (int b = 0; b < 4; b++)
#pragma unroll
            for (int r = 0; r < 4; r++) acc[a][b][r] = 0.f;

    const uint32_t sbase = smem_u32(&sT[0][0][0]);
    const int nChunks = d / KC;

    for (int c = 0; c < nChunks; c++) {
        __syncthreads();
        const int k0 = c * KC;
#pragma unroll
        for (int u8 = 0; u8 < 8; u8++) {
            const int u    = tid + u8 * 256;
            const int tile = u >> 9;
            const int r    = (u >> 2) & 127;
            const int cc   = u & 3;
            const int grow = (tile < 2 ? rowBlk : colBlk) + r;
            const __nv_bfloat16* src = (tile & 1) ? g_b1 : g_b0;
            const uint4 v = *(const uint4*)(src + (size_t)grow * d + k0 + cc * 8);
            *(uint4*)(&sT[tile][r][cc * 8]) = v;
        }
        __syncthreads();

#pragma unroll
        for (int ks = 0; ks < KC; ks += 16) {
            const uint32_t koff = (uint32_t)(ks + lh8) * 2;
            // B fragments: two ldmatrix.x4 per operand (each covers n16 x k16)
            uint32_t b0f[8], b1f[8];
            {
                const uint32_t bb = sbase + 2u * (BT * SPE * 2) +
                                    (uint32_t)(wn * 32 + lr15) * (SPE * 2) + koff;
                LDMX4(b0f + 0, bb);
                LDMX4(b0f + 4, bb + 16u * (SPE * 2));
                const uint32_t cb = bb + (uint32_t)(BT * SPE * 2);
                LDMX4(b1f + 0, cb);
                LDMX4(b1f + 4, cb + 16u * (SPE * 2));
            }
#pragma unroll
            for (int mi = 0; mi < 4; mi++) {
                uint32_t a0f[4], a1f[4];
                const uint32_t ab = sbase +
                    (uint32_t)(wm * 64 + mi * 16 + lr15) * (SPE * 2) + koff;
                LDMX4(a0f, ab);
                LDMX4(a1f, ab + (uint32_t)(BT * SPE * 2));
#pragma unroll
                for (int nj = 0; nj < 4; nj++) {
                    const int h = (nj >> 1) * 4 + (nj & 1);
                    float* D = acc[mi][nj];
                    MMA16816(D, a0f, b0f[h], b0f[h + 2]);
                    MMA16816(D, a0f, b1f[h], b1f[h + 2]);
                    MMA16816(D, a1f, b0f[h], b0f[h + 2]);
                }
            }
        }
    }

    // ---- fused epilogue ----
    const float ALPHA = 40.f, MARGIN = 0.5f;
    const int r0 = l >> 2, c0 = (l & 3) * 2;
    float rowP[8], rowN[8], colP[8], colN[8];
#pragma unroll
    for (int g = 0; g < 8; g++) { rowP[g] = rowN[g] = colP[g] = colN[g] = 0.f; }
    float sp = 0.f, sn = 0.f, spc = 0.f, snc = 0.f;

#pragma unroll
    for (int mi = 0; mi < 4; mi++) {
#pragma unroll
        for (int rh = 0; rh < 2; rh++) {
            const int rloc = wm * 64 + mi * 16 + r0 + rh * 8;
            const int gr = rowBlk + rloc;
            const int tr = tR[rloc];
            const bool isLastRow = (gr == n - 1);
            const int g = mi * 2 + rh;
#pragma unroll
            for (int nj = 0; nj < 4; nj++) {
#pragma unroll
                for (int p = 0; p < 2; p++) {
                    const int cloc = wn * 32 + nj * 8 + c0 + p;
                    const int gc = colBlk + cloc;
                    const int h = nj * 2 + p;
                    const float sv = acc[mi][nj][rh * 2 + p];
                    if (gc == gr) {
                        if (g_diag_in[gr]) {
                            const float dv = g_diag_val[gr];
                            rowP[g] += softplus_fast(-2.f * (dv - MARGIN));
                            if (isLastRow) sp += dv;
                        }
                    } else {
                        const bool same = (tr == tC[cloc]);
                        const float z = same ? (-2.f * (sv - MARGIN))
                                             : (ALPHA * (sv - MARGIN));
                        const float lv = softplus_fast(z);
                        if (same) {
                            rowP[g] += lv; colP[h] += lv;
                            if (isLastRow) sp += sv;
                            if (offd && gc == n - 1) spc += sv;
                        } else {
                            rowN[g] += lv; colN[h] += lv;
                            if (isLastRow) sn += sv;
                            if (offd && gc == n - 1) snc += sv;
                        }
                    }
                }
            }
        }
    }

    // row reduce: lanes sharing r0 (xor 1,2)
#pragma unroll
    for (int g = 0; g < 8; g++) {
        rowP[g] += __shfl_xor_sync(0xffffffffu, rowP[g], 1);
        rowP[g] += __shfl_xor_sync(0xffffffffu, rowP[g], 2);
        rowN[g] += __shfl_xor_sync(0xffffffffu, rowN[g], 1);
        rowN[g] += __shfl_xor_sync(0xffffffffu, rowN[g], 2);
    }
    if ((l & 3) == 0) {
#pragma unroll
        for (int g = 0; g < 8; g++) {
            const int rloc = wm * 64 + (g >> 1) * 16 + r0 + (g & 1) * 8;
            sRP[wn][rloc] = rowP[g];
            sRN[wn][rloc] = rowN[g];
        }
    }
    // col reduce: lanes sharing c0 (xor 4,8,16)
#pragma unroll
    for (int h = 0; h < 8; h++) {
        colP[h] += __shfl_xor_sync(0xffffffffu, colP[h], 4);
        colP[h] += __shfl_xor_sync(0xffffffffu, colP[h], 8);
        colP[h] += __shfl_xor_sync(0xffffffffu, colP[h], 16);
        colN[h] += __shfl_xor_sync(0xffffffffu, colN[h], 4);
        colN[h] += __shfl_xor_sync(0xffffffffu, colN[h], 8);
        colN[h] += __shfl_xor_sync(0xffffffffu, colN[h], 16);
    }
    if (l < 4) {
#pragma unroll
        for (int h = 0; h < 8; h++) {
            const int cloc = wn * 32 + (h >> 1) * 8 + l * 2 + (h & 1);
            sCP[wm][cloc] = colP[h];
            sCN[wm][cloc] = colN[h];
        }
    }
    // specials: full-warp reduce
#pragma unroll
    for (int o = 16; o > 0; o >>= 1) {
        sp  += __shfl_xor_sync(0xffffffffu, sp,  o);
        sn  += __shfl_xor_sync(0xffffffffu, sn,  o);
        spc += __shfl_xor_sync(0xffffffffu, spc, o);
        snc += __shfl_xor_sync(0xffffffffu, snc, o);
    }
    if (l == 0) { sSpec[w][0] = sp; sSpec[w][1] = sn; sSpec[w][2] = spc; sSpec[w][3] = snc; }
    __syncthreads();

    if (tid < BT) {
        g_pos_part[bj * n + rowBlk + tid] =
            sRP[0][tid] + sRP[1][tid] + sRP[2][tid] + sRP[3][tid];
        g_neg_part[bj * n + rowBlk + tid] =
            sRN[0][tid] + sRN[1][tid] + sRN[2][tid] + sRN[3][tid];
    } else if (offd) {
        const int cc = tid - BT;
        g_pos_part[bi * n + colBlk + cc] = sCP[0][cc] + sCP[1][cc];
        g_neg_part[bi * n + colBlk + cc] = sCN[0][cc] + sCN[1][cc];
    }
    if (tid == 0 && bj == nT - 1) {
        float a0 = 0.f, a1 = 0.f, a2 = 0.f, a3 = 0.f;
#pragma unroll
        for (int ww = 0; ww < 8; ww++) {
            a0 += sSpec[ww][0]; a1 += sSpec[ww][1];
            a2 += sSpec[ww][2]; a3 += sSpec[ww][3];
        }
        if (offd) { g_last_part[bi][0] = a2; g_last_part[bi][1] = a3; }
        else      { g_last_part[bj][0] = a0; g_last_part[bj][1] = a1; }
    }
}

// ---------------------------------------------------------------------------
__global__ void finalize1_kernel(int n, int nTiles) {
    __shared__ float sLoss[128];
    __shared__ float sInv[128];
    const int t = threadIdx.x;
    const int i = blockIdx.x * 128 + t;
    float loss = 0.f, inv = 0.f;
    if (i < n) {
        float ps = 0.f, ns = 0.f;
        for (int b = 0; b < nTiles; b++) {
            ps += g_pos_part[b * n + i];
            ns += g_neg_part[b * n + i];
        }
        const int c = g_hist[g_tgt[i]];
        const float pc = (float)(c - 1 + g_diag_in[i]);
        const float nc = (float)(n - c);
        const float pl = ps / fmaxf(pc, 1.f);
        const float nl = ns / fmaxf(nc, 1.f);
        if (nc > 0.f) loss = pl + nl; else inv = 1.f;
    }
    sLoss[t] = loss; sInv[t] = inv;
    __syncthreads();
    for (int s = 64; s > 0; s >>= 1) {
        if (t < s) { sLoss[t] += sLoss[t + s]; sInv[t] += sInv[t + s]; }
        __syncthreads();
    }
    if (t == 0) { g_loss_part[blockIdx.x] = sLoss[0]; g_inv_part[blockIdx.x] = sInv[0]; }
}

__global__ void finalize2_kernel(float* __restrict__ out, int n, int nTiles, int nB) {
    const int t = threadIdx.x;
    float loss = (t < nB) ? g_loss_part[t] : 0.f;
    float inv  = (t < nB) ? g_inv_part[t]  : 0.f;
    float sp   = (t < nTiles) ? g_last_part[t][0] : 0.f;
    float sn   = (t < nTiles) ? g_last_part[t][1] : 0.f;
#pragma unroll
    for (int off = 16; off > 0; off >>= 1) {
        loss += __shfl_down_sync(0xffffffffu, loss, off);
        inv  += __shfl_down_sync(0xffffffffu, inv,  off);
        sp   += __shfl_down_sync(0xffffffffu, sp,   off);
        sn   += __shfl_down_sync(0xffffffffu, sn,   off);
    }
    if (t == 0) {
        const int c = g_hist[g_tgt[n - 1]];
        const float pc = (float)(c - 1 + g_diag_in[n - 1]);
        out[0] = loss / (float)n;
        out[1] = inv / (float)n;
        out[2] = sp / fmaxf(pc, 1.f);
        out[3] = sn / fmaxf((float)(n - c), 1.f);
    }
}

// ---------------------------------------------------------------------------
extern "C" void kernel_launch(void* const* d_in, const int* in_sizes, int n_in,
                              void* d_out, int out_size) {
    int ix = 0, it = 1;
    if (n_in >= 2 && in_sizes[0] < in_sizes[1]) { ix = 1; it = 0; }
    const float* X = (const float*)d_in[ix];
    const void*  T = d_in[it];
    const int n = in_sizes[it];
    const int d = in_sizes[ix] / n;
    const int nT = n / BT;
    const int nBlocks = nT * (nT + 1) / 2;
    const int nFin = (n + 127) / 128;
    const int total = n * d;

    prep_kernel<<<1, 256>>>(T, n);
    diag_kernel<<<(n + 255) / 256, 256>>>(X, n, d);
    split_kernel<<<(total / 4 + 255) / 256, 256>>>(X, total);
    binloss_mma<<<nBlocks, 256>>>(n, d);
    finalize1_kernel<<<nFin, 128>>>(n, nT);
    finalize2_kernel<<<1, 32>>>((float*)d_out, n, nT, nFin);
}

// round 7
// speedup vs baseline: 3.2086x; 1.4292x over previous
#include <cuda_runtime.h>
#include <cuda_bf16.h>
#include <stdint.h>

// ---------------------------------------------------------------------------
// BinomialLoss, round 7: R6 with the diag_split coverage bug fixed (u<64).
// HMMA bf16x2-split GEMM + cp.async 3-stage pipeline, fused split+diag,
// triangle tiles, dual epilogue.
// Diagonal <1.0 decision: exact sequential ascending-k fp32 FMA chain.
// ---------------------------------------------------------------------------

#define NMAX   4096
#define DMAX   512
#define CLSMAX 512
#define TILES_MAX 32
#define BT   128
#define KC   32
#define SPE  40                         // smem row stride in bf16 (80 B)
#define STAGES 3
#define TILE_B  (BT * SPE * 2)          // 10240 B per tile
#define STAGE_B (4 * TILE_B)            // 40960 B per stage (A0,A1,B0,B1)

// -------- scratch ----------------------------------------------------------
__device__ int   g_tgt[NMAX];
__device__ int   g_hist[CLSMAX];
__device__ float g_diag_val[NMAX];
__device__ int   g_diag_in[NMAX];
__device__ float g_pos_part[TILES_MAX * NMAX];
__device__ float g_neg_part[TILES_MAX * NMAX];
__device__ float g_last_part[TILES_MAX][2];
__device__ float g_loss_part[64];
__device__ float g_inv_part[64];
__device__ __nv_bfloat16 g_b0[NMAX * DMAX];
__device__ __nv_bfloat16 g_b1[NMAX * DMAX];

__device__ __forceinline__ uint32_t smem_u32(const void* p) {
    uint32_t a;
    asm("{ .reg .u64 t; cvta.to.shared.u64 t, %1; cvt.u32.u64 %0, t; }" : "=r"(a) : "l"(p));
    return a;
}
__device__ __forceinline__ float softplus_fast(float z) {
    return fmaxf(z, 0.f) + __logf(1.f + __expf(-fabsf(z)));
}
__device__ __forceinline__ void cp16(uint32_t s, const void* g) {
    asm volatile("cp.async.cg.shared.global [%0], [%1], 16;" :: "r"(s), "l"(g));
}
__device__ __forceinline__ void cp_commit() {
    asm volatile("cp.async.commit_group;" ::: "memory");
}
__device__ __forceinline__ void cp_wait1() {
    asm volatile("cp.async.wait_group 1;" ::: "memory");
}

#define LDMX4(R, ADDR)                                                          \
    asm volatile("ldmatrix.sync.aligned.m8n8.x4.shared.b16 {%0,%1,%2,%3}, [%4];"\
        : "=r"((R)[0]), "=r"((R)[1]), "=r"((R)[2]), "=r"((R)[3]) : "r"(ADDR))

#define MMA16816(D, A, B0r, B1r)                                                \
    asm volatile(                                                               \
        "mma.sync.aligned.m16n8k16.row.col.f32.bf16.bf16.f32 "                  \
        "{%0,%1,%2,%3}, {%4,%5,%6,%7}, {%8,%9}, {%0,%1,%2,%3};"                 \
        : "+f"((D)[0]), "+f"((D)[1]), "+f"((D)[2]), "+f"((D)[3])                \
        : "r"((A)[0]), "r"((A)[1]), "r"((A)[2]), "r"((A)[3]),                   \
          "r"(B0r), "r"(B1r))

// ---------------------------------------------------------------------------
__global__ void prep_kernel(const void* __restrict__ tgt_raw, int n) {
    __shared__ int sh[CLSMAX];
    __shared__ int is64;
    const int t = threadIdx.x;
    if (t == 0) is64 = 1;
    for (int i = t; i < CLSMAX; i += blockDim.x) sh[i] = 0;
    __syncthreads();
    const long long* p64 = (const long long*)tgt_raw;
    const int*       p32 = (const int*)tgt_raw;
    for (int i = t; i < 64 && i < n; i += blockDim.x) {
        long long v = p64[i];
        if (v < 0 || v >= (long long)CLSMAX) atomicAnd(&is64, 0);
    }
    __syncthreads();
    const bool use64 = (is64 != 0);
    for (int i = t; i < n; i += blockDim.x) {
        int v = use64 ? (int)p64[i] : p32[i];
        if (v < 0) v = 0;
        if (v >= CLSMAX) v = CLSMAX - 1;
        g_tgt[i] = v;
        atomicAdd(&sh[v], 1);
    }
    __syncthreads();
    for (int i = t; i < CLSMAX; i += blockDim.x) g_hist[i] = sh[i];
}

// ---------------------------------------------------------------------------
// fused split + diag: coalesced tile load -> smem; coalesced bf16 writes;
// per-row chain from smem in EXACT ascending-k order (decision-preserving).
// grid = n/128 blocks x 128 threads. 128x64 tile = 8192 elems = 64 iters.
// ---------------------------------------------------------------------------
__global__ void diag_split_kernel(const float* __restrict__ X, int n, int d) {
    __shared__ float sx[128][65];
    const int t = threadIdx.x;
    const int rowBlk = blockIdx.x * 128;
    float acc = 0.f;
    for (int k0 = 0; k0 < d; k0 += 64) {
        __syncthreads();
#pragma unroll
        for (int u = 0; u < 64; u++) {          // FIX: full 8192-elem coverage
            const int e = t + u * 128;          // 0..8191
            const int r = e >> 6, c = e & 63;
            const size_t gi = (size_t)(rowBlk + r) * d + k0 + c;
            const float v = X[gi];
            const __nv_bfloat16 b0 = __float2bfloat16(v);
            g_b0[gi] = b0;
            g_b1[gi] = __float2bfloat16(v - __bfloat162float(b0));
            sx[r][c] = v;
        }
        __syncthreads();
#pragma unroll 8
        for (int c = 0; c < 64; c++)
            acc = fmaf(sx[t][c], sx[t][c], acc); // sequential, do not reassociate
    }
    g_diag_val[rowBlk + t] = acc;
    g_diag_in[rowBlk + t]  = (acc < 1.0f) ? 1 : 0;
}

// ---------------------------------------------------------------------------
// main: triangle tiles, HMMA bf16x2-split, cp.async 3-stage ring.
// grid = nT*(nT+1)/2, block = 256 (2x4 warp grid, 64x32 warp tiles).
// ---------------------------------------------------------------------------
__global__ __launch_bounds__(256, 1)
void binloss_mma(int n, int d) {
    extern __shared__ __align__(16) char dyn_smem[];
    __shared__ float sRP[4][BT], sRN[4][BT];
    __shared__ float sCP[2][BT], sCN[2][BT];
    __shared__ int tR[BT], tC[BT];
    __shared__ float sSpec[8][4];

    const int nT = n / BT;
    int idx = blockIdx.x, bi = 0;
    while (idx >= nT - bi) { idx -= nT - bi; bi++; }
    const int bj = bi + idx;
    const bool offd = (bi != bj);
    const int rowBlk = bi * BT, colBlk = bj * BT;

    const int tid = threadIdx.x;
    const int w = tid >> 5, l = tid & 31;
    const int wm = w & 1, wn = w >> 1;
    const int lr15 = l & 15, lh8 = (l >> 4) * 8;

    if (tid < BT) { tR[tid] = g_tgt[rowBlk + tid]; tC[tid] = g_tgt[colBlk + tid]; }

    float acc[4][4][4];
#pragma unroll
    for (int a = 0; a < 4; a++)
#pragma unroll
        for (int b = 0; b < 4; b++)
#pragma unroll
            for (int r = 0; r < 4; r++) acc[a][b][r] = 0.f;

    const uint32_t sbase = smem_u32(dyn_smem);
    const int nChunks = d / KC;

#define PREFETCH(CHUNK, STG)                                                    \
    do {                                                                        \
        const int k0_ = (CHUNK) * KC;                                           \
        const uint32_t sb_ = sbase + (uint32_t)(STG) * STAGE_B;                 \
        _Pragma("unroll")                                                       \
        for (int u = 0; u < 8; u++) {                                           \
            const int e = tid + u * 256;                                        \
            const int tile = e >> 9;                                            \
            const int r = (e >> 2) & 127;                                       \
            const int cc = e & 3;                                               \
            const int grow = (tile < 2 ? rowBlk : colBlk) + r;                  \
            const __nv_bfloat16* src_ = (tile & 1) ? g_b1 : g_b0;               \
            cp16(sb_ + (uint32_t)(tile * TILE_B + r * (SPE * 2) + cc * 16),     \
                 src_ + (size_t)grow * d + k0_ + cc * 8);                       \
        }                                                                       \
    } while (0)

    PREFETCH(0, 0); cp_commit();
    PREFETCH(1, 1); cp_commit();

    for (int c = 0; c < nChunks; c++) {
        cp_wait1();
        __syncthreads();
        const uint32_t stageBase = sbase + (uint32_t)(c % STAGES) * STAGE_B;

#pragma unroll
        for (int ks = 0; ks < KC; ks += 16) {
            const uint32_t koff = (uint32_t)(ks + lh8) * 2;
            uint32_t b0f[8], b1f[8];
            {
                const uint32_t bb = stageBase + 2u * TILE_B +
                                    (uint32_t)(wn * 32 + lr15) * (SPE * 2) + koff;
                LDMX4(b0f + 0, bb);
                LDMX4(b0f + 4, bb + 16u * (SPE * 2));
                const uint32_t cb = bb + (uint32_t)TILE_B;
                LDMX4(b1f + 0, cb);
                LDMX4(b1f + 4, cb + 16u * (SPE * 2));
            }
#pragma unroll
            for (int mi = 0; mi < 4; mi++) {
                uint32_t a0f[4], a1f[4];
                const uint32_t ab = stageBase +
                    (uint32_t)(wm * 64 + mi * 16 + lr15) * (SPE * 2) + koff;
                LDMX4(a0f, ab);
                LDMX4(a1f, ab + (uint32_t)TILE_B);
#pragma unroll
                for (int nj = 0; nj < 4; nj++) {
                    const int h = (nj >> 1) * 4 + (nj & 1);
                    float* D = acc[mi][nj];
                    MMA16816(D, a0f, b0f[h], b0f[h + 2]);
                    MMA16816(D, a0f, b1f[h], b1f[h + 2]);
                    MMA16816(D, a1f, b0f[h], b0f[h + 2]);
                }
            }
        }
        __syncthreads();
        if (c + STAGES - 1 < nChunks)
            PREFETCH(c + STAGES - 1, (c + STAGES - 1) % STAGES);
        cp_commit();
    }
#undef PREFETCH

    // ---- fused epilogue ----
    const float ALPHA = 40.f, MARGIN = 0.5f;
    const int r0 = l >> 2, c0 = (l & 3) * 2;
    float rowP[8], rowN[8], colP[8], colN[8];
#pragma unroll
    for (int g = 0; g < 8; g++) { rowP[g] = rowN[g] = colP[g] = colN[g] = 0.f; }
    float sp = 0.f, sn = 0.f, spc = 0.f, snc = 0.f;

#pragma unroll
    for (int mi = 0; mi < 4; mi++) {
#pragma unroll
        for (int rh = 0; rh < 2; rh++) {
            const int rloc = wm * 64 + mi * 16 + r0 + rh * 8;
            const int gr = rowBlk + rloc;
            const int tr = tR[rloc];
            const bool isLastRow = (gr == n - 1);
            const int g = mi * 2 + rh;
#pragma unroll
            for (int nj = 0; nj < 4; nj++) {
#pragma unroll
                for (int p = 0; p < 2; p++) {
                    const int cloc = wn * 32 + nj * 8 + c0 + p;
                    const int gc = colBlk + cloc;
                    const int h = nj * 2 + p;
                    const float sv = acc[mi][nj][rh * 2 + p];
                    if (gc == gr) {
                        if (g_diag_in[gr]) {
                            const float dv = g_diag_val[gr];
                            rowP[g] += softplus_fast(-2.f * (dv - MARGIN));
                            if (isLastRow) sp += dv;
                        }
                    } else {
                        const bool same = (tr == tC[cloc]);
                        const float z = same ? (-2.f * (sv - MARGIN))
                                             : (ALPHA * (sv - MARGIN));
                        const float lv = softplus_fast(z);
                        if (same) {
                            rowP[g] += lv; colP[h] += lv;
                            if (isLastRow) sp += sv;
                            if (offd && gc == n - 1) spc += sv;
                        } else {
                            rowN[g] += lv; colN[h] += lv;
                            if (isLastRow) sn += sv;
                            if (offd && gc == n - 1) snc += sv;
                        }
                    }
                }
            }
        }
    }

#pragma unroll
    for (int g = 0; g < 8; g++) {
        rowP[g] += __shfl_xor_sync(0xffffffffu, rowP[g], 1);
        rowP[g] += __shfl_xor_sync(0xffffffffu, rowP[g], 2);
        rowN[g] += __shfl_xor_sync(0xffffffffu, rowN[g], 1);
        rowN[g] += __shfl_xor_sync(0xffffffffu, rowN[g], 2);
    }
    if ((l & 3) == 0) {
#pragma unroll
        for (int g = 0; g < 8; g++) {
            const int rloc = wm * 64 + (g >> 1) * 16 + r0 + (g & 1) * 8;
            sRP[wn][rloc] = rowP[g];
            sRN[wn][rloc] = rowN[g];
        }
    }
#pragma unroll
    for (int h = 0; h < 8; h++) {
        colP[h] += __shfl_xor_sync(0xffffffffu, colP[h], 4);
        colP[h] += __shfl_xor_sync(0xffffffffu, colP[h], 8);
        colP[h] += __shfl_xor_sync(0xffffffffu, colP[h], 16);
        colN[h] += __shfl_xor_sync(0xffffffffu, colN[h], 4);
        colN[h] += __shfl_xor_sync(0xffffffffu, colN[h], 8);
        colN[h] += __shfl_xor_sync(0xffffffffu, colN[h], 16);
    }
    if (l < 4) {
#pragma unroll
        for (int h = 0; h < 8; h++) {
            const int cloc = wn * 32 + (h >> 1) * 8 + l * 2 + (h & 1);
            sCP[wm][cloc] = colP[h];
            sCN[wm][cloc] = colN[h];
        }
    }
#pragma unroll
    for (int o = 16; o > 0; o >>= 1) {
        sp  += __shfl_xor_sync(0xffffffffu, sp,  o);
        sn  += __shfl_xor_sync(0xffffffffu, sn,  o);
        spc += __shfl_xor_sync(0xffffffffu, spc, o);
        snc += __shfl_xor_sync(0xffffffffu, snc, o);
    }
    if (l == 0) { sSpec[w][0] = sp; sSpec[w][1] = sn; sSpec[w][2] = spc; sSpec[w][3] = snc; }
    __syncthreads();

    if (tid < BT) {
        g_pos_part[bj * n + rowBlk + tid] =
            sRP[0][tid] + sRP[1][tid] + sRP[2][tid] + sRP[3][tid];
        g_neg_part[bj * n + rowBlk + tid] =
            sRN[0][tid] + sRN[1][tid] + sRN[2][tid] + sRN[3][tid];
    } else if (offd) {
        const int cc = tid - BT;
        g_pos_part[bi * n + colBlk + cc] = sCP[0][cc] + sCP[1][cc];
        g_neg_part[bi * n + colBlk + cc] = sCN[0][cc] + sCN[1][cc];
    }
    if (tid == 0 && bj == nT - 1) {
        float a0 = 0.f, a1 = 0.f, a2 = 0.f, a3 = 0.f;
#pragma unroll
        for (int ww = 0; ww < 8; ww++) {
            a0 += sSpec[ww][0]; a1 += sSpec[ww][1];
            a2 += sSpec[ww][2]; a3 += sSpec[ww][3];
        }
        if (offd) { g_last_part[bi][0] = a2; g_last_part[bi][1] = a3; }
        else      { g_last_part[bj][0] = a0; g_last_part[bj][1] = a1; }
    }
}

// ---------------------------------------------------------------------------
__global__ void finalize1_kernel(int n, int nTiles) {
    __shared__ float sLoss[128];
    __shared__ float sInv[128];
    const int t = threadIdx.x;
    const int i = blockIdx.x * 128 + t;
    float loss = 0.f, inv = 0.f;
    if (i < n) {
        float ps = 0.f, ns = 0.f;
        for (int b = 0; b < nTiles; b++) {
            ps += g_pos_part[b * n + i];
            ns += g_neg_part[b * n + i];
        }
        const int c = g_hist[g_tgt[i]];
        const float pc = (float)(c - 1 + g_diag_in[i]);
        const float nc = (float)(n - c);
        const float pl = ps / fmaxf(pc, 1.f);
        const float nl = ns / fmaxf(nc, 1.f);
        if (nc > 0.f) loss = pl + nl; else inv = 1.f;
    }
    sLoss[t] = loss; sInv[t] = inv;
    __syncthreads();
    for (int s = 64; s > 0; s >>= 1) {
        if (t < s) { sLoss[t] += sLoss[t + s]; sInv[t] += sInv[t + s]; }
        __syncthreads();
    }
    if (t == 0) { g_loss_part[blockIdx.x] = sLoss[0]; g_inv_part[blockIdx.x] = sInv[0]; }
}

__global__ void finalize2_kernel(float* __restrict__ out, int n, int nTiles, int nB) {
    const int t = threadIdx.x;
    float loss = (t < nB) ? g_loss_part[t] : 0.f;
    float inv  = (t < nB) ? g_inv_part[t]  : 0.f;
    float sp   = (t < nTiles) ? g_last_part[t][0] : 0.f;
    float sn   = (t < nTiles) ? g_last_part[t][1] : 0.f;
#pragma unroll
    for (int off = 16; off > 0; off >>= 1) {
        loss += __shfl_down_sync(0xffffffffu, loss, off);
        inv  += __shfl_down_sync(0xffffffffu, inv,  off);
        sp   += __shfl_down_sync(0xffffffffu, sp,   off);
        sn   += __shfl_down_sync(0xffffffffu, sn,   off);
    }
    if (t == 0) {
        const int c = g_hist[g_tgt[n - 1]];
        const float pc = (float)(c - 1 + g_diag_in[n - 1]);
        out[0] = loss / (float)n;
        out[1] = inv / (float)n;
        out[2] = sp / fmaxf(pc, 1.f);
        out[3] = sn / fmaxf((float)(n - c), 1.f);
    }
}

// ---------------------------------------------------------------------------
extern "C" void kernel_launch(void* const* d_in, const int* in_sizes, int n_in,
                              void* d_out, int out_size) {
    int ix = 0, it = 1;
    if (n_in >= 2 && in_sizes[0] < in_sizes[1]) { ix = 1; it = 0; }
    const float* X = (const float*)d_in[ix];
    const void*  T = d_in[it];
    const int n = in_sizes[it];
    const int d = in_sizes[ix] / n;
    const int nT = n / BT;
    const int nBlocks = nT * (nT + 1) / 2;
    const int nFin = (n + 127) / 128;
    const int dynBytes = STAGES * STAGE_B;   // 122880

    static int attr_set = 0;
    if (!attr_set) {
        cudaFuncSetAttribute(binloss_mma, cudaFuncAttributeMaxDynamicSharedMemorySize, dynBytes);
        attr_set = 1;
    }

    prep_kernel<<<1, 256>>>(T, n);
    diag_split_kernel<<<n / 128, 128>>>(X, n, d);
    binloss_mma<<<nBlocks, 256, dynBytes>>>(n, d);
    finalize1_kernel<<<nFin, 128>>>(n, nT);
    finalize2_kernel<<<1, 32>>>((float*)d_out, n, nT, nFin);
}

// round 8
// speedup vs baseline: 3.2927x; 1.0262x over previous
#include <cuda_runtime.h>
#include <cuda_bf16.h>
#include <stdint.h>

// ---------------------------------------------------------------------------
// BinomialLoss, round 8: KC=64 2-stage double buffer with prefetch-during-
// compute; 256-thread diag_split with packed bf16x2 stores.
// HMMA bf16x2-split GEMM, triangle tiles, dual epilogue.
// Diagonal <1.0 decision: exact sequential ascending-k fp32 FMA chain.
// ---------------------------------------------------------------------------

#define NMAX   4096
#define DMAX   512
#define CLSMAX 512
#define TILES_MAX 32
#define BT   128
#define KC   64
#define SPE  72                         // smem row stride in bf16 (144 B)
#define TILE_B  (BT * SPE * 2)          // 18432 B per tile
#define STAGE_B (4 * TILE_B)            // 73728 B per stage (A0,A1,B0,B1)

// -------- scratch ----------------------------------------------------------
__device__ int   g_tgt[NMAX];
__device__ int   g_hist[CLSMAX];
__device__ float g_diag_val[NMAX];
__device__ int   g_diag_in[NMAX];
__device__ float g_pos_part[TILES_MAX * NMAX];
__device__ float g_neg_part[TILES_MAX * NMAX];
__device__ float g_last_part[TILES_MAX][2];
__device__ float g_loss_part[64];
__device__ float g_inv_part[64];
__device__ __nv_bfloat16 g_b0[NMAX * DMAX];
__device__ __nv_bfloat16 g_b1[NMAX * DMAX];

__device__ __forceinline__ uint32_t smem_u32(const void* p) {
    uint32_t a;
    asm("{ .reg .u64 t; cvta.to.shared.u64 t, %1; cvt.u32.u64 %0, t; }" : "=r"(a) : "l"(p));
    return a;
}
__device__ __forceinline__ float softplus_fast(float z) {
    return fmaxf(z, 0.f) + __logf(1.f + __expf(-fabsf(z)));
}
__device__ __forceinline__ void cp16(uint32_t s, const void* g) {
    asm volatile("cp.async.cg.shared.global [%0], [%1], 16;" :: "r"(s), "l"(g));
}
__device__ __forceinline__ void cp_commit() {
    asm volatile("cp.async.commit_group;" ::: "memory");
}
__device__ __forceinline__ void cp_wait1() {
    asm volatile("cp.async.wait_group 1;" ::: "memory");
}
__device__ __forceinline__ void cp_wait0() {
    asm volatile("cp.async.wait_group 0;" ::: "memory");
}

#define LDMX4(R, ADDR)                                                          \
    asm volatile("ldmatrix.sync.aligned.m8n8.x4.shared.b16 {%0,%1,%2,%3}, [%4];"\
        : "=r"((R)[0]), "=r"((R)[1]), "=r"((R)[2]), "=r"((R)[3]) : "r"(ADDR))

#define MMA16816(D, A, B0r, B1r)                                                \
    asm volatile(                                                               \
        "mma.sync.aligned.m16n8k16.row.col.f32.bf16.bf16.f32 "                  \
        "{%0,%1,%2,%3}, {%4,%5,%6,%7}, {%8,%9}, {%0,%1,%2,%3};"                 \
        : "+f"((D)[0]), "+f"((D)[1]), "+f"((D)[2]), "+f"((D)[3])                \
        : "r"((A)[0]), "r"((A)[1]), "r"((A)[2]), "r"((A)[3]),                   \
          "r"(B0r), "r"(B1r))

// ---------------------------------------------------------------------------
__global__ void prep_kernel(const void* __restrict__ tgt_raw, int n) {
    __shared__ int sh[CLSMAX];
    __shared__ int is64;
    const int t = threadIdx.x;
    if (t == 0) is64 = 1;
    for (int i = t; i < CLSMAX; i += blockDim.x) sh[i] = 0;
    __syncthreads();
    const long long* p64 = (const long long*)tgt_raw;
    const int*       p32 = (const int*)tgt_raw;
    for (int i = t; i < 64 && i < n; i += blockDim.x) {
        long long v = p64[i];
        if (v < 0 || v >= (long long)CLSMAX) atomicAnd(&is64, 0);
    }
    __syncthreads();
    const bool use64 = (is64 != 0);
    for (int i = t; i < n; i += blockDim.x) {
        int v = use64 ? (int)p64[i] : p32[i];
        if (v < 0) v = 0;
        if (v >= CLSMAX) v = CLSMAX - 1;
        g_tgt[i] = v;
        atomicAdd(&sh[v], 1);
    }
    __syncthreads();
    for (int i = t; i < CLSMAX; i += blockDim.x) g_hist[i] = sh[i];
}

// ---------------------------------------------------------------------------
// fused split + diag: 256 threads stage a 128x64 tile (2 elems/thread/iter,
// packed bf16x2 stores), then 128 threads run the EXACT ascending-k chains.
// ---------------------------------------------------------------------------
__global__ void diag_split_kernel(const float* __restrict__ X, int n, int d) {
    __shared__ float sx[128][65];
    const int t = threadIdx.x;
    const int rowBlk = blockIdx.x * 128;
    float acc = 0.f;
    for (int k0 = 0; k0 < d; k0 += 64) {
        __syncthreads();
#pragma unroll
        for (int u = 0; u < 16; u++) {
            const int e2 = (t + u * 256) * 2;     // 0..8190, even
            const int r = e2 >> 6, c = e2 & 63;
            const size_t gi = (size_t)(rowBlk + r) * d + k0 + c;
            const float2 v = *(const float2*)(X + gi);
            const __nv_bfloat162 b = __float22bfloat162_rn(v);
            *(__nv_bfloat162*)(g_b0 + gi) = b;
            float2 rres;
            rres.x = v.x - __bfloat162float(b.x);
            rres.y = v.y - __bfloat162float(b.y);
            *(__nv_bfloat162*)(g_b1 + gi) = __float22bfloat162_rn(rres);
            sx[r][c] = v.x;
            sx[r][c + 1] = v.y;
        }
        __syncthreads();
        if (t < 128) {
#pragma unroll 8
            for (int c = 0; c < 64; c++)
                acc = fmaf(sx[t][c], sx[t][c], acc); // sequential, do not reassociate
        }
    }
    if (t < 128) {
        g_diag_val[rowBlk + t] = acc;
        g_diag_in[rowBlk + t]  = (acc < 1.0f) ? 1 : 0;
    }
}

// ---------------------------------------------------------------------------
// main: triangle tiles, HMMA bf16x2-split, KC=64 2-stage double buffer.
// grid = nT*(nT+1)/2, block = 256 (2x4 warp grid, 64x32 warp tiles).
// ---------------------------------------------------------------------------
__global__ __launch_bounds__(256, 1)
void binloss_mma(int n, int d) {
    extern __shared__ __align__(16) char dyn_smem[];
    __shared__ float sRP[4][BT], sRN[4][BT];
    __shared__ float sCP[2][BT], sCN[2][BT];
    __shared__ int tR[BT], tC[BT];
    __shared__ float sSpec[8][4];

    const int nT = n / BT;
    int idx = blockIdx.x, bi = 0;
    while (idx >= nT - bi) { idx -= nT - bi; bi++; }
    const int bj = bi + idx;
    const bool offd = (bi != bj);
    const int rowBlk = bi * BT, colBlk = bj * BT;

    const int tid = threadIdx.x;
    const int w = tid >> 5, l = tid & 31;
    const int wm = w & 1, wn = w >> 1;
    const int lr15 = l & 15, lh8 = (l >> 4) * 8;

    if (tid < BT) { tR[tid] = g_tgt[rowBlk + tid]; tC[tid] = g_tgt[colBlk + tid]; }

    float acc[4][4][4];
#pragma unroll
    for (int a = 0; a < 4; a++)
#pragma unroll
        for (int b = 0; b < 4; b++)
#pragma unroll
            for (int r = 0; r < 4; r++) acc[a][b][r] = 0.f;

    const uint32_t sbase = smem_u32(dyn_smem);
    const int nChunks = d / KC;                      // 8

    // 4 tiles x 128 rows x 8 16B-units = 4096 cp16 / 256 thr = 16 per thread
#define PREFETCH(CHUNK, STG)                                                    \
    do {                                                                        \
        const int k0_ = (CHUNK) * KC;                                           \
        const uint32_t sb_ = sbase + (uint32_t)(STG) * STAGE_B;                 \
        _Pragma("unroll")                                                       \
        for (int u = 0; u < 16; u++) {                                          \
            const int e = tid + u * 256;                                        \
            const int tile = e >> 10;                                           \
            const int r = (e >> 3) & 127;                                       \
            const int cc = e & 7;                                               \
            const int grow = (tile < 2 ? rowBlk : colBlk) + r;                  \
            const __nv_bfloat16* src_ = (tile & 1) ? g_b1 : g_b0;               \
            cp16(sb_ + (uint32_t)(tile * TILE_B + r * (SPE * 2) + cc * 16),     \
                 src_ + (size_t)grow * d + k0_ + cc * 8);                       \
        }                                                                       \
    } while (0)

    PREFETCH(0, 0);
    cp_commit();

    for (int c = 0; c < nChunks; c++) {
        if (c + 1 < nChunks) {
            PREFETCH(c + 1, (c + 1) & 1);   // overlaps compute of chunk c
            cp_commit();
            cp_wait1();                      // chunk c landed
        } else {
            cp_wait0();
        }
        __syncthreads();
        const uint32_t stageBase = sbase + (uint32_t)(c & 1) * STAGE_B;

#pragma unroll
        for (int ks = 0; ks < KC; ks += 16) {
            const uint32_t koff = (uint32_t)(ks + lh8) * 2;
            uint32_t b0f[8], b1f[8];
            {
                const uint32_t bb = stageBase + 2u * TILE_B +
                                    (uint32_t)(wn * 32 + lr15) * (SPE * 2) + koff;
                LDMX4(b0f + 0, bb);
                LDMX4(b0f + 4, bb + 16u * (SPE * 2));
                const uint32_t cb = bb + (uint32_t)TILE_B;
                LDMX4(b1f + 0, cb);
                LDMX4(b1f + 4, cb + 16u * (SPE * 2));
            }
#pragma unroll
            for (int mi = 0; mi < 4; mi++) {
                uint32_t a0f[4], a1f[4];
                const uint32_t ab = stageBase +
                    (uint32_t)(wm * 64 + mi * 16 + lr15) * (SPE * 2) + koff;
                LDMX4(a0f, ab);
                LDMX4(a1f, ab + (uint32_t)TILE_B);
#pragma unroll
                for (int nj = 0; nj < 4; nj++) {
                    const int h = (nj >> 1) * 4 + (nj & 1);
                    float* D = acc[mi][nj];
                    MMA16816(D, a0f, b0f[h], b0f[h + 2]);
                    MMA16816(D, a0f, b1f[h], b1f[h + 2]);
                    MMA16816(D, a1f, b0f[h], b0f[h + 2]);
                }
            }
        }
        __syncthreads();   // stage (c&1) free for prefetch c+2 next iter
    }
#undef PREFETCH

    // ---- fused epilogue (verified) ----
    const float ALPHA = 40.f, MARGIN = 0.5f;
    const int r0 = l >> 2, c0 = (l & 3) * 2;
    float rowP[8], rowN[8], colP[8], colN[8];
#pragma unroll
    for (int g = 0; g < 8; g++) { rowP[g] = rowN[g] = colP[g] = colN[g] = 0.f; }
    float sp = 0.f, sn = 0.f, spc = 0.f, snc = 0.f;

#pragma unroll
    for (int mi = 0; mi < 4; mi++) {
#pragma unroll
        for (int rh = 0; rh < 2; rh++) {
            const int rloc = wm * 64 + mi * 16 + r0 + rh * 8;
            const int gr = rowBlk + rloc;
            const int tr = tR[rloc];
            const bool isLastRow = (gr == n - 1);
            const int g = mi * 2 + rh;
#pragma unroll
            for (int nj = 0; nj < 4; nj++) {
#pragma unroll
                for (int p = 0; p < 2; p++) {
                    const int cloc = wn * 32 + nj * 8 + c0 + p;
                    const int gc = colBlk + cloc;
                    const int h = nj * 2 + p;
                    const float sv = acc[mi][nj][rh * 2 + p];
                    if (gc == gr) {
                        if (g_diag_in[gr]) {
                            const float dv = g_diag_val[gr];
                            rowP[g] += softplus_fast(-2.f * (dv - MARGIN));
                            if (isLastRow) sp += dv;
                        }
                    } else {
                        const bool same = (tr == tC[cloc]);
                        const float z = same ? (-2.f * (sv - MARGIN))
                                             : (ALPHA * (sv - MARGIN));
                        const float lv = softplus_fast(z);
                        if (same) {
                            rowP[g] += lv; colP[h] += lv;
                            if (isLastRow) sp += sv;
                            if (offd && gc == n - 1) spc += sv;
                        } else {
                            rowN[g] += lv; colN[h] += lv;
                            if (isLastRow) sn += sv;
                            if (offd && gc == n - 1) snc += sv;
                        }
                    }
                }
            }
        }
    }

#pragma unroll
    for (int g = 0; g < 8; g++) {
        rowP[g] += __shfl_xor_sync(0xffffffffu, rowP[g], 1);
        rowP[g] += __shfl_xor_sync(0xffffffffu, rowP[g], 2);
        rowN[g] += __shfl_xor_sync(0xffffffffu, rowN[g], 1);
        rowN[g] += __shfl_xor_sync(0xffffffffu, rowN[g], 2);
    }
    if ((l & 3) == 0) {
#pragma unroll
        for (int g = 0; g < 8; g++) {
            const int rloc = wm * 64 + (g >> 1) * 16 + r0 + (g & 1) * 8;
            sRP[wn][rloc] = rowP[g];
            sRN[wn][rloc] = rowN[g];
        }
    }
#pragma unroll
    for (int h = 0; h < 8; h++) {
        colP[h] += __shfl_xor_sync(0xffffffffu, colP[h], 4);
        colP[h] += __shfl_xor_sync(0xffffffffu, colP[h], 8);
        colP[h] += __shfl_xor_sync(0xffffffffu, colP[h], 16);
        colN[h] += __shfl_xor_sync(0xffffffffu, colN[h], 4);
        colN[h] += __shfl_xor_sync(0xffffffffu, colN[h], 8);
        colN[h] += __shfl_xor_sync(0xffffffffu, colN[h], 16);
    }
    if (l < 4) {
#pragma unroll
        for (int h = 0; h < 8; h++) {
            const int cloc = wn * 32 + (h >> 1) * 8 + l * 2 + (h & 1);
            sCP[wm][cloc] = colP[h];
            sCN[wm][cloc] = colN[h];
        }
    }
#pragma unroll
    for (int o = 16; o > 0; o >>= 1) {
        sp  += __shfl_xor_sync(0xffffffffu, sp,  o);
        sn  += __shfl_xor_sync(0xffffffffu, sn,  o);
        spc += __shfl_xor_sync(0xffffffffu, spc, o);
        snc += __shfl_xor_sync(0xffffffffu, snc, o);
    }
    if (l == 0) { sSpec[w][0] = sp; sSpec[w][1] = sn; sSpec[w][2] = spc; sSpec[w][3] = snc; }
    __syncthreads();

    if (tid < BT) {
        g_pos_part[bj * n + rowBlk + tid] =
            sRP[0][tid] + sRP[1][tid] + sRP[2][tid] + sRP[3][tid];
        g_neg_part[bj * n + rowBlk + tid] =
            sRN[0][tid] + sRN[1][tid] + sRN[2][tid] + sRN[3][tid];
    } else if (offd) {
        const int cc = tid - BT;
        g_pos_part[bi * n + colBlk + cc] = sCP[0][cc] + sCP[1][cc];
        g_neg_part[bi * n + colBlk + cc] = sCN[0][cc] + sCN[1][cc];
    }
    if (tid == 0 && bj == nT - 1) {
        float a0 = 0.f, a1 = 0.f, a2 = 0.f, a3 = 0.f;
#pragma unroll
        for (int ww = 0; ww < 8; ww++) {
            a0 += sSpec[ww][0]; a1 += sSpec[ww][1];
            a2 += sSpec[ww][2]; a3 += sSpec[ww][3];
        }
        if (offd) { g_last_part[bi][0] = a2; g_last_part[bi][1] = a3; }
        else      { g_last_part[bj][0] = a0; g_last_part[bj][1] = a1; }
    }
}

// ---------------------------------------------------------------------------
__global__ void finalize1_kernel(int n, int nTiles) {
    __shared__ float sLoss[128];
    __shared__ float sInv[128];
    const int t = threadIdx.x;
    const int i = blockIdx.x * 128 + t;
    float loss = 0.f, inv = 0.f;
    if (i < n) {
        float ps = 0.f, ns = 0.f;
        for (int b = 0; b < nTiles; b++) {
            ps += g_pos_part[b * n + i];
            ns += g_neg_part[b * n + i];
        }
        const int c = g_hist[g_tgt[i]];
        const float pc = (float)(c - 1 + g_diag_in[i]);
        const float nc = (float)(n - c);
        const float pl = ps / fmaxf(pc, 1.f);
        const float nl = ns / fmaxf(nc, 1.f);
        if (nc > 0.f) loss = pl + nl; else inv = 1.f;
    }
    sLoss[t] = loss; sInv[t] = inv;
    __syncthreads();
    for (int s = 64; s > 0; s >>= 1) {
        if (t < s) { sLoss[t] += sLoss[t + s]; sInv[t] += sInv[t + s]; }
        __syncthreads();
    }
    if (t == 0) { g_loss_part[blockIdx.x] = sLoss[0]; g_inv_part[blockIdx.x] = sInv[0]; }
}

__global__ void finalize2_kernel(float* __restrict__ out, int n, int nTiles, int nB) {
    const int t = threadIdx.x;
    float loss = (t < nB) ? g_loss_part[t] : 0.f;
    float inv  = (t < nB) ? g_inv_part[t]  : 0.f;
    float sp   = (t < nTiles) ? g_last_part[t][0] : 0.f;
    float sn   = (t < nTiles) ? g_last_part[t][1] : 0.f;
#pragma unroll
    for (int off = 16; off > 0; off >>= 1) {
        loss += __shfl_down_sync(0xffffffffu, loss, off);
        inv  += __shfl_down_sync(0xffffffffu, inv,  off);
        sp   += __shfl_down_sync(0xffffffffu, sp,   off);
        sn   += __shfl_down_sync(0xffffffffu, sn,   off);
    }
    if (t == 0) {
        const int c = g_hist[g_tgt[n - 1]];
        const float pc = (float)(c - 1 + g_diag_in[n - 1]);
        out[0] = loss / (float)n;
        out[1] = inv / (float)n;
        out[2] = sp / fmaxf(pc, 1.f);
        out[3] = sn / fmaxf((float)(n - c), 1.f);
    }
}

// ---------------------------------------------------------------------------
extern "C" void kernel_launch(void* const* d_in, const int* in_sizes, int n_in,
                              void* d_out, int out_size) {
    int ix = 0, it = 1;
    if (n_in >= 2 && in_sizes[0] < in_sizes[1]) { ix = 1; it = 0; }
    const float* X = (const float*)d_in[ix];
    const void*  T = d_in[it];
    const int n = in_sizes[it];
    const int d = in_sizes[ix] / n;
    const int nT = n / BT;
    const int nBlocks = nT * (nT + 1) / 2;
    const int nFin = (n + 127) / 128;
    const int dynBytes = 2 * STAGE_B;     // 147456

    static int attr_set = 0;
    if (!attr_set) {
        cudaFuncSetAttribute(binloss_mma, cudaFuncAttributeMaxDynamicSharedMemorySize, dynBytes);
        attr_set = 1;
    }

    prep_kernel<<<1, 256>>>(T, n);
    diag_split_kernel<<<n / 128, 256>>>(X, n, d);
    binloss_mma<<<nBlocks, 256, dynBytes>>>(n, d);
    finalize1_kernel<<<nFin, 128>>>(n, nT);
    finalize2_kernel<<<1, 32>>>((float*)d_out, n, nT, nFin);
}

// round 9
// speedup vs baseline: 3.3252x; 1.0099x over previous
#include <cuda_runtime.h>
#include <cuda_bf16.h>
#include <stdint.h>

// ---------------------------------------------------------------------------
// BinomialLoss, round 9:
//  - software-pipelined (double-buffered) ldmatrix fragments in the mainloop
//  - transposed partials layout [row*32+tile] for coalesced finalize reads
//  - prep folded into diag_split (atomic int histogram; finalize2 re-zeroes)
// HMMA bf16x2-split GEMM, KC=64 2-stage cp.async, triangle tiles, dual epilogue.
// Diagonal <1.0 decision: exact sequential ascending-k fp32 FMA chain.
// ---------------------------------------------------------------------------

#define NMAX   4096
#define DMAX   512
#define CLSMAX 512
#define TILES_MAX 32
#define BT   128
#define KC   64
#define SPE  72                         // smem row stride in bf16 (144 B)
#define TILE_B  (BT * SPE * 2)          // 18432 B per tile
#define STAGE_B (4 * TILE_B)            // 73728 B per stage (A0,A1,B0,B1)

// -------- scratch ----------------------------------------------------------
__device__ int   g_tgt[NMAX];
__device__ int   g_hist[CLSMAX];        // zeroed at module load; finalize2 re-zeroes
__device__ float g_diag_val[NMAX];
__device__ int   g_diag_in[NMAX];
__device__ float g_pos_part[NMAX * TILES_MAX];   // [row*32 + tile]
__device__ float g_neg_part[NMAX * TILES_MAX];
__device__ float g_last_part[TILES_MAX][2];
__device__ float g_loss_part[64];
__device__ float g_inv_part[64];
__device__ __nv_bfloat16 g_b0[NMAX * DMAX];
__device__ __nv_bfloat16 g_b1[NMAX * DMAX];

__device__ __forceinline__ uint32_t smem_u32(const void* p) {
    uint32_t a;
    asm("{ .reg .u64 t; cvta.to.shared.u64 t, %1; cvt.u32.u64 %0, t; }" : "=r"(a) : "l"(p));
    return a;
}
__device__ __forceinline__ float softplus_fast(float z) {
    return fmaxf(z, 0.f) + __logf(1.f + __expf(-fabsf(z)));
}
__device__ __forceinline__ void cp16(uint32_t s, const void* g) {
    asm volatile("cp.async.cg.shared.global [%0], [%1], 16;" :: "r"(s), "l"(g));
}
__device__ __forceinline__ void cp_commit() {
    asm volatile("cp.async.commit_group;" ::: "memory");
}
__device__ __forceinline__ void cp_wait1() {
    asm volatile("cp.async.wait_group 1;" ::: "memory");
}
__device__ __forceinline__ void cp_wait0() {
    asm volatile("cp.async.wait_group 0;" ::: "memory");
}

#define LDMX4(R, ADDR)                                                          \
    asm volatile("ldmatrix.sync.aligned.m8n8.x4.shared.b16 {%0,%1,%2,%3}, [%4];"\
        : "=r"((R)[0]), "=r"((R)[1]), "=r"((R)[2]), "=r"((R)[3]) : "r"(ADDR))

#define MMA16816(D, A, B0r, B1r)                                                \
    asm volatile(                                                               \
        "mma.sync.aligned.m16n8k16.row.col.f32.bf16.bf16.f32 "                  \
        "{%0,%1,%2,%3}, {%4,%5,%6,%7}, {%8,%9}, {%0,%1,%2,%3};"                 \
        : "+f"((D)[0]), "+f"((D)[1]), "+f"((D)[2]), "+f"((D)[3])                \
        : "r"((A)[0]), "r"((A)[1]), "r"((A)[2]), "r"((A)[3]),                   \
          "r"(B0r), "r"(B1r))

// ---------------------------------------------------------------------------
// fused targets + split + diag. grid = n/128 blocks x 256 threads.
// ---------------------------------------------------------------------------
__global__ void diag_split_kernel(const float* __restrict__ X,
                                  const void* __restrict__ tgt_raw, int n, int d) {
    __shared__ float sx[128][65];
    __shared__ int sIs64;
    const int t = threadIdx.x;
    const int rowBlk = blockIdx.x * 128;

    // -- targets: dtype detect (first 64 global entries), convert, histogram --
    if (t == 0) sIs64 = 1;
    __syncthreads();
    const long long* p64 = (const long long*)tgt_raw;
    const int*       p32 = (const int*)tgt_raw;
    if (t < 64) {
        long long v = p64[t];
        if (v < 0 || v >= (long long)CLSMAX) atomicAnd(&sIs64, 0);
    }
    __syncthreads();
    if (t < 128) {
        int v = sIs64 ? (int)p64[rowBlk + t] : p32[rowBlk + t];
        if (v < 0) v = 0;
        if (v >= CLSMAX) v = CLSMAX - 1;
        g_tgt[rowBlk + t] = v;
        atomicAdd(&g_hist[v], 1);        // int adds: order-independent
    }

    // -- split + diag --
    float acc = 0.f;
    for (int k0 = 0; k0 < d; k0 += 64) {
        __syncthreads();
#pragma unroll
        for (int u = 0; u < 16; u++) {
            const int e2 = (t + u * 256) * 2;
            const int r = e2 >> 6, c = e2 & 63;
            const size_t gi = (size_t)(rowBlk + r) * d + k0 + c;
            const float2 v = *(const float2*)(X + gi);
            const __nv_bfloat162 b = __float22bfloat162_rn(v);
            *(__nv_bfloat162*)(g_b0 + gi) = b;
            float2 rres;
            rres.x = v.x - __bfloat162float(b.x);
            rres.y = v.y - __bfloat162float(b.y);
            *(__nv_bfloat162*)(g_b1 + gi) = __float22bfloat162_rn(rres);
            sx[r][c] = v.x;
            sx[r][c + 1] = v.y;
        }
        __syncthreads();
        if (t < 128) {
#pragma unroll 8
            for (int c = 0; c < 64; c++)
                acc = fmaf(sx[t][c], sx[t][c], acc); // sequential, do not reassociate
        }
    }
    if (t < 128) {
        g_diag_val[rowBlk + t] = acc;
        g_diag_in[rowBlk + t]  = (acc < 1.0f) ? 1 : 0;
    }
}

// ---------------------------------------------------------------------------
// main: triangle tiles, HMMA bf16x2-split, KC=64 double buffer,
// software-pipelined fragments.
// ---------------------------------------------------------------------------
__global__ __launch_bounds__(256, 1)
void binloss_mma(int n, int d) {
    extern __shared__ __align__(16) char dyn_smem[];
    __shared__ float sRP[4][BT], sRN[4][BT];
    __shared__ float sCP[2][BT], sCN[2][BT];
    __shared__ int tR[BT], tC[BT];
    __shared__ float sSpec[8][4];

    const int nT = n / BT;
    int idx = blockIdx.x, bi = 0;
    while (idx >= nT - bi) { idx -= nT - bi; bi++; }
    const int bj = bi + idx;
    const bool offd = (bi != bj);
    const int rowBlk = bi * BT, colBlk = bj * BT;

    const int tid = threadIdx.x;
    const int w = tid >> 5, l = tid & 31;
    const int wm = w & 1, wn = w >> 1;
    const int lr15 = l & 15, lh8 = (l >> 4) * 8;

    if (tid < BT) { tR[tid] = g_tgt[rowBlk + tid]; tC[tid] = g_tgt[colBlk + tid]; }

    float acc[4][4][4];
#pragma unroll
    for (int a = 0; a < 4; a++)
#pragma unroll
        for (int b = 0; b < 4; b++)
#pragma unroll
            for (int r = 0; r < 4; r++) acc[a][b][r] = 0.f;

    const uint32_t sbase = smem_u32(dyn_smem);
    const int nChunks = d / KC;                      // 8

#define PREFETCH(CHUNK, STG)                                                    \
    do {                                                                        \
        const int k0_ = (CHUNK) * KC;                                           \
        const uint32_t sb_ = sbase + (uint32_t)(STG) * STAGE_B;                 \
        _Pragma("unroll")                                                       \
        for (int u = 0; u < 16; u++) {                                          \
            const int e = tid + u * 256;                                        \
            const int tile = e >> 10;                                           \
            const int r = (e >> 3) & 127;                                       \
            const int cc = e & 7;                                               \
            const int grow = (tile < 2 ? rowBlk : colBlk) + r;                  \
            const __nv_bfloat16* src_ = (tile & 1) ? g_b1 : g_b0;               \
            cp16(sb_ + (uint32_t)(tile * TILE_B + r * (SPE * 2) + cc * 16),     \
                 src_ + (size_t)grow * d + k0_ + cc * 8);                       \
        }                                                                       \
    } while (0)

    // fragment loads (layout identical to verified R8 code)
#define LOADB(BF, BASE, KS)                                                     \
    do {                                                                        \
        const uint32_t koff_ = (uint32_t)((KS) * 16 + lh8) * 2;                 \
        const uint32_t bb_ = (BASE) + 2u * TILE_B +                             \
                             (uint32_t)(wn * 32 + lr15) * (SPE * 2) + koff_;    \
        LDMX4((BF) + 0, bb_);                                                   \
        LDMX4((BF) + 4, bb_ + 16u * (SPE * 2));                                 \
        const uint32_t cb_ = bb_ + (uint32_t)TILE_B;                            \
        LDMX4((BF) + 8, cb_);                                                   \
        LDMX4((BF) + 12, cb_ + 16u * (SPE * 2));                                \
    } while (0)

#define LOADA(AF, BASE, KS, MI)                                                 \
    do {                                                                        \
        const uint32_t koff_ = (uint32_t)((KS) * 16 + lh8) * 2;                 \
        const uint32_t ab_ = (BASE) +                                           \
            (uint32_t)(wm * 64 + (MI) * 16 + lr15) * (SPE * 2) + koff_;         \
        LDMX4((AF) + 0, ab_);                                                   \
        LDMX4((AF) + 4, ab_ + (uint32_t)TILE_B);                                \
    } while (0)

    PREFETCH(0, 0);
    cp_commit();

    uint32_t Bf[2][16], Af[2][8];

    for (int c = 0; c < nChunks; c++) {
        if (c + 1 < nChunks) {
            PREFETCH(c + 1, (c + 1) & 1);
            cp_commit();
            cp_wait1();
        } else {
            cp_wait0();
        }
        __syncthreads();
        const uint32_t stageBase = sbase + (uint32_t)(c & 1) * STAGE_B;

        // fragment pipeline prologue
        LOADB(Bf[0], stageBase, 0);
        LOADA(Af[0], stageBase, 0, 0);

        int ab = 0, bb = 0;
#pragma unroll
        for (int ks = 0; ks < 4; ks++) {
#pragma unroll
            for (int mi = 0; mi < 4; mi++) {
                // prefetch next fragments while this set's MMAs issue
                if (mi < 3) {
                    LOADA(Af[ab ^ 1], stageBase, ks, mi + 1);
                } else if (ks < 3) {
                    LOADB(Bf[bb ^ 1], stageBase, ks + 1);
                    LOADA(Af[ab ^ 1], stageBase, ks + 1, 0);
                }
                const uint32_t* A0 = Af[ab];
                const uint32_t* A1 = Af[ab] + 4;
                const uint32_t* B  = Bf[bb];
#pragma unroll
                for (int nj = 0; nj < 4; nj++) {
                    const int h = (nj >> 1) * 4 + (nj & 1);
                    float* D = acc[mi][nj];
                    MMA16816(D, A0, B[h], B[h + 2]);
                    MMA16816(D, A0, B[8 + h], B[8 + h + 2]);
                    MMA16816(D, A1, B[h], B[h + 2]);
                }
                ab ^= 1;
            }
            bb ^= 1;
        }
        __syncthreads();
    }
#undef PREFETCH
#undef LOADA
#undef LOADB

    // ---- fused epilogue (verified; only partials layout changed) ----
    const float ALPHA = 40.f, MARGIN = 0.5f;
    const int r0 = l >> 2, c0 = (l & 3) * 2;
    float rowP[8], rowN[8], colP[8], colN[8];
#pragma unroll
    for (int g = 0; g < 8; g++) { rowP[g] = rowN[g] = colP[g] = colN[g] = 0.f; }
    float sp = 0.f, sn = 0.f, spc = 0.f, snc = 0.f;

#pragma unroll
    for (int mi = 0; mi < 4; mi++) {
#pragma unroll
        for (int rh = 0; rh < 2; rh++) {
            const int rloc = wm * 64 + mi * 16 + r0 + rh * 8;
            const int gr = rowBlk + rloc;
            const int tr = tR[rloc];
            const bool isLastRow = (gr == n - 1);
            const int g = mi * 2 + rh;
#pragma unroll
            for (int nj = 0; nj < 4; nj++) {
#pragma unroll
                for (int p = 0; p < 2; p++) {
                    const int cloc = wn * 32 + nj * 8 + c0 + p;
                    const int gc = colBlk + cloc;
                    const int h = nj * 2 + p;
                    const float sv = acc[mi][nj][rh * 2 + p];
                    if (gc == gr) {
                        if (g_diag_in[gr]) {
                            const float dv = g_diag_val[gr];
                            rowP[g] += softplus_fast(-2.f * (dv - MARGIN));
                            if (isLastRow) sp += dv;
                        }
                    } else {
                        const bool same = (tr == tC[cloc]);
                        const float z = same ? (-2.f * (sv - MARGIN))
                                             : (ALPHA * (sv - MARGIN));
                        const float lv = softplus_fast(z);
                        if (same) {
                            rowP[g] += lv; colP[h] += lv;
                            if (isLastRow) sp += sv;
                            if (offd && gc == n - 1) spc += sv;
                        } else {
                            rowN[g] += lv; colN[h] += lv;
                            if (isLastRow) sn += sv;
                            if (offd && gc == n - 1) snc += sv;
                        }
                    }
                }
            }
        }
    }

#pragma unroll
    for (int g = 0; g < 8; g++) {
        rowP[g] += __shfl_xor_sync(0xffffffffu, rowP[g], 1);
        rowP[g] += __shfl_xor_sync(0xffffffffu, rowP[g], 2);
        rowN[g] += __shfl_xor_sync(0xffffffffu, rowN[g], 1);
        rowN[g] += __shfl_xor_sync(0xffffffffu, rowN[g], 2);
    }
    if ((l & 3) == 0) {
#pragma unroll
        for (int g = 0; g < 8; g++) {
            const int rloc = wm * 64 + (g >> 1) * 16 + r0 + (g & 1) * 8;
            sRP[wn][rloc] = rowP[g];
            sRN[wn][rloc] = rowN[g];
        }
    }
#pragma unroll
    for (int h = 0; h < 8; h++) {
        colP[h] += __shfl_xor_sync(0xffffffffu, colP[h], 4);
        colP[h] += __shfl_xor_sync(0xffffffffu, colP[h], 8);
        colP[h] += __shfl_xor_sync(0xffffffffu, colP[h], 16);
        colN[h] += __shfl_xor_sync(0xffffffffu, colN[h], 4);
        colN[h] += __shfl_xor_sync(0xffffffffu, colN[h], 8);
        colN[h] += __shfl_xor_sync(0xffffffffu, colN[h], 16);
    }
    if (l < 4) {
#pragma unroll
        for (int h = 0; h < 8; h++) {
            const int cloc = wn * 32 + (h >> 1) * 8 + l * 2 + (h & 1);
            sCP[wm][cloc] = colP[h];
            sCN[wm][cloc] = colN[h];
        }
    }
#pragma unroll
    for (int o = 16; o > 0; o >>= 1) {
        sp  += __shfl_xor_sync(0xffffffffu, sp,  o);
        sn  += __shfl_xor_sync(0xffffffffu, sn,  o);
        spc += __shfl_xor_sync(0xffffffffu, spc, o);
        snc += __shfl_xor_sync(0xffffffffu, snc, o);
    }
    if (l == 0) { sSpec[w][0] = sp; sSpec[w][1] = sn; sSpec[w][2] = spc; sSpec[w][3] = snc; }
    __syncthreads();

    if (tid < BT) {
        g_pos_part[(rowBlk + tid) * TILES_MAX + bj] =
            sRP[0][tid] + sRP[1][tid] + sRP[2][tid] + sRP[3][tid];
        g_neg_part[(rowBlk + tid) * TILES_MAX + bj] =
            sRN[0][tid] + sRN[1][tid] + sRN[2][tid] + sRN[3][tid];
    } else if (offd) {
        const int cc = tid - BT;
        g_pos_part[(colBlk + cc) * TILES_MAX + bi] = sCP[0][cc] + sCP[1][cc];
        g_neg_part[(colBlk + cc) * TILES_MAX + bi] = sCN[0][cc] + sCN[1][cc];
    }
    if (tid == 0 && bj == nT - 1) {
        float a0 = 0.f, a1 = 0.f, a2 = 0.f, a3 = 0.f;
#pragma unroll
        for (int ww = 0; ww < 8; ww++) {
            a0 += sSpec[ww][0]; a1 += sSpec[ww][1];
            a2 += sSpec[ww][2]; a3 += sSpec[ww][3];
        }
        if (offd) { g_last_part[bi][0] = a2; g_last_part[bi][1] = a3; }
        else      { g_last_part[bj][0] = a0; g_last_part[bj][1] = a1; }
    }
}

// ---------------------------------------------------------------------------
__global__ void finalize1_kernel(int n, int nTiles) {
    __shared__ float sLoss[128];
    __shared__ float sInv[128];
    const int t = threadIdx.x;
    const int i = blockIdx.x * 128 + t;
    float loss = 0.f, inv = 0.f;
    if (i < n) {
        float ps = 0.f, ns = 0.f;
        for (int b = 0; b < nTiles; b++) {
            ps += g_pos_part[i * TILES_MAX + b];   // one 128B line per row
            ns += g_neg_part[i * TILES_MAX + b];
        }
        const int c = g_hist[g_tgt[i]];
        const float pc = (float)(c - 1 + g_diag_in[i]);
        const float nc = (float)(n - c);
        const float pl = ps / fmaxf(pc, 1.f);
        const float nl = ns / fmaxf(nc, 1.f);
        if (nc > 0.f) loss = pl + nl; else inv = 1.f;
    }
    sLoss[t] = loss; sInv[t] = inv;
    __syncthreads();
    for (int s = 64; s > 0; s >>= 1) {
        if (t < s) { sLoss[t] += sLoss[t + s]; sInv[t] += sInv[t + s]; }
        __syncthreads();
    }
    if (t == 0) { g_loss_part[blockIdx.x] = sLoss[0]; g_inv_part[blockIdx.x] = sInv[0]; }
}

__global__ void finalize2_kernel(float* __restrict__ out, int n, int nTiles, int nB) {
    const int t = threadIdx.x;
    float loss = (t < nB) ? g_loss_part[t] : 0.f;
    float inv  = (t < nB) ? g_inv_part[t]  : 0.f;
    float sp   = (t < nTiles) ? g_last_part[t][0] : 0.f;
    float sn   = (t < nTiles) ? g_last_part[t][1] : 0.f;
#pragma unroll
    for (int off = 16; off > 0; off >>= 1) {
        loss += __shfl_down_sync(0xffffffffu, loss, off);
        inv  += __shfl_down_sync(0xffffffffu, inv,  off);
        sp   += __shfl_down_sync(0xffffffffu, sp,   off);
        sn   += __shfl_down_sync(0xffffffffu, sn,   off);
    }
    if (t == 0) {
        const int c = g_hist[g_tgt[n - 1]];
        const float pc = (float)(c - 1 + g_diag_in[n - 1]);
        out[0] = loss / (float)n;
        out[1] = inv / (float)n;
        out[2] = sp / fmaxf(pc, 1.f);
        out[3] = sn / fmaxf((float)(n - c), 1.f);
    }
    // re-zero histogram for the next graph replay (after all reads above)
    __syncwarp();
    for (int i = t; i < CLSMAX; i += 32) g_hist[i] = 0;
}

// ---------------------------------------------------------------------------
extern "C" void kernel_launch(void* const* d_in, const int* in_sizes, int n_in,
                              void* d_out, int out_size) {
    int ix = 0, it = 1;
    if (n_in >= 2 && in_sizes[0] < in_sizes[1]) { ix = 1; it = 0; }
    const float* X = (const float*)d_in[ix];
    const void*  T = d_in[it];
    const int n = in_sizes[it];
    const int d = in_sizes[ix] / n;
    const int nT = n / BT;
    const int nBlocks = nT * (nT + 1) / 2;
    const int nFin = (n + 127) / 128;
    const int dynBytes = 2 * STAGE_B;     // 147456

    static int attr_set = 0;
    if (!attr_set) {
        cudaFuncSetAttribute(binloss_mma, cudaFuncAttributeMaxDynamicSharedMemorySize, dynBytes);
        attr_set = 1;
    }

    diag_split_kernel<<<n / 128, 256>>>(X, T, n, d);
    binloss_mma<<<nBlocks, 256, dynBytes>>>(n, d);
    finalize1_kernel<<<nFin, 128>>>(n, nT);
    finalize2_kernel<<<1, 32>>>((float*)d_out, n, nT, nFin);
}

// round 10
// speedup vs baseline: 3.6041x; 1.0839x over previous
#include <cuda_runtime.h>
#include <cuda_bf16.h>
#include <stdint.h>

// ---------------------------------------------------------------------------
// BinomialLoss, round 10:
//  - main kernel at occupancy 2 (KC=32, 2-stage, launch_bounds(256,2))
//  - diag_split with double-buffered staging (chain overlaps next loads)
//  - finalize2 folded into finalize1's last block (atomic ticket)
// HMMA bf16x2-split GEMM, triangle tiles, dual epilogue.
// Diagonal <1.0 decision: exact sequential ascending-k fp32 FMA chain.
// ---------------------------------------------------------------------------

#define NMAX   4096
#define DMAX   512
#define CLSMAX 512
#define TILES_MAX 32
#define BT   128
#define KC   32
#define SPE  40                         // smem row stride in bf16 (80 B)
#define TILE_B  (BT * SPE * 2)          // 10240 B per tile
#define STAGE_B (4 * TILE_B)            // 40960 B per stage (A0,A1,B0,B1)

// -------- scratch ----------------------------------------------------------
__device__ int   g_tgt[NMAX];
__device__ int   g_hist[CLSMAX];        // zero-init; re-zeroed each replay
__device__ int   g_fin_cnt;             // finalize ticket; re-zeroed each replay
__device__ float g_diag_val[NMAX];
__device__ int   g_diag_in[NMAX];
__device__ float g_pos_part[NMAX * TILES_MAX];   // [row*32 + tile]
__device__ float g_neg_part[NMAX * TILES_MAX];
__device__ float g_last_part[TILES_MAX][2];
__device__ float g_loss_part[64];
__device__ float g_inv_part[64];
__device__ __nv_bfloat16 g_b0[NMAX * DMAX];
__device__ __nv_bfloat16 g_b1[NMAX * DMAX];

__device__ __forceinline__ uint32_t smem_u32(const void* p) {
    uint32_t a;
    asm("{ .reg .u64 t; cvta.to.shared.u64 t, %1; cvt.u32.u64 %0, t; }" : "=r"(a) : "l"(p));
    return a;
}
__device__ __forceinline__ float softplus_fast(float z) {
    return fmaxf(z, 0.f) + __logf(1.f + __expf(-fabsf(z)));
}
__device__ __forceinline__ void cp16(uint32_t s, const void* g) {
    asm volatile("cp.async.cg.shared.global [%0], [%1], 16;" :: "r"(s), "l"(g));
}
__device__ __forceinline__ void cp_commit() {
    asm volatile("cp.async.commit_group;" ::: "memory");
}
__device__ __forceinline__ void cp_wait1() {
    asm volatile("cp.async.wait_group 1;" ::: "memory");
}
__device__ __forceinline__ void cp_wait0() {
    asm volatile("cp.async.wait_group 0;" ::: "memory");
}

#define LDMX4(R, ADDR)                                                          \
    asm volatile("ldmatrix.sync.aligned.m8n8.x4.shared.b16 {%0,%1,%2,%3}, [%4];"\
        : "=r"((R)[0]), "=r"((R)[1]), "=r"((R)[2]), "=r"((R)[3]) : "r"(ADDR))

#define MMA16816(D, A, B0r, B1r)                                                \
    asm volatile(                                                               \
        "mma.sync.aligned.m16n8k16.row.col.f32.bf16.bf16.f32 "                  \
        "{%0,%1,%2,%3}, {%4,%5,%6,%7}, {%8,%9}, {%0,%1,%2,%3};"                 \
        : "+f"((D)[0]), "+f"((D)[1]), "+f"((D)[2]), "+f"((D)[3])                \
        : "r"((A)[0]), "r"((A)[1]), "r"((A)[2]), "r"((A)[3]),                   \
          "r"(B0r), "r"(B1r))

// ---------------------------------------------------------------------------
// fused targets + split + diag, double-buffered 32-col staging.
// grid = n/128 blocks x 256 threads.
// ---------------------------------------------------------------------------
__global__ void diag_split_kernel(const float* __restrict__ X,
                                  const void* __restrict__ tgt_raw, int n, int d) {
    __shared__ float sx[2][128][33];
    __shared__ int sIs64;
    const int t = threadIdx.x;
    const int rowBlk = blockIdx.x * 128;

    if (t == 0) sIs64 = 1;
    __syncthreads();
    const long long* p64 = (const long long*)tgt_raw;
    const int*       p32 = (const int*)tgt_raw;
    if (t < 64) {
        long long v = p64[t];
        if (v < 0 || v >= (long long)CLSMAX) atomicAnd(&sIs64, 0);
    }
    __syncthreads();
    if (t < 128) {
        int v = sIs64 ? (int)p64[rowBlk + t] : p32[rowBlk + t];
        if (v < 0) v = 0;
        if (v >= CLSMAX) v = CLSMAX - 1;
        g_tgt[rowBlk + t] = v;
        atomicAdd(&g_hist[v], 1);        // int adds: order-independent
    }

#define STAGE(K0, BUF)                                                          \
    do {                                                                        \
        _Pragma("unroll")                                                       \
        for (int u = 0; u < 8; u++) {                                           \
            const int e2 = (t + u * 256) * 2;      /* 0..8190 even */           \
            const int r = e2 >> 5, cc = e2 & 31;                                \
            const size_t gi = (size_t)(rowBlk + r) * d + (K0) + cc;             \
            const float2 v = *(const float2*)(X + gi);                          \
            const __nv_bfloat162 b = __float22bfloat162_rn(v);                  \
            *(__nv_bfloat162*)(g_b0 + gi) = b;                                  \
            float2 rr;                                                          \
            rr.x = v.x - __bfloat162float(b.x);                                 \
            rr.y = v.y - __bfloat162float(b.y);                                 \
            *(__nv_bfloat162*)(g_b1 + gi) = __float22bfloat162_rn(rr);          \
            sx[BUF][r][cc] = v.x;                                               \
            sx[BUF][r][cc + 1] = v.y;                                           \
        }                                                                       \
    } while (0)

    float acc = 0.f;
    const int nCh = d / 32;              // 16
    STAGE(0, 0);
    __syncthreads();
    for (int ch = 0; ch < nCh; ch++) {
        if (ch + 1 < nCh) STAGE((ch + 1) * 32, (ch + 1) & 1);  // overlaps chain
        if (t < 128) {
#pragma unroll 8
            for (int cc = 0; cc < 32; cc++)
                acc = fmaf(sx[ch & 1][t][cc], sx[ch & 1][t][cc], acc); // seq order
        }
        __syncthreads();
    }
#undef STAGE
    if (t < 128) {
        g_diag_val[rowBlk + t] = acc;
        g_diag_in[rowBlk + t]  = (acc < 1.0f) ? 1 : 0;
    }
}

// ---------------------------------------------------------------------------
// main: triangle tiles, HMMA bf16x2-split, KC=32 2-stage, occupancy 2.
// ---------------------------------------------------------------------------
__global__ __launch_bounds__(256, 2)
void binloss_mma(int n, int d) {
    extern __shared__ __align__(16) char dyn_smem[];
    __shared__ float sRP[4][BT], sRN[4][BT];
    __shared__ float sCP[2][BT], sCN[2][BT];
    __shared__ int tR[BT], tC[BT];
    __shared__ float sSpec[8][4];

    const int nT = n / BT;
    int idx = blockIdx.x, bi = 0;
    while (idx >= nT - bi) { idx -= nT - bi; bi++; }
    const int bj = bi + idx;
    const bool offd = (bi != bj);
    const int rowBlk = bi * BT, colBlk = bj * BT;

    const int tid = threadIdx.x;
    const int w = tid >> 5, l = tid & 31;
    const int wm = w & 1, wn = w >> 1;
    const int lr15 = l & 15, lh8 = (l >> 4) * 8;

    if (tid < BT) { tR[tid] = g_tgt[rowBlk + tid]; tC[tid] = g_tgt[colBlk + tid]; }

    float acc[4][4][4];
#pragma unroll
    for (int a = 0; a < 4; a++)
#pragma unroll
        for (int b = 0; b < 4; b++)
#pragma unroll
            for (int r = 0; r < 4; r++) acc[a][b][r] = 0.f;

    const uint32_t sbase = smem_u32(dyn_smem);
    const int nChunks = d / KC;                      // 16

#define PREFETCH(CHUNK, STG)                                                    \
    do {                                                                        \
        const int k0_ = (CHUNK) * KC;                                           \
        const uint32_t sb_ = sbase + (uint32_t)(STG) * STAGE_B;                 \
        _Pragma("unroll")                                                       \
        for (int u = 0; u < 8; u++) {                                           \
            const int e = tid + u * 256;                                        \
            const int tile = e >> 9;                                            \
            const int r = (e >> 2) & 127;                                       \
            const int cc = e & 3;                                               \
            const int grow = (tile < 2 ? rowBlk : colBlk) + r;                  \
            const __nv_bfloat16* src_ = (tile & 1) ? g_b1 : g_b0;               \
            cp16(sb_ + (uint32_t)(tile * TILE_B + r * (SPE * 2) + cc * 16),     \
                 src_ + (size_t)grow * d + k0_ + cc * 8);                       \
        }                                                                       \
    } while (0)

    PREFETCH(0, 0);
    cp_commit();

    for (int c = 0; c < nChunks; c++) {
        if (c + 1 < nChunks) {
            PREFETCH(c + 1, (c + 1) & 1);
            cp_commit();
            cp_wait1();
        } else {
            cp_wait0();
        }
        __syncthreads();
        const uint32_t stageBase = sbase + (uint32_t)(c & 1) * STAGE_B;

#pragma unroll
        for (int ks = 0; ks < KC; ks += 16) {
            const uint32_t koff = (uint32_t)(ks + lh8) * 2;
            uint32_t b0f[8], b1f[8];
            {
                const uint32_t bb = stageBase + 2u * TILE_B +
                                    (uint32_t)(wn * 32 + lr15) * (SPE * 2) + koff;
                LDMX4(b0f + 0, bb);
                LDMX4(b0f + 4, bb + 16u * (SPE * 2));
                const uint32_t cb = bb + (uint32_t)TILE_B;
                LDMX4(b1f + 0, cb);
                LDMX4(b1f + 4, cb + 16u * (SPE * 2));
            }
#pragma unroll
            for (int mi = 0; mi < 4; mi++) {
                uint32_t a0f[4], a1f[4];
                const uint32_t ab = stageBase +
                    (uint32_t)(wm * 64 + mi * 16 + lr15) * (SPE * 2) + koff;
                LDMX4(a0f, ab);
                LDMX4(a1f, ab + (uint32_t)TILE_B);
#pragma unroll
                for (int nj = 0; nj < 4; nj++) {
                    const int h = (nj >> 1) * 4 + (nj & 1);
                    float* D = acc[mi][nj];
                    MMA16816(D, a0f, b0f[h], b0f[h + 2]);
                    MMA16816(D, a0f, b1f[h], b1f[h + 2]);
                    MMA16816(D, a1f, b0f[h], b0f[h + 2]);
                }
            }
        }
        __syncthreads();
    }
#undef PREFETCH

    // ---- fused epilogue (verified) ----
    const float ALPHA = 40.f, MARGIN = 0.5f;
    const int r0 = l >> 2, c0 = (l & 3) * 2;
    float rowP[8], rowN[8], colP[8], colN[8];
#pragma unroll
    for (int g = 0; g < 8; g++) { rowP[g] = rowN[g] = colP[g] = colN[g] = 0.f; }
    float sp = 0.f, sn = 0.f, spc = 0.f, snc = 0.f;

#pragma unroll
    for (int mi = 0; mi < 4; mi++) {
#pragma unroll
        for (int rh = 0; rh < 2; rh++) {
            const int rloc = wm * 64 + mi * 16 + r0 + rh * 8;
            const int gr = rowBlk + rloc;
            const int tr = tR[rloc];
            const bool isLastRow = (gr == n - 1);
            const int g = mi * 2 + rh;
#pragma unroll
            for (int nj = 0; nj < 4; nj++) {
#pragma unroll
                for (int p = 0; p < 2; p++) {
                    const int cloc = wn * 32 + nj * 8 + c0 + p;
                    const int gc = colBlk + cloc;
                    const int h = nj * 2 + p;
                    const float sv = acc[mi][nj][rh * 2 + p];
                    if (gc == gr) {
                        if (g_diag_in[gr]) {
                            const float dv = g_diag_val[gr];
                            rowP[g] += softplus_fast(-2.f * (dv - MARGIN));
                            if (isLastRow) sp += dv;
                        }
                    } else {
                        const bool same = (tr == tC[cloc]);
                        const float z = same ? (-2.f * (sv - MARGIN))
                                             : (ALPHA * (sv - MARGIN));
                        const float lv = softplus_fast(z);
                        if (same) {
                            rowP[g] += lv; colP[h] += lv;
                            if (isLastRow) sp += sv;
                            if (offd && gc == n - 1) spc += sv;
                        } else {
                            rowN[g] += lv; colN[h] += lv;
                            if (isLastRow) sn += sv;
                            if (offd && gc == n - 1) snc += sv;
                        }
                    }
                }
            }
        }
    }

#pragma unroll
    for (int g = 0; g < 8; g++) {
        rowP[g] += __shfl_xor_sync(0xffffffffu, rowP[g], 1);
        rowP[g] += __shfl_xor_sync(0xffffffffu, rowP[g], 2);
        rowN[g] += __shfl_xor_sync(0xffffffffu, rowN[g], 1);
        rowN[g] += __shfl_xor_sync(0xffffffffu, rowN[g], 2);
    }
    if ((l & 3) == 0) {
#pragma unroll
        for (int g = 0; g < 8; g++) {
            const int rloc = wm * 64 + (g >> 1) * 16 + r0 + (g & 1) * 8;
            sRP[wn][rloc] = rowP[g];
            sRN[wn][rloc] = rowN[g];
        }
    }
#pragma unroll
    for (int h = 0; h < 8; h++) {
        colP[h] += __shfl_xor_sync(0xffffffffu, colP[h], 4);
        colP[h] += __shfl_xor_sync(0xffffffffu, colP[h], 8);
        colP[h] += __shfl_xor_sync(0xffffffffu, colP[h], 16);
        colN[h] += __shfl_xor_sync(0xffffffffu, colN[h], 4);
        colN[h] += __shfl_xor_sync(0xffffffffu, colN[h], 8);
        colN[h] += __shfl_xor_sync(0xffffffffu, colN[h], 16);
    }
    if (l < 4) {
#pragma unroll
        for (int h = 0; h < 8; h++) {
            const int cloc = wn * 32 + (h >> 1) * 8 + l * 2 + (h & 1);
            sCP[wm][cloc] = colP[h];
            sCN[wm][cloc] = colN[h];
        }
    }
#pragma unroll
    for (int o = 16; o > 0; o >>= 1) {
        sp  += __shfl_xor_sync(0xffffffffu, sp,  o);
        sn  += __shfl_xor_sync(0xffffffffu, sn,  o);
        spc += __shfl_xor_sync(0xffffffffu, spc, o);
        snc += __shfl_xor_sync(0xffffffffu, snc, o);
    }
    if (l == 0) { sSpec[w][0] = sp; sSpec[w][1] = sn; sSpec[w][2] = spc; sSpec[w][3] = snc; }
    __syncthreads();

    if (tid < BT) {
        g_pos_part[(rowBlk + tid) * TILES_MAX + bj] =
            sRP[0][tid] + sRP[1][tid] + sRP[2][tid] + sRP[3][tid];
        g_neg_part[(rowBlk + tid) * TILES_MAX + bj] =
            sRN[0][tid] + sRN[1][tid] + sRN[2][tid] + sRN[3][tid];
    } else if (offd) {
        const int cc = tid - BT;
        g_pos_part[(colBlk + cc) * TILES_MAX + bi] = sCP[0][cc] + sCP[1][cc];
        g_neg_part[(colBlk + cc) * TILES_MAX + bi] = sCN[0][cc] + sCN[1][cc];
    }
    if (tid == 0 && bj == nT - 1) {
        float a0 = 0.f, a1 = 0.f, a2 = 0.f, a3 = 0.f;
#pragma unroll
        for (int ww = 0; ww < 8; ww++) {
            a0 += sSpec[ww][0]; a1 += sSpec[ww][1];
            a2 += sSpec[ww][2]; a3 += sSpec[ww][3];
        }
        if (offd) { g_last_part[bi][0] = a2; g_last_part[bi][1] = a3; }
        else      { g_last_part[bj][0] = a0; g_last_part[bj][1] = a1; }
    }
}

// ---------------------------------------------------------------------------
// finalize: 32 blocks; last-arriving block produces the 4 outputs.
// ---------------------------------------------------------------------------
__global__ void finalize_kernel(float* __restrict__ out, int n, int nTiles) {
    __shared__ float sLoss[128];
    __shared__ float sInv[128];
    __shared__ int sLast;
    const int t = threadIdx.x;
    const int i = blockIdx.x * 128 + t;
    float loss = 0.f, inv = 0.f;
    if (i < n) {
        float ps = 0.f, ns = 0.f;
        for (int b = 0; b < nTiles; b++) {
            ps += g_pos_part[i * TILES_MAX + b];
            ns += g_neg_part[i * TILES_MAX + b];
        }
        const int c = g_hist[g_tgt[i]];
        const float pc = (float)(c - 1 + g_diag_in[i]);
        const float nc = (float)(n - c);
        const float pl = ps / fmaxf(pc, 1.f);
        const float nl = ns / fmaxf(nc, 1.f);
        if (nc > 0.f) loss = pl + nl; else inv = 1.f;
    }
    sLoss[t] = loss; sInv[t] = inv;
    __syncthreads();
    for (int s = 64; s > 0; s >>= 1) {
        if (t < s) { sLoss[t] += sLoss[t + s]; sInv[t] += sInv[t + s]; }
        __syncthreads();
    }
    if (t == 0) {
        g_loss_part[blockIdx.x] = sLoss[0];
        g_inv_part[blockIdx.x]  = sInv[0];
        __threadfence();
        sLast = (atomicAdd(&g_fin_cnt, 1) == (int)gridDim.x - 1) ? 1 : 0;
    }
    __syncthreads();
    if (sLast && t < 32) {
        const int nB = (int)gridDim.x;
        float ls = (t < nB) ? g_loss_part[t] : 0.f;
        float iv = (t < nB) ? g_inv_part[t]  : 0.f;
        float sp = (t < nTiles) ? g_last_part[t][0] : 0.f;
        float sn = (t < nTiles) ? g_last_part[t][1] : 0.f;
#pragma unroll
        for (int off = 16; off > 0; off >>= 1) {
            ls += __shfl_down_sync(0xffffffffu, ls, off);
            iv += __shfl_down_sync(0xffffffffu, iv, off);
            sp += __shfl_down_sync(0xffffffffu, sp, off);
            sn += __shfl_down_sync(0xffffffffu, sn, off);
        }
        if (t == 0) {
            const int c = g_hist[g_tgt[n - 1]];
            const float pc = (float)(c - 1 + g_diag_in[n - 1]);
            out[0] = ls / (float)n;
            out[1] = iv / (float)n;
            out[2] = sp / fmaxf(pc, 1.f);
            out[3] = sn / fmaxf((float)(n - c), 1.f);
        }
        __syncwarp();
        for (int ii = t; ii < CLSMAX; ii += 32) g_hist[ii] = 0;  // replay reset
        if (t == 0) g_fin_cnt = 0;
    }
}

// ---------------------------------------------------------------------------
extern "C" void kernel_launch(void* const* d_in, const int* in_sizes, int n_in,
                              void* d_out, int out_size) {
    int ix = 0, it = 1;
    if (n_in >= 2 && in_sizes[0] < in_sizes[1]) { ix = 1; it = 0; }
    const float* X = (const float*)d_in[ix];
    const void*  T = d_in[it];
    const int n = in_sizes[it];
    const int d = in_sizes[ix] / n;
    const int nT = n / BT;
    const int nBlocks = nT * (nT + 1) / 2;
    const int nFin = (n + 127) / 128;
    const int dynBytes = 2 * STAGE_B;     // 81920

    static int attr_set = 0;
    if (!attr_set) {
        cudaFuncSetAttribute(binloss_mma, cudaFuncAttributeMaxDynamicSharedMemorySize, dynBytes);
        attr_set = 1;
    }

    diag_split_kernel<<<n / 128, 256>>>(X, T, n, d);
    binloss_mma<<<nBlocks, 256, dynBytes>>>(n, d);
    finalize_kernel<<<nFin, 128>>>((float*)d_out, n, nT);
}

// round 11
// speedup vs baseline: 4.0486x; 1.1233x over previous
#include <cuda_runtime.h>
#include <cuda_bf16.h>
#include <stdint.h>

// ---------------------------------------------------------------------------
// BinomialLoss, round 11: diag_split parallelized to 128 blocks (32 rows each,
// warp-0 chains, double-buffered staging). Main kernel + finalize = R10.
// HMMA bf16x2-split GEMM, KC=32 2-stage, occupancy 2, triangle tiles.
// Diagonal <1.0 decision: exact sequential ascending-k fp32 FMA chain.
// ---------------------------------------------------------------------------

#define NMAX   4096
#define DMAX   512
#define CLSMAX 512
#define TILES_MAX 32
#define BT   128
#define KC   32
#define SPE  40                         // smem row stride in bf16 (80 B)
#define TILE_B  (BT * SPE * 2)          // 10240 B per tile
#define STAGE_B (4 * TILE_B)            // 40960 B per stage (A0,A1,B0,B1)

// -------- scratch ----------------------------------------------------------
__device__ int   g_tgt[NMAX];
__device__ int   g_hist[CLSMAX];        // zero-init; re-zeroed each replay
__device__ int   g_fin_cnt;             // finalize ticket; re-zeroed each replay
__device__ float g_diag_val[NMAX];
__device__ int   g_diag_in[NMAX];
__device__ float g_pos_part[NMAX * TILES_MAX];   // [row*32 + tile]
__device__ float g_neg_part[NMAX * TILES_MAX];
__device__ float g_last_part[TILES_MAX][2];
__device__ float g_loss_part[64];
__device__ float g_inv_part[64];
__device__ __nv_bfloat16 g_b0[NMAX * DMAX];
__device__ __nv_bfloat16 g_b1[NMAX * DMAX];

__device__ __forceinline__ uint32_t smem_u32(const void* p) {
    uint32_t a;
    asm("{ .reg .u64 t; cvta.to.shared.u64 t, %1; cvt.u32.u64 %0, t; }" : "=r"(a) : "l"(p));
    return a;
}
__device__ __forceinline__ float softplus_fast(float z) {
    return fmaxf(z, 0.f) + __logf(1.f + __expf(-fabsf(z)));
}
__device__ __forceinline__ void cp16(uint32_t s, const void* g) {
    asm volatile("cp.async.cg.shared.global [%0], [%1], 16;" :: "r"(s), "l"(g));
}
__device__ __forceinline__ void cp_commit() {
    asm volatile("cp.async.commit_group;" ::: "memory");
}
__device__ __forceinline__ void cp_wait1() {
    asm volatile("cp.async.wait_group 1;" ::: "memory");
}
__device__ __forceinline__ void cp_wait0() {
    asm volatile("cp.async.wait_group 0;" ::: "memory");
}

#define LDMX4(R, ADDR)                                                          \
    asm volatile("ldmatrix.sync.aligned.m8n8.x4.shared.b16 {%0,%1,%2,%3}, [%4];"\
        : "=r"((R)[0]), "=r"((R)[1]), "=r"((R)[2]), "=r"((R)[3]) : "r"(ADDR))

#define MMA16816(D, A, B0r, B1r)                                                \
    asm volatile(                                                               \
        "mma.sync.aligned.m16n8k16.row.col.f32.bf16.bf16.f32 "                  \
        "{%0,%1,%2,%3}, {%4,%5,%6,%7}, {%8,%9}, {%0,%1,%2,%3};"                 \
        : "+f"((D)[0]), "+f"((D)[1]), "+f"((D)[2]), "+f"((D)[3])                \
        : "r"((A)[0]), "r"((A)[1]), "r"((A)[2]), "r"((A)[3]),                   \
          "r"(B0r), "r"(B1r))

// ---------------------------------------------------------------------------
// fused targets + split + diag. grid = n/32 blocks x 256 threads.
// Each block: 32 rows. Staging double-buffered (32x128 floats per chunk);
// warp 0 runs the 32 sequential chains (lane t <-> row t).
// ---------------------------------------------------------------------------
__global__ void diag_split_kernel(const float* __restrict__ X,
                                  const void* __restrict__ tgt_raw, int n, int d) {
    __shared__ float sx[2][32][129];
    __shared__ int sIs64;
    const int t = threadIdx.x;
    const int rowBlk = blockIdx.x * 32;

    if (t == 0) sIs64 = 1;
    __syncthreads();
    const long long* p64 = (const long long*)tgt_raw;
    const int*       p32 = (const int*)tgt_raw;
    if (t < 64) {
        long long v = p64[t];
        if (v < 0 || v >= (long long)CLSMAX) atomicAnd(&sIs64, 0);
    }
    __syncthreads();
    if (t < 32) {
        int v = sIs64 ? (int)p64[rowBlk + t] : p32[rowBlk + t];
        if (v < 0) v = 0;
        if (v >= CLSMAX) v = CLSMAX - 1;
        g_tgt[rowBlk + t] = v;
        atomicAdd(&g_hist[v], 1);        // int adds: order-independent
    }

    // one chunk = 32 rows x 128 cols = 4096 floats = 2048 float2 / 256 thr = 8
#define STAGE(K0, BUF)                                                          \
    do {                                                                        \
        _Pragma("unroll")                                                       \
        for (int u = 0; u < 8; u++) {                                           \
            const int e2 = (t + u * 256) * 2;       /* 0..4094 even */          \
            const int r = e2 >> 7, cc = e2 & 127;                               \
            const size_t gi = (size_t)(rowBlk + r) * d + (K0) + cc;             \
            const float2 v = *(const float2*)(X + gi);                          \
            const __nv_bfloat162 b = __float22bfloat162_rn(v);                  \
            *(__nv_bfloat162*)(g_b0 + gi) = b;                                  \
            float2 rr;                                                          \
            rr.x = v.x - __bfloat162float(b.x);                                 \
            rr.y = v.y - __bfloat162float(b.y);                                 \
            *(__nv_bfloat162*)(g_b1 + gi) = __float22bfloat162_rn(rr);          \
            sx[BUF][r][cc] = v.x;                                               \
            sx[BUF][r][cc + 1] = v.y;                                           \
        }                                                                       \
    } while (0)

    float acc = 0.f;
    const int nCh = d / 128;             // 4
    STAGE(0, 0);
    __syncthreads();
    for (int ch = 0; ch < nCh; ch++) {
        if (ch + 1 < nCh) STAGE((ch + 1) * 128, (ch + 1) & 1);  // overlaps chain
        if (t < 32) {
#pragma unroll 16
            for (int cc = 0; cc < 128; cc++)
                acc = fmaf(sx[ch & 1][t][cc], sx[ch & 1][t][cc], acc); // seq order
        }
        __syncthreads();
    }
#undef STAGE
    if (t < 32) {
        g_diag_val[rowBlk + t] = acc;
        g_diag_in[rowBlk + t]  = (acc < 1.0f) ? 1 : 0;
    }
}

// ---------------------------------------------------------------------------
// main: triangle tiles, HMMA bf16x2-split, KC=32 2-stage, occupancy 2.
// (verified R10 code, unchanged)
// ---------------------------------------------------------------------------
__global__ __launch_bounds__(256, 2)
void binloss_mma(int n, int d) {
    extern __shared__ __align__(16) char dyn_smem[];
    __shared__ float sRP[4][BT], sRN[4][BT];
    __shared__ float sCP[2][BT], sCN[2][BT];
    __shared__ int tR[BT], tC[BT];
    __shared__ float sSpec[8][4];

    const int nT = n / BT;
    int idx = blockIdx.x, bi = 0;
    while (idx >= nT - bi) { idx -= nT - bi; bi++; }
    const int bj = bi + idx;
    const bool offd = (bi != bj);
    const int rowBlk = bi * BT, colBlk = bj * BT;

    const int tid = threadIdx.x;
    const int w = tid >> 5, l = tid & 31;
    const int wm = w & 1, wn = w >> 1;
    const int lr15 = l & 15, lh8 = (l >> 4) * 8;

    if (tid < BT) { tR[tid] = g_tgt[rowBlk + tid]; tC[tid] = g_tgt[colBlk + tid]; }

    float acc[4][4][4];
#pragma unroll
    for (int a = 0; a < 4; a++)
#pragma unroll
        for (int b = 0; b < 4; b++)
#pragma unroll
            for (int r = 0; r < 4; r++) acc[a][b][r] = 0.f;

    const uint32_t sbase = smem_u32(dyn_smem);
    const int nChunks = d / KC;                      // 16

#define PREFETCH(CHUNK, STG)                                                    \
    do {                                                                        \
        const int k0_ = (CHUNK) * KC;                                           \
        const uint32_t sb_ = sbase + (uint32_t)(STG) * STAGE_B;                 \
        _Pragma("unroll")                                                       \
        for (int u = 0; u < 8; u++) {                                           \
            const int e = tid + u * 256;                                        \
            const int tile = e >> 9;                                            \
            const int r = (e >> 2) & 127;                                       \
            const int cc = e & 3;                                               \
            const int grow = (tile < 2 ? rowBlk : colBlk) + r;                  \
            const __nv_bfloat16* src_ = (tile & 1) ? g_b1 : g_b0;               \
            cp16(sb_ + (uint32_t)(tile * TILE_B + r * (SPE * 2) + cc * 16),     \
                 src_ + (size_t)grow * d + k0_ + cc * 8);                       \
        }                                                                       \
    } while (0)

    PREFETCH(0, 0);
    cp_commit();

    for (int c = 0; c < nChunks; c++) {
        if (c + 1 < nChunks) {
            PREFETCH(c + 1, (c + 1) & 1);
            cp_commit();
            cp_wait1();
        } else {
            cp_wait0();
        }
        __syncthreads();
        const uint32_t stageBase = sbase + (uint32_t)(c & 1) * STAGE_B;

#pragma unroll
        for (int ks = 0; ks < KC; ks += 16) {
            const uint32_t koff = (uint32_t)(ks + lh8) * 2;
            uint32_t b0f[8], b1f[8];
            {
                const uint32_t bb = stageBase + 2u * TILE_B +
                                    (uint32_t)(wn * 32 + lr15) * (SPE * 2) + koff;
                LDMX4(b0f + 0, bb);
                LDMX4(b0f + 4, bb + 16u * (SPE * 2));
                const uint32_t cb = bb + (uint32_t)TILE_B;
                LDMX4(b1f + 0, cb);
                LDMX4(b1f + 4, cb + 16u * (SPE * 2));
            }
#pragma unroll
            for (int mi = 0; mi < 4; mi++) {
                uint32_t a0f[4], a1f[4];
                const uint32_t ab = stageBase +
                    (uint32_t)(wm * 64 + mi * 16 + lr15) * (SPE * 2) + koff;
                LDMX4(a0f, ab);
                LDMX4(a1f, ab + (uint32_t)TILE_B);
#pragma unroll
                for (int nj = 0; nj < 4; nj++) {
                    const int h = (nj >> 1) * 4 + (nj & 1);
                    float* D = acc[mi][nj];
                    MMA16816(D, a0f, b0f[h], b0f[h + 2]);
                    MMA16816(D, a0f, b1f[h], b1f[h + 2]);
                    MMA16816(D, a1f, b0f[h], b0f[h + 2]);
                }
            }
        }
        __syncthreads();
    }
#undef PREFETCH

    // ---- fused epilogue (verified) ----
    const float ALPHA = 40.f, MARGIN = 0.5f;
    const int r0 = l >> 2, c0 = (l & 3) * 2;
    float rowP[8], rowN[8], colP[8], colN[8];
#pragma unroll
    for (int g = 0; g < 8; g++) { rowP[g] = rowN[g] = colP[g] = colN[g] = 0.f; }
    float sp = 0.f, sn = 0.f, spc = 0.f, snc = 0.f;

#pragma unroll
    for (int mi = 0; mi < 4; mi++) {
#pragma unroll
        for (int rh = 0; rh < 2; rh++) {
            const int rloc = wm * 64 + mi * 16 + r0 + rh * 8;
            const int gr = rowBlk + rloc;
            const int tr = tR[rloc];
            const bool isLastRow = (gr == n - 1);
            const int g = mi * 2 + rh;
#pragma unroll
            for (int nj = 0; nj < 4; nj++) {
#pragma unroll
                for (int p = 0; p < 2; p++) {
                    const int cloc = wn * 32 + nj * 8 + c0 + p;
                    const int gc = colBlk + cloc;
                    const int h = nj * 2 + p;
                    const float sv = acc[mi][nj][rh * 2 + p];
                    if (gc == gr) {
                        if (g_diag_in[gr]) {
                            const float dv = g_diag_val[gr];
                            rowP[g] += softplus_fast(-2.f * (dv - MARGIN));
                            if (isLastRow) sp += dv;
                        }
                    } else {
                        const bool same = (tr == tC[cloc]);
                        const float z = same ? (-2.f * (sv - MARGIN))
                                             : (ALPHA * (sv - MARGIN));
                        const float lv = softplus_fast(z);
                        if (same) {
                            rowP[g] += lv; colP[h] += lv;
                            if (isLastRow) sp += sv;
                            if (offd && gc == n - 1) spc += sv;
                        } else {
                            rowN[g] += lv; colN[h] += lv;
                            if (isLastRow) sn += sv;
                            if (offd && gc == n - 1) snc += sv;
                        }
                    }
                }
            }
        }
    }

#pragma unroll
    for (int g = 0; g < 8; g++) {
        rowP[g] += __shfl_xor_sync(0xffffffffu, rowP[g], 1);
        rowP[g] += __shfl_xor_sync(0xffffffffu, rowP[g], 2);
        rowN[g] += __shfl_xor_sync(0xffffffffu, rowN[g], 1);
        rowN[g] += __shfl_xor_sync(0xffffffffu, rowN[g], 2);
    }
    if ((l & 3) == 0) {
#pragma unroll
        for (int g = 0; g < 8; g++) {
            const int rloc = wm * 64 + (g >> 1) * 16 + r0 + (g & 1) * 8;
            sRP[wn][rloc] = rowP[g];
            sRN[wn][rloc] = rowN[g];
        }
    }
#pragma unroll
    for (int h = 0; h < 8; h++) {
        colP[h] += __shfl_xor_sync(0xffffffffu, colP[h], 4);
        colP[h] += __shfl_xor_sync(0xffffffffu, colP[h], 8);
        colP[h] += __shfl_xor_sync(0xffffffffu, colP[h], 16);
        colN[h] += __shfl_xor_sync(0xffffffffu, colN[h], 4);
        colN[h] += __shfl_xor_sync(0xffffffffu, colN[h], 8);
        colN[h] += __shfl_xor_sync(0xffffffffu, colN[h], 16);
    }
    if (l < 4) {
#pragma unroll
        for (int h = 0; h < 8; h++) {
            const int cloc = wn * 32 + (h >> 1) * 8 + l * 2 + (h & 1);
            sCP[wm][cloc] = colP[h];
            sCN[wm][cloc] = colN[h];
        }
    }
#pragma unroll
    for (int o = 16; o > 0; o >>= 1) {
        sp  += __shfl_xor_sync(0xffffffffu, sp,  o);
        sn  += __shfl_xor_sync(0xffffffffu, sn,  o);
        spc += __shfl_xor_sync(0xffffffffu, spc, o);
        snc += __shfl_xor_sync(0xffffffffu, snc, o);
    }
    if (l == 0) { sSpec[w][0] = sp; sSpec[w][1] = sn; sSpec[w][2] = spc; sSpec[w][3] = snc; }
    __syncthreads();

    if (tid < BT) {
        g_pos_part[(rowBlk + tid) * TILES_MAX + bj] =
            sRP[0][tid] + sRP[1][tid] + sRP[2][tid] + sRP[3][tid];
        g_neg_part[(rowBlk + tid) * TILES_MAX + bj] =
            sRN[0][tid] + sRN[1][tid] + sRN[2][tid] + sRN[3][tid];
    } else if (offd) {
        const int cc = tid - BT;
        g_pos_part[(colBlk + cc) * TILES_MAX + bi] = sCP[0][cc] + sCP[1][cc];
        g_neg_part[(colBlk + cc) * TILES_MAX + bi] = sCN[0][cc] + sCN[1][cc];
    }
    if (tid == 0 && bj == nT - 1) {
        float a0 = 0.f, a1 = 0.f, a2 = 0.f, a3 = 0.f;
#pragma unroll
        for (int ww = 0; ww < 8; ww++) {
            a0 += sSpec[ww][0]; a1 += sSpec[ww][1];
            a2 += sSpec[ww][2]; a3 += sSpec[ww][3];
        }
        if (offd) { g_last_part[bi][0] = a2; g_last_part[bi][1] = a3; }
        else      { g_last_part[bj][0] = a0; g_last_part[bj][1] = a1; }
    }
}

// ---------------------------------------------------------------------------
// finalize: 32 blocks; last-arriving block produces the 4 outputs.
// ---------------------------------------------------------------------------
__global__ void finalize_kernel(float* __restrict__ out, int n, int nTiles) {
    __shared__ float sLoss[128];
    __shared__ float sInv[128];
    __shared__ int sLast;
    const int t = threadIdx.x;
    const int i = blockIdx.x * 128 + t;
    float loss = 0.f, inv = 0.f;
    if (i < n) {
        float ps = 0.f, ns = 0.f;
        for (int b = 0; b < nTiles; b++) {
            ps += g_pos_part[i * TILES_MAX + b];
            ns += g_neg_part[i * TILES_MAX + b];
        }
        const int c = g_hist[g_tgt[i]];
        const float pc = (float)(c - 1 + g_diag_in[i]);
        const float nc = (float)(n - c);
        const float pl = ps / fmaxf(pc, 1.f);
        const float nl = ns / fmaxf(nc, 1.f);
        if (nc > 0.f) loss = pl + nl; else inv = 1.f;
    }
    sLoss[t] = loss; sInv[t] = inv;
    __syncthreads();
    for (int s = 64; s > 0; s >>= 1) {
        if (t < s) { sLoss[t] += sLoss[t + s]; sInv[t] += sInv[t + s]; }
        __syncthreads();
    }
    if (t == 0) {
        g_loss_part[blockIdx.x] = sLoss[0];
        g_inv_part[blockIdx.x]  = sInv[0];
        __threadfence();
        sLast = (atomicAdd(&g_fin_cnt, 1) == (int)gridDim.x - 1) ? 1 : 0;
    }
    __syncthreads();
    if (sLast && t < 32) {
        const int nB = (int)gridDim.x;
        float ls = (t < nB) ? g_loss_part[t] : 0.f;
        float iv = (t < nB) ? g_inv_part[t]  : 0.f;
        float sp = (t < nTiles) ? g_last_part[t][0] : 0.f;
        float sn = (t < nTiles) ? g_last_part[t][1] : 0.f;
#pragma unroll
        for (int off = 16; off > 0; off >>= 1) {
            ls += __shfl_down_sync(0xffffffffu, ls, off);
            iv += __shfl_down_sync(0xffffffffu, iv, off);
            sp += __shfl_down_sync(0xffffffffu, sp, off);
            sn += __shfl_down_sync(0xffffffffu, sn, off);
        }
        if (t == 0) {
            const int c = g_hist[g_tgt[n - 1]];
            const float pc = (float)(c - 1 + g_diag_in[n - 1]);
            out[0] = ls / (float)n;
            out[1] = iv / (float)n;
            out[2] = sp / fmaxf(pc, 1.f);
            out[3] = sn / fmaxf((float)(n - c), 1.f);
        }
        __syncwarp();
        for (int ii = t; ii < CLSMAX; ii += 32) g_hist[ii] = 0;  // replay reset
        if (t == 0) g_fin_cnt = 0;
    }
}

// ---------------------------------------------------------------------------
extern "C" void kernel_launch(void* const* d_in, const int* in_sizes, int n_in,
                              void* d_out, int out_size) {
    int ix = 0, it = 1;
    if (n_in >= 2 && in_sizes[0] < in_sizes[1]) { ix = 1; it = 0; }
    const float* X = (const float*)d_in[ix];
    const void*  T = d_in[it];
    const int n = in_sizes[it];
    const int d = in_sizes[ix] / n;
    const int nT = n / BT;
    const int nBlocks = nT * (nT + 1) / 2;
    const int nFin = (n + 127) / 128;
    const int dynBytes = 2 * STAGE_B;     // 81920

    static int attr_set = 0;
    if (!attr_set) {
        cudaFuncSetAttribute(binloss_mma, cudaFuncAttributeMaxDynamicSharedMemorySize, dynBytes);
        attr_set = 1;
    }

    diag_split_kernel<<<n / 32, 256>>>(X, T, n, d);
    binloss_mma<<<nBlocks, 256, dynBytes>>>(n, d);
    finalize_kernel<<<nFin, 128>>>((float*)d_out, n, nT);
}

// round 14
// speedup vs baseline: 4.1678x; 1.0294x over previous
#include <cuda_runtime.h>
#include <cuda_bf16.h>
#include <stdint.h>

// ---------------------------------------------------------------------------
// BinomialLoss, round 13 (R12 resubmit after infra failure):
//  - diag_split: 512 blocks x 8 rows, single-shot staging, no inner barriers
//  - main: MMA term-reordering (nj-inner) to break accumulator RAW chains
// HMMA bf16x2-split GEMM, KC=32 2-stage, occupancy 2, triangle tiles.
// Diagonal <1.0 decision: exact sequential ascending-k fp32 FMA chain.
// ---------------------------------------------------------------------------

#define NMAX   4096
#define DMAX   512
#define CLSMAX 512
#define TILES_MAX 32
#define BT   128
#define KC   32
#define SPE  40                         // smem row stride in bf16 (80 B)
#define TILE_B  (BT * SPE * 2)          // 10240 B per tile
#define STAGE_B (4 * TILE_B)            // 40960 B per stage (A0,A1,B0,B1)

// -------- scratch ----------------------------------------------------------
__device__ int   g_tgt[NMAX];
__device__ int   g_hist[CLSMAX];        // zero-init; re-zeroed each replay
__device__ int   g_fin_cnt;             // finalize ticket; re-zeroed each replay
__device__ float g_diag_val[NMAX];
__device__ int   g_diag_in[NMAX];
__device__ float g_pos_part[NMAX * TILES_MAX];   // [row*32 + tile]
__device__ float g_neg_part[NMAX * TILES_MAX];
__device__ float g_last_part[TILES_MAX][2];
__device__ float g_loss_part[64];
__device__ float g_inv_part[64];
__device__ __nv_bfloat16 g_b0[NMAX * DMAX];
__device__ __nv_bfloat16 g_b1[NMAX * DMAX];

__device__ __forceinline__ uint32_t smem_u32(const void* p) {
    uint32_t a;
    asm("{ .reg .u64 t; cvta.to.shared.u64 t, %1; cvt.u32.u64 %0, t; }" : "=r"(a) : "l"(p));
    return a;
}
__device__ __forceinline__ float softplus_fast(float z) {
    return fmaxf(z, 0.f) + __logf(1.f + __expf(-fabsf(z)));
}
__device__ __forceinline__ void cp16(uint32_t s, const void* g) {
    asm volatile("cp.async.cg.shared.global [%0], [%1], 16;" :: "r"(s), "l"(g));
}
__device__ __forceinline__ void cp_commit() {
    asm volatile("cp.async.commit_group;" ::: "memory");
}
__device__ __forceinline__ void cp_wait1() {
    asm volatile("cp.async.wait_group 1;" ::: "memory");
}
__device__ __forceinline__ void cp_wait0() {
    asm volatile("cp.async.wait_group 0;" ::: "memory");
}

#define LDMX4(R, ADDR)                                                          \
    asm volatile("ldmatrix.sync.aligned.m8n8.x4.shared.b16 {%0,%1,%2,%3}, [%4];"\
        : "=r"((R)[0]), "=r"((R)[1]), "=r"((R)[2]), "=r"((R)[3]) : "r"(ADDR))

#define MMA16816(D, A, B0r, B1r)                                                \
    asm volatile(                                                               \
        "mma.sync.aligned.m16n8k16.row.col.f32.bf16.bf16.f32 "                  \
        "{%0,%1,%2,%3}, {%4,%5,%6,%7}, {%8,%9}, {%0,%1,%2,%3};"                 \
        : "+f"((D)[0]), "+f"((D)[1]), "+f"((D)[2]), "+f"((D)[3])                \
        : "r"((A)[0]), "r"((A)[1]), "r"((A)[2]), "r"((A)[3]),                   \
          "r"(B0r), "r"(B1r))

// ---------------------------------------------------------------------------
// fused targets + split + diag. grid = n/8 blocks x 256 threads.
// Each block: 8 rows staged in one shot; lanes 0-7 run full 512-FMA chains.
// ---------------------------------------------------------------------------
__global__ void diag_split_kernel(const float* __restrict__ X,
                                  const void* __restrict__ tgt_raw, int n, int d) {
    __shared__ float sx[8][513];
    __shared__ int sIs64;
    const int t = threadIdx.x;
    const int rowBlk = blockIdx.x * 8;

    if (t == 0) sIs64 = 1;
    __syncthreads();
    const long long* p64 = (const long long*)tgt_raw;
    const int*       p32 = (const int*)tgt_raw;
    if (t < 64) {
        long long v = p64[t];
        if (v < 0 || v >= (long long)CLSMAX) atomicAnd(&sIs64, 0);
    }
    __syncthreads();
    if (t < 8) {
        int v = sIs64 ? (int)p64[rowBlk + t] : p32[rowBlk + t];
        if (v < 0) v = 0;
        if (v >= CLSMAX) v = CLSMAX - 1;
        g_tgt[rowBlk + t] = v;
        atomicAdd(&g_hist[v], 1);        // int adds: order-independent
    }

    // 8 rows x 512 cols = 4096 floats = 2048 float2 / 256 thr = 8 per thread
#pragma unroll
    for (int u = 0; u < 8; u++) {
        const int e2 = (t + u * 256) * 2;           // 0..4094 even
        const int r = e2 >> 9, cc = e2 & 511;
        const size_t gi = (size_t)(rowBlk + r) * d + cc;
        const float2 v = *(const float2*)(X + gi);
        const __nv_bfloat162 b = __float22bfloat162_rn(v);
        *(__nv_bfloat162*)(g_b0 + gi) = b;
        float2 rr;
        rr.x = v.x - __bfloat162float(b.x);
        rr.y = v.y - __bfloat162float(b.y);
        *(__nv_bfloat162*)(g_b1 + gi) = __float22bfloat162_rn(rr);
        sx[r][cc] = v.x;
        sx[r][cc + 1] = v.y;
    }
    __syncthreads();

    if (t < 8) {
        float acc = 0.f;
#pragma unroll 16
        for (int k = 0; k < 512; k++)
            acc = fmaf(sx[t][k], sx[t][k], acc);    // sequential, do not reassociate
        g_diag_val[rowBlk + t] = acc;
        g_diag_in[rowBlk + t]  = (acc < 1.0f) ? 1 : 0;
    }
}

// ---------------------------------------------------------------------------
// main: triangle tiles, HMMA bf16x2-split, KC=32 2-stage, occupancy 2.
// MMA terms reordered nj-inner to break accumulator RAW chains.
// ---------------------------------------------------------------------------
__global__ __launch_bounds__(256, 2)
void binloss_mma(int n, int d) {
    extern __shared__ __align__(16) char dyn_smem[];
    __shared__ float sRP[4][BT], sRN[4][BT];
    __shared__ float sCP[2][BT], sCN[2][BT];
    __shared__ int tR[BT], tC[BT];
    __shared__ float sSpec[8][4];

    const int nT = n / BT;
    int idx = blockIdx.x, bi = 0;
    while (idx >= nT - bi) { idx -= nT - bi; bi++; }
    const int bj = bi + idx;
    const bool offd = (bi != bj);
    const int rowBlk = bi * BT, colBlk = bj * BT;

    const int tid = threadIdx.x;
    const int w = tid >> 5, l = tid & 31;
    const int wm = w & 1, wn = w >> 1;
    const int lr15 = l & 15, lh8 = (l >> 4) * 8;

    if (tid < BT) { tR[tid] = g_tgt[rowBlk + tid]; tC[tid] = g_tgt[colBlk + tid]; }

    float acc[4][4][4];
#pragma unroll
    for (int a = 0; a < 4; a++)
#pragma unroll
        for (int b = 0; b < 4; b++)
#pragma unroll
            for (int r = 0; r < 4; r++) acc[a][b][r] = 0.f;

    const uint32_t sbase = smem_u32(dyn_smem);
    const int nChunks = d / KC;                      // 16

#define PREFETCH(CHUNK, STG)                                                    \
    do {                                                                        \
        const int k0_ = (CHUNK) * KC;                                           \
        const uint32_t sb_ = sbase + (uint32_t)(STG) * STAGE_B;                 \
        _Pragma("unroll")                                                       \
        for (int u = 0; u < 8; u++) {                                           \
            const int e = tid + u * 256;                                        \
            const int tile = e >> 9;                                            \
            const int r = (e >> 2) & 127;                                       \
            const int cc = e & 3;                                               \
            const int grow = (tile < 2 ? rowBlk : colBlk) + r;                  \
            const __nv_bfloat16* src_ = (tile & 1) ? g_b1 : g_b0;               \
            cp16(sb_ + (uint32_t)(tile * TILE_B + r * (SPE * 2) + cc * 16),     \
                 src_ + (size_t)grow * d + k0_ + cc * 8);                       \
        }                                                                       \
    } while (0)

    PREFETCH(0, 0);
    cp_commit();

    for (int c = 0; c < nChunks; c++) {
        if (c + 1 < nChunks) {
            PREFETCH(c + 1, (c + 1) & 1);
            cp_commit();
            cp_wait1();
        } else {
            cp_wait0();
        }
        __syncthreads();
        const uint32_t stageBase = sbase + (uint32_t)(c & 1) * STAGE_B;

#pragma unroll
        for (int ks = 0; ks < KC; ks += 16) {
            const uint32_t koff = (uint32_t)(ks + lh8) * 2;
            uint32_t b0f[8], b1f[8];
            {
                const uint32_t bb = stageBase + 2u * TILE_B +
                                    (uint32_t)(wn * 32 + lr15) * (SPE * 2) + koff;
                LDMX4(b0f + 0, bb);
                LDMX4(b0f + 4, bb + 16u * (SPE * 2));
                const uint32_t cb = bb + (uint32_t)TILE_B;
                LDMX4(b1f + 0, cb);
                LDMX4(b1f + 4, cb + 16u * (SPE * 2));
            }
#pragma unroll
            for (int mi = 0; mi < 4; mi++) {
                uint32_t a0f[4], a1f[4];
                const uint32_t ab = stageBase +
                    (uint32_t)(wm * 64 + mi * 16 + lr15) * (SPE * 2) + koff;
                LDMX4(a0f, ab);
                LDMX4(a1f, ab + (uint32_t)TILE_B);
                // term-outer / nj-inner: 4 independent accumulators between
                // reuses of any D register (breaks HMMA RAW chains)
#pragma unroll
                for (int nj = 0; nj < 4; nj++) {
                    const int h = (nj >> 1) * 4 + (nj & 1);
                    MMA16816(acc[mi][nj], a0f, b0f[h], b0f[h + 2]);
                }
#pragma unroll
                for (int nj = 0; nj < 4; nj++) {
                    const int h = (nj >> 1) * 4 + (nj & 1);
                    MMA16816(acc[mi][nj], a0f, b1f[h], b1f[h + 2]);
                }
#pragma unroll
                for (int nj = 0; nj < 4; nj++) {
                    const int h = (nj >> 1) * 4 + (nj & 1);
                    MMA16816(acc[mi][nj], a1f, b0f[h], b0f[h + 2]);
                }
            }
        }
        __syncthreads();
    }
#undef PREFETCH

    // ---- fused epilogue (verified) ----
    const float ALPHA = 40.f, MARGIN = 0.5f;
    const int r0 = l >> 2, c0 = (l & 3) * 2;
    float rowP[8], rowN[8], colP[8], colN[8];
#pragma unroll
    for (int g = 0; g < 8; g++) { rowP[g] = rowN[g] = colP[g] = colN[g] = 0.f; }
    float sp = 0.f, sn = 0.f, spc = 0.f, snc = 0.f;

#pragma unroll
    for (int mi = 0; mi < 4; mi++) {
#pragma unroll
        for (int rh = 0; rh < 2; rh++) {
            const int rloc = wm * 64 + mi * 16 + r0 + rh * 8;
            const int gr = rowBlk + rloc;
            const int tr = tR[rloc];
            const bool isLastRow = (gr == n - 1);
            const int g = mi * 2 + rh;
#pragma unroll
            for (int nj = 0; nj < 4; nj++) {
#pragma unroll
                for (int p = 0; p < 2; p++) {
                    const int cloc = wn * 32 + nj * 8 + c0 + p;
                    const int gc = colBlk + cloc;
                    const int h = nj * 2 + p;
                    const float sv = acc[mi][nj][rh * 2 + p];
                    if (gc == gr) {
                        if (g_diag_in[gr]) {
                            const float dv = g_diag_val[gr];
                            rowP[g] += softplus_fast(-2.f * (dv - MARGIN));
                            if (isLastRow) sp += dv;
                        }
                    } else {
                        const bool same = (tr == tC[cloc]);
                        const float z = same ? (-2.f * (sv - MARGIN))
                                             : (ALPHA * (sv - MARGIN));
                        const float lv = softplus_fast(z);
                        if (same) {
                            rowP[g] += lv; colP[h] += lv;
                            if (isLastRow) sp += sv;
                            if (offd && gc == n - 1) spc += sv;
                        } else {
                            rowN[g] += lv; colN[h] += lv;
                            if (isLastRow) sn += sv;
                            if (offd && gc == n - 1) snc += sv;
                        }
                    }
                }
            }
        }
    }

#pragma unroll
    for (int g = 0; g < 8; g++) {
        rowP[g] += __shfl_xor_sync(0xffffffffu, rowP[g], 1);
        rowP[g] += __shfl_xor_sync(0xffffffffu, rowP[g], 2);
        rowN[g] += __shfl_xor_sync(0xffffffffu, rowN[g], 1);
        rowN[g] += __shfl_xor_sync(0xffffffffu, rowN[g], 2);
    }
    if ((l & 3) == 0) {
#pragma unroll
        for (int g = 0; g < 8; g++) {
            const int rloc = wm * 64 + (g >> 1) * 16 + r0 + (g & 1) * 8;
            sRP[wn][rloc] = rowP[g];
            sRN[wn][rloc] = rowN[g];
        }
    }
#pragma unroll
    for (int h = 0; h < 8; h++) {
        colP[h] += __shfl_xor_sync(0xffffffffu, colP[h], 4);
        colP[h] += __shfl_xor_sync(0xffffffffu, colP[h], 8);
        colP[h] += __shfl_xor_sync(0xffffffffu, colP[h], 16);
        colN[h] += __shfl_xor_sync(0xffffffffu, colN[h], 4);
        colN[h] += __shfl_xor_sync(0xffffffffu, colN[h], 8);
        colN[h] += __shfl_xor_sync(0xffffffffu, colN[h], 16);
    }
    if (l < 4) {
#pragma unroll
        for (int h = 0; h < 8; h++) {
            const int cloc = wn * 32 + (h >> 1) * 8 + l * 2 + (h & 1);
            sCP[wm][cloc] = colP[h];
            sCN[wm][cloc] = colN[h];
        }
    }
#pragma unroll
    for (int o = 16; o > 0; o >>= 1) {
        sp  += __shfl_xor_sync(0xffffffffu, sp,  o);
        sn  += __shfl_xor_sync(0xffffffffu, sn,  o);
        spc += __shfl_xor_sync(0xffffffffu, spc, o);
        snc += __shfl_xor_sync(0xffffffffu, snc, o);
    }
    if (l == 0) { sSpec[w][0] = sp; sSpec[w][1] = sn; sSpec[w][2] = spc; sSpec[w][3] = snc; }
    __syncthreads();

    if (tid < BT) {
        g_pos_part[(rowBlk + tid) * TILES_MAX + bj] =
            sRP[0][tid] + sRP[1][tid] + sRP[2][tid] + sRP[3][tid];
        g_neg_part[(rowBlk + tid) * TILES_MAX + bj] =
            sRN[0][tid] + sRN[1][tid] + sRN[2][tid] + sRN[3][tid];
    } else if (offd) {
        const int cc = tid - BT;
        g_pos_part[(colBlk + cc) * TILES_MAX + bi] = sCP[0][cc] + sCP[1][cc];
        g_neg_part[(colBlk + cc) * TILES_MAX + bi] = sCN[0][cc] + sCN[1][cc];
    }
    if (tid == 0 && bj == nT - 1) {
        float a0 = 0.f, a1 = 0.f, a2 = 0.f, a3 = 0.f;
#pragma unroll
        for (int ww = 0; ww < 8; ww++) {
            a0 += sSpec[ww][0]; a1 += sSpec[ww][1];
            a2 += sSpec[ww][2]; a3 += sSpec[ww][3];
        }
        if (offd) { g_last_part[bi][0] = a2; g_last_part[bi][1] = a3; }
        else      { g_last_part[bj][0] = a0; g_last_part[bj][1] = a1; }
    }
}

// ---------------------------------------------------------------------------
// finalize: 32 blocks; last-arriving block produces the 4 outputs.
// ---------------------------------------------------------------------------
__global__ void finalize_kernel(float* __restrict__ out, int n, int nTiles) {
    __shared__ float sLoss[128];
    __shared__ float sInv[128];
    __shared__ int sLast;
    const int t = threadIdx.x;
    const int i = blockIdx.x * 128 + t;
    float loss = 0.f, inv = 0.f;
    if (i < n) {
        float ps = 0.f, ns = 0.f;
        for (int b = 0; b < nTiles; b++) {
            ps += g_pos_part[i * TILES_MAX + b];
            ns += g_neg_part[i * TILES_MAX + b];
        }
        const int c = g_hist[g_tgt[i]];
        const float pc = (float)(c - 1 + g_diag_in[i]);
        const float nc = (float)(n - c);
        const float pl = ps / fmaxf(pc, 1.f);
        const float nl = ns / fmaxf(nc, 1.f);
        if (nc > 0.f) loss = pl + nl; else inv = 1.f;
    }
    sLoss[t] = loss; sInv[t] = inv;
    __syncthreads();
    for (int s = 64; s > 0; s >>= 1) {
        if (t < s) { sLoss[t] += sLoss[t + s]; sInv[t] += sInv[t + s]; }
        __syncthreads();
    }
    if (t == 0) {
        g_loss_part[blockIdx.x] = sLoss[0];
        g_inv_part[blockIdx.x]  = sInv[0];
        __threadfence();
        sLast = (atomicAdd(&g_fin_cnt, 1) == (int)gridDim.x - 1) ? 1 : 0;
    }
    __syncthreads();
    if (sLast && t < 32) {
        const int nB = (int)gridDim.x;
        float ls = (t < nB) ? g_loss_part[t] : 0.f;
        float iv = (t < nB) ? g_inv_part[t]  : 0.f;
        float sp = (t < nTiles) ? g_last_part[t][0] : 0.f;
        float sn = (t < nTiles) ? g_last_part[t][1] : 0.f;
#pragma unroll
        for (int off = 16; off > 0; off >>= 1) {
            ls += __shfl_down_sync(0xffffffffu, ls, off);
            iv += __shfl_down_sync(0xffffffffu, iv, off);
            sp += __shfl_down_sync(0xffffffffu, sp, off);
            sn += __shfl_down_sync(0xffffffffu, sn, off);
        }
        if (t == 0) {
            const int c = g_hist[g_tgt[n - 1]];
            const float pc = (float)(c - 1 + g_diag_in[n - 1]);
            out[0] = ls / (float)n;
            out[1] = iv / (float)n;
            out[2] = sp / fmaxf(pc, 1.f);
            out[3] = sn / fmaxf((float)(n - c), 1.f);
        }
        __syncwarp();
        for (int ii = t; ii < CLSMAX; ii += 32) g_hist[ii] = 0;  // replay reset
        if (t == 0) g_fin_cnt = 0;
    }
}

// ---------------------------------------------------------------------------
extern "C" void kernel_launch(void* const* d_in, const int* in_sizes, int n_in,
                              void* d_out, int out_size) {
    int ix = 0, it = 1;
    if (n_in >= 2 && in_sizes[0] < in_sizes[1]) { ix = 1; it = 0; }
    const float* X = (const float*)d_in[ix];
    const void*  T = d_in[it];
    const int n = in_sizes[it];
    const int d = in_sizes[ix] / n;
    const int nT = n / BT;
    const int nBlocks = nT * (nT + 1) / 2;
    const int nFin = (n + 127) / 128;
    const int dynBytes = 2 * STAGE_B;     // 81920

    static int attr_set = 0;
    if (!attr_set) {
        cudaFuncSetAttribute(binloss_mma, cudaFuncAttributeMaxDynamicSharedMemorySize, dynBytes);
        attr_set = 1;
    }

    diag_split_kernel<<<n / 8, 256>>>(X, T, n, d);
    binloss_mma<<<nBlocks, 256, dynBytes>>>(n, d);
    finalize_kernel<<<nFin, 128>>>((float*)d_out, n, nT);
}

// round 15
// speedup vs baseline: 4.2855x; 1.0282x over previous
#include <cuda_runtime.h>
#include <cuda_bf16.h>
#include <stdint.h>

// ---------------------------------------------------------------------------
// BinomialLoss, round 15:
//  - diag_split: batched float4 loads + 8B bf16x2-pair stores
//  - finalize: float4 partial reads
//  - main kernel frozen (at ~93% of the mma.sync issue wall)
// HMMA bf16x2-split GEMM, KC=32 2-stage, occupancy 2, triangle tiles.
// Diagonal <1.0 decision: exact sequential ascending-k fp32 FMA chain.
// ---------------------------------------------------------------------------

#define NMAX   4096
#define DMAX   512
#define CLSMAX 512
#define TILES_MAX 32
#define BT   128
#define KC   32
#define SPE  40                         // smem row stride in bf16 (80 B)
#define TILE_B  (BT * SPE * 2)          // 10240 B per tile
#define STAGE_B (4 * TILE_B)            // 40960 B per stage (A0,A1,B0,B1)

// -------- scratch ----------------------------------------------------------
__device__ int   g_tgt[NMAX];
__device__ int   g_hist[CLSMAX];        // zero-init; re-zeroed each replay
__device__ int   g_fin_cnt;             // finalize ticket; re-zeroed each replay
__device__ float g_diag_val[NMAX];
__device__ int   g_diag_in[NMAX];
__device__ float g_pos_part[NMAX * TILES_MAX];   // [row*32 + tile]
__device__ float g_neg_part[NMAX * TILES_MAX];
__device__ float g_last_part[TILES_MAX][2];
__device__ float g_loss_part[64];
__device__ float g_inv_part[64];
__device__ __nv_bfloat16 g_b0[NMAX * DMAX];
__device__ __nv_bfloat16 g_b1[NMAX * DMAX];

__device__ __forceinline__ uint32_t smem_u32(const void* p) {
    uint32_t a;
    asm("{ .reg .u64 t; cvta.to.shared.u64 t, %1; cvt.u32.u64 %0, t; }" : "=r"(a) : "l"(p));
    return a;
}
__device__ __forceinline__ float softplus_fast(float z) {
    return fmaxf(z, 0.f) + __logf(1.f + __expf(-fabsf(z)));
}
__device__ __forceinline__ void cp16(uint32_t s, const void* g) {
    asm volatile("cp.async.cg.shared.global [%0], [%1], 16;" :: "r"(s), "l"(g));
}
__device__ __forceinline__ void cp_commit() {
    asm volatile("cp.async.commit_group;" ::: "memory");
}
__device__ __forceinline__ void cp_wait1() {
    asm volatile("cp.async.wait_group 1;" ::: "memory");
}
__device__ __forceinline__ void cp_wait0() {
    asm volatile("cp.async.wait_group 0;" ::: "memory");
}

#define LDMX4(R, ADDR)                                                          \
    asm volatile("ldmatrix.sync.aligned.m8n8.x4.shared.b16 {%0,%1,%2,%3}, [%4];"\
        : "=r"((R)[0]), "=r"((R)[1]), "=r"((R)[2]), "=r"((R)[3]) : "r"(ADDR))

#define MMA16816(D, A, B0r, B1r)                                                \
    asm volatile(                                                               \
        "mma.sync.aligned.m16n8k16.row.col.f32.bf16.bf16.f32 "                  \
        "{%0,%1,%2,%3}, {%4,%5,%6,%7}, {%8,%9}, {%0,%1,%2,%3};"                 \
        : "+f"((D)[0]), "+f"((D)[1]), "+f"((D)[2]), "+f"((D)[3])                \
        : "r"((A)[0]), "r"((A)[1]), "r"((A)[2]), "r"((A)[3]),                   \
          "r"(B0r), "r"(B1r))

// ---------------------------------------------------------------------------
// fused targets + split + diag. grid = n/8 blocks x 256 threads.
// Batched float4 loads; 8B packed bf16x2-pair stores; lanes 0-7 run chains.
// ---------------------------------------------------------------------------
__global__ void diag_split_kernel(const float* __restrict__ X,
                                  const void* __restrict__ tgt_raw, int n, int d) {
    __shared__ float sx[8][513];
    __shared__ int sIs64;
    const int t = threadIdx.x;
    const int rowBlk = blockIdx.x * 8;

    if (t == 0) sIs64 = 1;
    __syncthreads();
    const long long* p64 = (const long long*)tgt_raw;
    const int*       p32 = (const int*)tgt_raw;
    if (t < 64) {
        long long v = p64[t];
        if (v < 0 || v >= (long long)CLSMAX) atomicAnd(&sIs64, 0);
    }
    __syncthreads();
    if (t < 8) {
        int v = sIs64 ? (int)p64[rowBlk + t] : p32[rowBlk + t];
        if (v < 0) v = 0;
        if (v >= CLSMAX) v = CLSMAX - 1;
        g_tgt[rowBlk + t] = v;
        atomicAdd(&g_hist[v], 1);        // int adds: order-independent
    }

    // 8 rows x 512 cols = 4096 floats = 1024 float4 / 256 thr = 4 per thread
    float4 vv[4];
#pragma unroll
    for (int u = 0; u < 4; u++) {
        const int e4 = (t + u * 256) * 4;           // 0..4092, mult of 4
        const int r = e4 >> 9, cc = e4 & 511;
        vv[u] = *(const float4*)(X + (size_t)(rowBlk + r) * d + cc);
    }
#pragma unroll
    for (int u = 0; u < 4; u++) {
        const int e4 = (t + u * 256) * 4;
        const int r = e4 >> 9, cc = e4 & 511;
        const size_t gi = (size_t)(rowBlk + r) * d + cc;
        const float4 v = vv[u];
        float2 lo = make_float2(v.x, v.y), hi = make_float2(v.z, v.w);
        const __nv_bfloat162 b0lo = __float22bfloat162_rn(lo);
        const __nv_bfloat162 b0hi = __float22bfloat162_rn(hi);
        uint2 pk0;
        pk0.x = *(const uint32_t*)&b0lo;
        pk0.y = *(const uint32_t*)&b0hi;
        *(uint2*)(g_b0 + gi) = pk0;                 // 8B store
        float2 r0 = make_float2(v.x - __bfloat162float(b0lo.x),
                                v.y - __bfloat162float(b0lo.y));
        float2 r1 = make_float2(v.z - __bfloat162float(b0hi.x),
                                v.w - __bfloat162float(b0hi.y));
        const __nv_bfloat162 b1lo = __float22bfloat162_rn(r0);
        const __nv_bfloat162 b1hi = __float22bfloat162_rn(r1);
        uint2 pk1;
        pk1.x = *(const uint32_t*)&b1lo;
        pk1.y = *(const uint32_t*)&b1hi;
        *(uint2*)(g_b1 + gi) = pk1;                 // 8B store
        sx[r][cc] = v.x; sx[r][cc + 1] = v.y;
        sx[r][cc + 2] = v.z; sx[r][cc + 3] = v.w;
    }
    __syncthreads();

    if (t < 8) {
        float acc = 0.f;
#pragma unroll 16
        for (int k = 0; k < 512; k++)
            acc = fmaf(sx[t][k], sx[t][k], acc);    // sequential, do not reassociate
        g_diag_val[rowBlk + t] = acc;
        g_diag_in[rowBlk + t]  = (acc < 1.0f) ? 1 : 0;
    }
}

// ---------------------------------------------------------------------------
// main: triangle tiles, HMMA bf16x2-split, KC=32 2-stage, occupancy 2.
// (frozen — at the mma.sync issue wall)
// ---------------------------------------------------------------------------
__global__ __launch_bounds__(256, 2)
void binloss_mma(int n, int d) {
    extern __shared__ __align__(16) char dyn_smem[];
    __shared__ float sRP[4][BT], sRN[4][BT];
    __shared__ float sCP[2][BT], sCN[2][BT];
    __shared__ int tR[BT], tC[BT];
    __shared__ float sSpec[8][4];

    const int nT = n / BT;
    int idx = blockIdx.x, bi = 0;
    while (idx >= nT - bi) { idx -= nT - bi; bi++; }
    const int bj = bi + idx;
    const bool offd = (bi != bj);
    const int rowBlk = bi * BT, colBlk = bj * BT;

    const int tid = threadIdx.x;
    const int w = tid >> 5, l = tid & 31;
    const int wm = w & 1, wn = w >> 1;
    const int lr15 = l & 15, lh8 = (l >> 4) * 8;

    if (tid < BT) { tR[tid] = g_tgt[rowBlk + tid]; tC[tid] = g_tgt[colBlk + tid]; }

    float acc[4][4][4];
#pragma unroll
    for (int a = 0; a < 4; a++)
#pragma unroll
        for (int b = 0; b < 4; b++)
#pragma unroll
            for (int r = 0; r < 4; r++) acc[a][b][r] = 0.f;

    const uint32_t sbase = smem_u32(dyn_smem);
    const int nChunks = d / KC;                      // 16

#define PREFETCH(CHUNK, STG)                                                    \
    do {                                                                        \
        const int k0_ = (CHUNK) * KC;                                           \
        const uint32_t sb_ = sbase + (uint32_t)(STG) * STAGE_B;                 \
        _Pragma("unroll")                                                       \
        for (int u = 0; u < 8; u++) {                                           \
            const int e = tid + u * 256;                                        \
            const int tile = e >> 9;                                            \
            const int r = (e >> 2) & 127;                                       \
            const int cc = e & 3;                                               \
            const int grow = (tile < 2 ? rowBlk : colBlk) + r;                  \
            const __nv_bfloat16* src_ = (tile & 1) ? g_b1 : g_b0;               \
            cp16(sb_ + (uint32_t)(tile * TILE_B + r * (SPE * 2) + cc * 16),     \
                 src_ + (size_t)grow * d + k0_ + cc * 8);                       \
        }                                                                       \
    } while (0)

    PREFETCH(0, 0);
    cp_commit();

    for (int c = 0; c < nChunks; c++) {
        if (c + 1 < nChunks) {
            PREFETCH(c + 1, (c + 1) & 1);
            cp_commit();
            cp_wait1();
        } else {
            cp_wait0();
        }
        __syncthreads();
        const uint32_t stageBase = sbase + (uint32_t)(c & 1) * STAGE_B;

#pragma unroll
        for (int ks = 0; ks < KC; ks += 16) {
            const uint32_t koff = (uint32_t)(ks + lh8) * 2;
            uint32_t b0f[8], b1f[8];
            {
                const uint32_t bb = stageBase + 2u * TILE_B +
                                    (uint32_t)(wn * 32 + lr15) * (SPE * 2) + koff;
                LDMX4(b0f + 0, bb);
                LDMX4(b0f + 4, bb + 16u * (SPE * 2));
                const uint32_t cb = bb + (uint32_t)TILE_B;
                LDMX4(b1f + 0, cb);
                LDMX4(b1f + 4, cb + 16u * (SPE * 2));
            }
#pragma unroll
            for (int mi = 0; mi < 4; mi++) {
                uint32_t a0f[4], a1f[4];
                const uint32_t ab = stageBase +
                    (uint32_t)(wm * 64 + mi * 16 + lr15) * (SPE * 2) + koff;
                LDMX4(a0f, ab);
                LDMX4(a1f, ab + (uint32_t)TILE_B);
#pragma unroll
                for (int nj = 0; nj < 4; nj++) {
                    const int h = (nj >> 1) * 4 + (nj & 1);
                    MMA16816(acc[mi][nj], a0f, b0f[h], b0f[h + 2]);
                }
#pragma unroll
                for (int nj = 0; nj < 4; nj++) {
                    const int h = (nj >> 1) * 4 + (nj & 1);
                    MMA16816(acc[mi][nj], a0f, b1f[h], b1f[h + 2]);
                }
#pragma unroll
                for (int nj = 0; nj < 4; nj++) {
                    const int h = (nj >> 1) * 4 + (nj & 1);
                    MMA16816(acc[mi][nj], a1f, b0f[h], b0f[h + 2]);
                }
            }
        }
        __syncthreads();
    }
#undef PREFETCH

    // ---- fused epilogue (verified) ----
    const float ALPHA = 40.f, MARGIN = 0.5f;
    const int r0 = l >> 2, c0 = (l & 3) * 2;
    float rowP[8], rowN[8], colP[8], colN[8];
#pragma unroll
    for (int g = 0; g < 8; g++) { rowP[g] = rowN[g] = colP[g] = colN[g] = 0.f; }
    float sp = 0.f, sn = 0.f, spc = 0.f, snc = 0.f;

#pragma unroll
    for (int mi = 0; mi < 4; mi++) {
#pragma unroll
        for (int rh = 0; rh < 2; rh++) {
            const int rloc = wm * 64 + mi * 16 + r0 + rh * 8;
            const int gr = rowBlk + rloc;
            const int tr = tR[rloc];
            const bool isLastRow = (gr == n - 1);
            const int g = mi * 2 + rh;
#pragma unroll
            for (int nj = 0; nj < 4; nj++) {
#pragma unroll
                for (int p = 0; p < 2; p++) {
                    const int cloc = wn * 32 + nj * 8 + c0 + p;
                    const int gc = colBlk + cloc;
                    const int h = nj * 2 + p;
                    const float sv = acc[mi][nj][rh * 2 + p];
                    if (gc == gr) {
                        if (g_diag_in[gr]) {
                            const float dv = g_diag_val[gr];
                            rowP[g] += softplus_fast(-2.f * (dv - MARGIN));
                            if (isLastRow) sp += dv;
                        }
                    } else {
                        const bool same = (tr == tC[cloc]);
                        const float z = same ? (-2.f * (sv - MARGIN))
                                             : (ALPHA * (sv - MARGIN));
                        const float lv = softplus_fast(z);
                        if (same) {
                            rowP[g] += lv; colP[h] += lv;
                            if (isLastRow) sp += sv;
                            if (offd && gc == n - 1) spc += sv;
                        } else {
                            rowN[g] += lv; colN[h] += lv;
                            if (isLastRow) sn += sv;
                            if (offd && gc == n - 1) snc += sv;
                        }
                    }
                }
            }
        }
    }

#pragma unroll
    for (int g = 0; g < 8; g++) {
        rowP[g] += __shfl_xor_sync(0xffffffffu, rowP[g], 1);
        rowP[g] += __shfl_xor_sync(0xffffffffu, rowP[g], 2);
        rowN[g] += __shfl_xor_sync(0xffffffffu, rowN[g], 1);
        rowN[g] += __shfl_xor_sync(0xffffffffu, rowN[g], 2);
    }
    if ((l & 3) == 0) {
#pragma unroll
        for (int g = 0; g < 8; g++) {
            const int rloc = wm * 64 + (g >> 1) * 16 + r0 + (g & 1) * 8;
            sRP[wn][rloc] = rowP[g];
            sRN[wn][rloc] = rowN[g];
        }
    }
#pragma unroll
    for (int h = 0; h < 8; h++) {
        colP[h] += __shfl_xor_sync(0xffffffffu, colP[h], 4);
        colP[h] += __shfl_xor_sync(0xffffffffu, colP[h], 8);
        colP[h] += __shfl_xor_sync(0xffffffffu, colP[h], 16);
        colN[h] += __shfl_xor_sync(0xffffffffu, colN[h], 4);
        colN[h] += __shfl_xor_sync(0xffffffffu, colN[h], 8);
        colN[h] += __shfl_xor_sync(0xffffffffu, colN[h], 16);
    }
    if (l < 4) {
#pragma unroll
        for (int h = 0; h < 8; h++) {
            const int cloc = wn * 32 + (h >> 1) * 8 + l * 2 + (h & 1);
            sCP[wm][cloc] = colP[h];
            sCN[wm][cloc] = colN[h];
        }
    }
#pragma unroll
    for (int o = 16; o > 0; o >>= 1) {
        sp  += __shfl_xor_sync(0xffffffffu, sp,  o);
        sn  += __shfl_xor_sync(0xffffffffu, sn,  o);
        spc += __shfl_xor_sync(0xffffffffu, spc, o);
        snc += __shfl_xor_sync(0xffffffffu, snc, o);
    }
    if (l == 0) { sSpec[w][0] = sp; sSpec[w][1] = sn; sSpec[w][2] = spc; sSpec[w][3] = snc; }
    __syncthreads();

    if (tid < BT) {
        g_pos_part[(rowBlk + tid) * TILES_MAX + bj] =
            sRP[0][tid] + sRP[1][tid] + sRP[2][tid] + sRP[3][tid];
        g_neg_part[(rowBlk + tid) * TILES_MAX + bj] =
            sRN[0][tid] + sRN[1][tid] + sRN[2][tid] + sRN[3][tid];
    } else if (offd) {
        const int cc = tid - BT;
        g_pos_part[(colBlk + cc) * TILES_MAX + bi] = sCP[0][cc] + sCP[1][cc];
        g_neg_part[(colBlk + cc) * TILES_MAX + bi] = sCN[0][cc] + sCN[1][cc];
    }
    if (tid == 0 && bj == nT - 1) {
        float a0 = 0.f, a1 = 0.f, a2 = 0.f, a3 = 0.f;
#pragma unroll
        for (int ww = 0; ww < 8; ww++) {
            a0 += sSpec[ww][0]; a1 += sSpec[ww][1];
            a2 += sSpec[ww][2]; a3 += sSpec[ww][3];
        }
        if (offd) { g_last_part[bi][0] = a2; g_last_part[bi][1] = a3; }
        else      { g_last_part[bj][0] = a0; g_last_part[bj][1] = a1; }
    }
}

// ---------------------------------------------------------------------------
// finalize: 32 blocks, float4 partial reads; last block produces outputs.
// ---------------------------------------------------------------------------
__global__ void finalize_kernel(float* __restrict__ out, int n, int nTiles) {
    __shared__ float sLoss[128];
    __shared__ float sInv[128];
    __shared__ int sLast;
    const int t = threadIdx.x;
    const int i = blockIdx.x * 128 + t;
    float loss = 0.f, inv = 0.f;
    if (i < n) {
        float ps = 0.f, ns = 0.f;
        const float4* pp = (const float4*)(g_pos_part + (size_t)i * TILES_MAX);
        const float4* np = (const float4*)(g_neg_part + (size_t)i * TILES_MAX);
#pragma unroll
        for (int b = 0; b < TILES_MAX / 4; b++) {
            const float4 p4 = pp[b];
            const float4 n4 = np[b];
            ps += (p4.x + p4.y) + (p4.z + p4.w);
            ns += (n4.x + n4.y) + (n4.z + n4.w);
        }
        const int c = g_hist[g_tgt[i]];
        const float pc = (float)(c - 1 + g_diag_in[i]);
        const float nc = (float)(n - c);
        const float pl = ps / fmaxf(pc, 1.f);
        const float nl = ns / fmaxf(nc, 1.f);
        if (nc > 0.f) loss = pl + nl; else inv = 1.f;
    }
    sLoss[t] = loss; sInv[t] = inv;
    __syncthreads();
    for (int s = 64; s > 0; s >>= 1) {
        if (t < s) { sLoss[t] += sLoss[t + s]; sInv[t] += sInv[t + s]; }
        __syncthreads();
    }
    if (t == 0) {
        g_loss_part[blockIdx.x] = sLoss[0];
        g_inv_part[blockIdx.x]  = sInv[0];
        __threadfence();
        sLast = (atomicAdd(&g_fin_cnt, 1) == (int)gridDim.x - 1) ? 1 : 0;
    }
    __syncthreads();
    if (sLast && t < 32) {
        const int nB = (int)gridDim.x;
        float ls = (t < nB) ? g_loss_part[t] : 0.f;
        float iv = (t < nB) ? g_inv_part[t]  : 0.f;
        float sp = (t < nTiles) ? g_last_part[t][0] : 0.f;
        float sn = (t < nTiles) ? g_last_part[t][1] : 0.f;
#pragma unroll
        for (int off = 16; off > 0; off >>= 1) {
            ls += __shfl_down_sync(0xffffffffu, ls, off);
            iv += __shfl_down_sync(0xffffffffu, iv, off);
            sp += __shfl_down_sync(0xffffffffu, sp, off);
            sn += __shfl_down_sync(0xffffffffu, sn, off);
        }
        if (t == 0) {
            const int c = g_hist[g_tgt[n - 1]];
            const float pc = (float)(c - 1 + g_diag_in[n - 1]);
            out[0] = ls / (float)n;
            out[1] = iv / (float)n;
            out[2] = sp / fmaxf(pc, 1.f);
            out[3] = sn / fmaxf((float)(n - c), 1.f);
        }
        __syncwarp();
        for (int ii = t; ii < CLSMAX; ii += 32) g_hist[ii] = 0;  // replay reset
        if (t == 0) g_fin_cnt = 0;
    }
}

// ---------------------------------------------------------------------------
extern "C" void kernel_launch(void* const* d_in, const int* in_sizes, int n_in,
                              void* d_out, int out_size) {
    int ix = 0, it = 1;
    if (n_in >= 2 && in_sizes[0] < in_sizes[1]) { ix = 1; it = 0; }
    const float* X = (const float*)d_in[ix];
    const void*  T = d_in[it];
    const int n = in_sizes[it];
    const int d = in_sizes[ix] / n;
    const int nT = n / BT;
    const int nBlocks = nT * (nT + 1) / 2;
    const int nFin = (n + 127) / 128;
    const int dynBytes = 2 * STAGE_B;     // 81920

    static int attr_set = 0;
    if (!attr_set) {
        cudaFuncSetAttribute(binloss_mma, cudaFuncAttributeMaxDynamicSharedMemorySize, dynBytes);
        attr_set = 1;
    }

    diag_split_kernel<<<n / 8, 256>>>(X, T, n, d);
    binloss_mma<<<nBlocks, 256, dynBytes>>>(n, d);
    finalize_kernel<<<nFin, 128>>>((float*)d_out, n, nT);
}

// round 16
// speedup vs baseline: 4.3474x; 1.0145x over previous
#include <cuda_runtime.h>
#include <cuda_bf16.h>
#include <stdint.h>

// ---------------------------------------------------------------------------
// BinomialLoss, round 16:
//  - diag_split: 1024 blocks x 128 thr x 4 rows (smem 8.3KB -> 2x residency)
//  - finalize: 128 blocks x 32 thr, diagonal contributions moved here
//  - main epilogue: diagonal skipped (no g_diag loads); GEMM frozen
// HMMA bf16x2-split GEMM, KC=32 2-stage, occupancy 2, triangle tiles.
// Diagonal <1.0 decision: exact sequential ascending-k fp32 FMA chain.
// ---------------------------------------------------------------------------

#define NMAX   4096
#define DMAX   512
#define CLSMAX 512
#define TILES_MAX 32
#define BT   128
#define KC   32
#define SPE  40                         // smem row stride in bf16 (80 B)
#define TILE_B  (BT * SPE * 2)          // 10240 B per tile
#define STAGE_B (4 * TILE_B)            // 40960 B per stage (A0,A1,B0,B1)

// -------- scratch ----------------------------------------------------------
__device__ int   g_tgt[NMAX];
__device__ int   g_hist[CLSMAX];        // zero-init; re-zeroed each replay
__device__ int   g_fin_cnt;             // finalize ticket; re-zeroed each replay
__device__ float g_diag_val[NMAX];
__device__ int   g_diag_in[NMAX];
__device__ float g_pos_part[NMAX * TILES_MAX];   // [row*32 + tile]
__device__ float g_neg_part[NMAX * TILES_MAX];
__device__ float g_last_part[TILES_MAX][2];
__device__ float g_loss_part[128];
__device__ float g_inv_part[128];
__device__ __nv_bfloat16 g_b0[NMAX * DMAX];
__device__ __nv_bfloat16 g_b1[NMAX * DMAX];

__device__ __forceinline__ uint32_t smem_u32(const void* p) {
    uint32_t a;
    asm("{ .reg .u64 t; cvta.to.shared.u64 t, %1; cvt.u32.u64 %0, t; }" : "=r"(a) : "l"(p));
    return a;
}
__device__ __forceinline__ float softplus_fast(float z) {
    return fmaxf(z, 0.f) + __logf(1.f + __expf(-fabsf(z)));
}
__device__ __forceinline__ void cp16(uint32_t s, const void* g) {
    asm volatile("cp.async.cg.shared.global [%0], [%1], 16;" :: "r"(s), "l"(g));
}
__device__ __forceinline__ void cp_commit() {
    asm volatile("cp.async.commit_group;" ::: "memory");
}
__device__ __forceinline__ void cp_wait1() {
    asm volatile("cp.async.wait_group 1;" ::: "memory");
}
__device__ __forceinline__ void cp_wait0() {
    asm volatile("cp.async.wait_group 0;" ::: "memory");
}

#define LDMX4(R, ADDR)                                                          \
    asm volatile("ldmatrix.sync.aligned.m8n8.x4.shared.b16 {%0,%1,%2,%3}, [%4];"\
        : "=r"((R)[0]), "=r"((R)[1]), "=r"((R)[2]), "=r"((R)[3]) : "r"(ADDR))

#define MMA16816(D, A, B0r, B1r)                                                \
    asm volatile(                                                               \
        "mma.sync.aligned.m16n8k16.row.col.f32.bf16.bf16.f32 "                  \
        "{%0,%1,%2,%3}, {%4,%5,%6,%7}, {%8,%9}, {%0,%1,%2,%3};"                 \
        : "+f"((D)[0]), "+f"((D)[1]), "+f"((D)[2]), "+f"((D)[3])                \
        : "r"((A)[0]), "r"((A)[1]), "r"((A)[2]), "r"((A)[3]),                   \
          "r"(B0r), "r"(B1r))

// ---------------------------------------------------------------------------
// fused targets + split + diag. grid = n/4 blocks x 128 threads.
// 4 rows/block; batched float4 loads, packed 8B stores; lanes 0-3 run chains.
// ---------------------------------------------------------------------------
__global__ void diag_split_kernel(const float* __restrict__ X,
                                  const void* __restrict__ tgt_raw, int n, int d) {
    __shared__ float sx[4][516];
    __shared__ int sIs64;
    const int t = threadIdx.x;
    const int rowBlk = blockIdx.x * 4;

    if (t == 0) sIs64 = 1;
    __syncthreads();
    const long long* p64 = (const long long*)tgt_raw;
    const int*       p32 = (const int*)tgt_raw;
    if (t < 64) {
        long long v = p64[t];
        if (v < 0 || v >= (long long)CLSMAX) atomicAnd(&sIs64, 0);
    }
    __syncthreads();
    if (t < 4) {
        int v = sIs64 ? (int)p64[rowBlk + t] : p32[rowBlk + t];
        if (v < 0) v = 0;
        if (v >= CLSMAX) v = CLSMAX - 1;
        g_tgt[rowBlk + t] = v;
        atomicAdd(&g_hist[v], 1);        // int adds: order-independent
    }

    // 4 rows x 512 cols = 2048 floats = 512 float4 / 128 thr = 4 per thread
    float4 vv[4];
#pragma unroll
    for (int u = 0; u < 4; u++) {
        const int e4 = (t + u * 128) * 4;           // 0..2044, mult of 4
        const int r = e4 >> 9, cc = e4 & 511;
        vv[u] = *(const float4*)(X + (size_t)(rowBlk + r) * d + cc);
    }
#pragma unroll
    for (int u = 0; u < 4; u++) {
        const int e4 = (t + u * 128) * 4;
        const int r = e4 >> 9, cc = e4 & 511;
        const size_t gi = (size_t)(rowBlk + r) * d + cc;
        const float4 v = vv[u];
        float2 lo = make_float2(v.x, v.y), hi = make_float2(v.z, v.w);
        const __nv_bfloat162 b0lo = __float22bfloat162_rn(lo);
        const __nv_bfloat162 b0hi = __float22bfloat162_rn(hi);
        uint2 pk0;
        pk0.x = *(const uint32_t*)&b0lo;
        pk0.y = *(const uint32_t*)&b0hi;
        *(uint2*)(g_b0 + gi) = pk0;                 // 8B store
        float2 r0 = make_float2(v.x - __bfloat162float(b0lo.x),
                                v.y - __bfloat162float(b0lo.y));
        float2 r1 = make_float2(v.z - __bfloat162float(b0hi.x),
                                v.w - __bfloat162float(b0hi.y));
        const __nv_bfloat162 b1lo = __float22bfloat162_rn(r0);
        const __nv_bfloat162 b1hi = __float22bfloat162_rn(r1);
        uint2 pk1;
        pk1.x = *(const uint32_t*)&b1lo;
        pk1.y = *(const uint32_t*)&b1hi;
        *(uint2*)(g_b1 + gi) = pk1;                 // 8B store
        sx[r][cc] = v.x; sx[r][cc + 1] = v.y;
        sx[r][cc + 2] = v.z; sx[r][cc + 3] = v.w;
    }
    __syncthreads();

    if (t < 4) {
        float acc = 0.f;
#pragma unroll 16
        for (int k = 0; k < 512; k++)
            acc = fmaf(sx[t][k], sx[t][k], acc);    // sequential, do not reassociate
        g_diag_val[rowBlk + t] = acc;
        g_diag_in[rowBlk + t]  = (acc < 1.0f) ? 1 : 0;
    }
}

// ---------------------------------------------------------------------------
// main: triangle tiles, HMMA bf16x2-split, KC=32 2-stage, occupancy 2.
// (frozen — at the mma.sync issue wall; diagonal elements simply skipped)
// ---------------------------------------------------------------------------
__global__ __launch_bounds__(256, 2)
void binloss_mma(int n, int d) {
    extern __shared__ __align__(16) char dyn_smem[];
    __shared__ float sRP[4][BT], sRN[4][BT];
    __shared__ float sCP[2][BT], sCN[2][BT];
    __shared__ int tR[BT], tC[BT];
    __shared__ float sSpec[8][4];

    const int nT = n / BT;
    int idx = blockIdx.x, bi = 0;
    while (idx >= nT - bi) { idx -= nT - bi; bi++; }
    const int bj = bi + idx;
    const bool offd = (bi != bj);
    const int rowBlk = bi * BT, colBlk = bj * BT;

    const int tid = threadIdx.x;
    const int w = tid >> 5, l = tid & 31;
    const int wm = w & 1, wn = w >> 1;
    const int lr15 = l & 15, lh8 = (l >> 4) * 8;

    if (tid < BT) { tR[tid] = g_tgt[rowBlk + tid]; tC[tid] = g_tgt[colBlk + tid]; }

    float acc[4][4][4];
#pragma unroll
    for (int a = 0; a < 4; a++)
#pragma unroll
        for (int b = 0; b < 4; b++)
#pragma unroll
            for (int r = 0; r < 4; r++) acc[a][b][r] = 0.f;

    const uint32_t sbase = smem_u32(dyn_smem);
    const int nChunks = d / KC;                      // 16

#define PREFETCH(CHUNK, STG)                                                    \
    do {                                                                        \
        const int k0_ = (CHUNK) * KC;                                           \
        const uint32_t sb_ = sbase + (uint32_t)(STG) * STAGE_B;                 \
        _Pragma("unroll")                                                       \
        for (int u = 0; u < 8; u++) {                                           \
            const int e = tid + u * 256;                                        \
            const int tile = e >> 9;                                            \
            const int r = (e >> 2) & 127;                                       \
            const int cc = e & 3;                                               \
            const int grow = (tile < 2 ? rowBlk : colBlk) + r;                  \
            const __nv_bfloat16* src_ = (tile & 1) ? g_b1 : g_b0;               \
            cp16(sb_ + (uint32_t)(tile * TILE_B + r * (SPE * 2) + cc * 16),     \
                 src_ + (size_t)grow * d + k0_ + cc * 8);                       \
        }                                                                       \
    } while (0)

    PREFETCH(0, 0);
    cp_commit();

    for (int c = 0; c < nChunks; c++) {
        if (c + 1 < nChunks) {
            PREFETCH(c + 1, (c + 1) & 1);
            cp_commit();
            cp_wait1();
        } else {
            cp_wait0();
        }
        __syncthreads();
        const uint32_t stageBase = sbase + (uint32_t)(c & 1) * STAGE_B;

#pragma unroll
        for (int ks = 0; ks < KC; ks += 16) {
            const uint32_t koff = (uint32_t)(ks + lh8) * 2;
            uint32_t b0f[8], b1f[8];
            {
                const uint32_t bb = stageBase + 2u * TILE_B +
                                    (uint32_t)(wn * 32 + lr15) * (SPE * 2) + koff;
                LDMX4(b0f + 0, bb);
                LDMX4(b0f + 4, bb + 16u * (SPE * 2));
                const uint32_t cb = bb + (uint32_t)TILE_B;
                LDMX4(b1f + 0, cb);
                LDMX4(b1f + 4, cb + 16u * (SPE * 2));
            }
#pragma unroll
            for (int mi = 0; mi < 4; mi++) {
                uint32_t a0f[4], a1f[4];
                const uint32_t ab = stageBase +
                    (uint32_t)(wm * 64 + mi * 16 + lr15) * (SPE * 2) + koff;
                LDMX4(a0f, ab);
                LDMX4(a1f, ab + (uint32_t)TILE_B);
#pragma unroll
                for (int nj = 0; nj < 4; nj++) {
                    const int h = (nj >> 1) * 4 + (nj & 1);
                    MMA16816(acc[mi][nj], a0f, b0f[h], b0f[h + 2]);
                }
#pragma unroll
                for (int nj = 0; nj < 4; nj++) {
                    const int h = (nj >> 1) * 4 + (nj & 1);
                    MMA16816(acc[mi][nj], a0f, b1f[h], b1f[h + 2]);
                }
#pragma unroll
                for (int nj = 0; nj < 4; nj++) {
                    const int h = (nj >> 1) * 4 + (nj & 1);
                    MMA16816(acc[mi][nj], a1f, b0f[h], b0f[h + 2]);
                }
            }
        }
        __syncthreads();
    }
#undef PREFETCH

    // ---- fused epilogue (diagonal skipped; handled in finalize) ----
    const float ALPHA = 40.f, MARGIN = 0.5f;
    const int r0 = l >> 2, c0 = (l & 3) * 2;
    float rowP[8], rowN[8], colP[8], colN[8];
#pragma unroll
    for (int g = 0; g < 8; g++) { rowP[g] = rowN[g] = colP[g] = colN[g] = 0.f; }
    float sp = 0.f, sn = 0.f, spc = 0.f, snc = 0.f;

#pragma unroll
    for (int mi = 0; mi < 4; mi++) {
#pragma unroll
        for (int rh = 0; rh < 2; rh++) {
            const int rloc = wm * 64 + mi * 16 + r0 + rh * 8;
            const int gr = rowBlk + rloc;
            const int tr = tR[rloc];
            const bool isLastRow = (gr == n - 1);
            const int g = mi * 2 + rh;
#pragma unroll
            for (int nj = 0; nj < 4; nj++) {
#pragma unroll
                for (int p = 0; p < 2; p++) {
                    const int cloc = wn * 32 + nj * 8 + c0 + p;
                    const int gc = colBlk + cloc;
                    const int h = nj * 2 + p;
                    const float sv = acc[mi][nj][rh * 2 + p];
                    if (gc != gr) {
                        const bool same = (tr == tC[cloc]);
                        const float z = same ? (-2.f * (sv - MARGIN))
                                             : (ALPHA * (sv - MARGIN));
                        const float lv = softplus_fast(z);
                        if (same) {
                            rowP[g] += lv; colP[h] += lv;
                            if (isLastRow) sp += sv;
                            if (offd && gc == n - 1) spc += sv;
                        } else {
                            rowN[g] += lv; colN[h] += lv;
                            if (isLastRow) sn += sv;
                            if (offd && gc == n - 1) snc += sv;
                        }
                    }
                }
            }
        }
    }

#pragma unroll
    for (int g = 0; g < 8; g++) {
        rowP[g] += __shfl_xor_sync(0xffffffffu, rowP[g], 1);
        rowP[g] += __shfl_xor_sync(0xffffffffu, rowP[g], 2);
        rowN[g] += __shfl_xor_sync(0xffffffffu, rowN[g], 1);
        rowN[g] += __shfl_xor_sync(0xffffffffu, rowN[g], 2);
    }
    if ((l & 3) == 0) {
#pragma unroll
        for (int g = 0; g < 8; g++) {
            const int rloc = wm * 64 + (g >> 1) * 16 + r0 + (g & 1) * 8;
            sRP[wn][rloc] = rowP[g];
            sRN[wn][rloc] = rowN[g];
        }
    }
#pragma unroll
    for (int h = 0; h < 8; h++) {
        colP[h] += __shfl_xor_sync(0xffffffffu, colP[h], 4);
        colP[h] += __shfl_xor_sync(0xffffffffu, colP[h], 8);
        colP[h] += __shfl_xor_sync(0xffffffffu, colP[h], 16);
        colN[h] += __shfl_xor_sync(0xffffffffu, colN[h], 4);
        colN[h] += __shfl_xor_sync(0xffffffffu, colN[h], 8);
        colN[h] += __shfl_xor_sync(0xffffffffu, colN[h], 16);
    }
    if (l < 4) {
#pragma unroll
        for (int h = 0; h < 8; h++) {
            const int cloc = wn * 32 + (h >> 1) * 8 + l * 2 + (h & 1);
            sCP[wm][cloc] = colP[h];
            sCN[wm][cloc] = colN[h];
        }
    }
#pragma unroll
    for (int o = 16; o > 0; o >>= 1) {
        sp  += __shfl_xor_sync(0xffffffffu, sp,  o);
        sn  += __shfl_xor_sync(0xffffffffu, sn,  o);
        spc += __shfl_xor_sync(0xffffffffu, spc, o);
        snc += __shfl_xor_sync(0xffffffffu, snc, o);
    }
    if (l == 0) { sSpec[w][0] = sp; sSpec[w][1] = sn; sSpec[w][2] = spc; sSpec[w][3] = snc; }
    __syncthreads();

    if (tid < BT) {
        g_pos_part[(rowBlk + tid) * TILES_MAX + bj] =
            sRP[0][tid] + sRP[1][tid] + sRP[2][tid] + sRP[3][tid];
        g_neg_part[(rowBlk + tid) * TILES_MAX + bj] =
            sRN[0][tid] + sRN[1][tid] + sRN[2][tid] + sRN[3][tid];
    } else if (offd) {
        const int cc = tid - BT;
        g_pos_part[(colBlk + cc) * TILES_MAX + bi] = sCP[0][cc] + sCP[1][cc];
        g_neg_part[(colBlk + cc) * TILES_MAX + bi] = sCN[0][cc] + sCN[1][cc];
    }
    if (tid == 0 && bj == nT - 1) {
        float a0 = 0.f, a1 = 0.f, a2 = 0.f, a3 = 0.f;
#pragma unroll
        for (int ww = 0; ww < 8; ww++) {
            a0 += sSpec[ww][0]; a1 += sSpec[ww][1];
            a2 += sSpec[ww][2]; a3 += sSpec[ww][3];
        }
        if (offd) { g_last_part[bi][0] = a2; g_last_part[bi][1] = a3; }
        else      { g_last_part[bj][0] = a0; g_last_part[bj][1] = a1; }
    }
}

// ---------------------------------------------------------------------------
// finalize: 128 blocks x 32 threads (row/thread); diagonal contributions
// applied here; last-arriving block produces the 4 outputs.
// ---------------------------------------------------------------------------
__global__ void finalize_kernel(float* __restrict__ out, int n, int nTiles) {
    __shared__ int sLast;
    const int t = threadIdx.x;
    const int i = blockIdx.x * 32 + t;
    const float MARGIN = 0.5f;
    float loss = 0.f, inv = 0.f;
    if (i < n) {
        float ps = 0.f, ns = 0.f;
        const float4* pp = (const float4*)(g_pos_part + (size_t)i * TILES_MAX);
        const float4* np = (const float4*)(g_neg_part + (size_t)i * TILES_MAX);
#pragma unroll
        for (int b = 0; b < TILES_MAX / 4; b++) {
            const float4 p4 = pp[b];
            const float4 n4 = np[b];
            ps += (p4.x + p4.y) + (p4.z + p4.w);
            ns += (n4.x + n4.y) + (n4.z + n4.w);
        }
        const int din = g_diag_in[i];
        if (din) ps += softplus_fast(-2.f * (g_diag_val[i] - MARGIN));
        const int c = g_hist[g_tgt[i]];
        const float pc = (float)(c - 1 + din);
        const float nc = (float)(n - c);
        const float pl = ps / fmaxf(pc, 1.f);
        const float nl = ns / fmaxf(nc, 1.f);
        if (nc > 0.f) loss = pl + nl; else inv = 1.f;
    }
#pragma unroll
    for (int off = 16; off > 0; off >>= 1) {
        loss += __shfl_down_sync(0xffffffffu, loss, off);
        inv  += __shfl_down_sync(0xffffffffu, inv,  off);
    }
    if (t == 0) {
        g_loss_part[blockIdx.x] = loss;
        g_inv_part[blockIdx.x]  = inv;
        __threadfence();
        sLast = (atomicAdd(&g_fin_cnt, 1) == (int)gridDim.x - 1) ? 1 : 0;
    }
    __syncthreads();
    if (sLast) {
        const int nB = (int)gridDim.x;
        float ls = 0.f, iv = 0.f;
        for (int b = t; b < nB; b += 32) { ls += g_loss_part[b]; iv += g_inv_part[b]; }
        float sp = (t < nTiles) ? g_last_part[t][0] : 0.f;
        float sn = (t < nTiles) ? g_last_part[t][1] : 0.f;
#pragma unroll
        for (int off = 16; off > 0; off >>= 1) {
            ls += __shfl_down_sync(0xffffffffu, ls, off);
            iv += __shfl_down_sync(0xffffffffu, iv, off);
            sp += __shfl_down_sync(0xffffffffu, sp, off);
            sn += __shfl_down_sync(0xffffffffu, sn, off);
        }
        if (t == 0) {
            const int din = g_diag_in[n - 1];
            if (din) sp += g_diag_val[n - 1];       // diagonal sim for last row
            const int c = g_hist[g_tgt[n - 1]];
            const float pc = (float)(c - 1 + din);
            out[0] = ls / (float)n;
            out[1] = iv / (float)n;
            out[2] = sp / fmaxf(pc, 1.f);
            out[3] = sn / fmaxf((float)(n - c), 1.f);
        }
        __syncwarp();
        for (int ii = t; ii < CLSMAX; ii += 32) g_hist[ii] = 0;  // replay reset
        if (t == 0) g_fin_cnt = 0;
    }
}

// ---------------------------------------------------------------------------
extern "C" void kernel_launch(void* const* d_in, const int* in_sizes, int n_in,
                              void* d_out, int out_size) {
    int ix = 0, it = 1;
    if (n_in >= 2 && in_sizes[0] < in_sizes[1]) { ix = 1; it = 0; }
    const float* X = (const float*)d_in[ix];
    const void*  T = d_in[it];
    const int n = in_sizes[it];
    const int d = in_sizes[ix] / n;
    const int nT = n / BT;
    const int nBlocks = nT * (nT + 1) / 2;
    const int nFin = (n + 31) / 32;       // 128 blocks
    const int dynBytes = 2 * STAGE_B;     // 81920

    static int attr_set = 0;
    if (!attr_set) {
        cudaFuncSetAttribute(binloss_mma, cudaFuncAttributeMaxDynamicSharedMemorySize, dynBytes);
        attr_set = 1;
    }

    diag_split_kernel<<<n / 4, 128>>>(X, T, n, d);
    binloss_mma<<<nBlocks, 256, dynBytes>>>(n, d);
    finalize_kernel<<<nFin, 32>>>((float*)d_out, n, nT);
}